// round 1
// baseline (speedup 1.0000x reference)
#include <cuda_runtime.h>
#include <cuda_bf16.h>

#define NN 20000
#define EE 160000
#define FIN 9
#define F 64
#define NL 7
#define DIM 3
#define BN_EPS 1e-5f

// ---------------- device scratch (static, no allocation) ----------------
__device__ float d_h[NN * F];
__device__ float d_pos[NN * DIM];
__device__ float d_m1[EE * F];        // 40 MB edge intermediate
__device__ float d_dvec[EE * DIM];
__device__ float d_aggm[NN * F];
__device__ float d_aggpm[NN * DIM];
__device__ int   d_counts[NN];
__device__ float d_bnsum[F];
__device__ float d_bnsumsq[F];
__device__ float d_bnA[F];
__device__ float d_bnB[F];

__device__ __forceinline__ float silu_f(float x) {
    return x / (1.0f + expf(-x));
}

// ---------------- init: zero scratch + copy pos ----------------
__global__ void init_kernel(const float* __restrict__ pos_in) {
    int i = blockIdx.x * blockDim.x + threadIdx.x;
    if (i < NN * F) d_aggm[i] = 0.0f;
    if (i < NN * DIM) { d_aggpm[i] = 0.0f; d_pos[i] = pos_in[i]; }
    if (i < NN) d_counts[i] = 0;
    if (i < F) { d_bnsum[i] = 0.0f; d_bnsumsq[i] = 0.0f; }
}

__global__ void count_kernel(const int* __restrict__ edge_dst) {
    int i = blockIdx.x * blockDim.x + threadIdx.x;
    if (i < EE) atomicAdd(&d_counts[edge_dst[i]], 1);
}

// ---------------- embedding MLP: h = silu(h_in@W1+b1)@W2+b2 ----------------
// 500 blocks x 256 thr, 40 nodes/block (4 nodes per group, 64 thr/node)
__global__ void embed_kernel(const float* __restrict__ h_in,
                             const float* __restrict__ W1, const float* __restrict__ b1,
                             const float* __restrict__ W2, const float* __restrict__ b2) {
    __shared__ float sW1[FIN * F];
    __shared__ float sW2[F * F];
    __shared__ float sb1[F], sb2[F];
    __shared__ float sfeat[4][FIN];
    __shared__ float buf[4][F];
    int tid = threadIdx.x;
    for (int i = tid; i < FIN * F; i += 256) sW1[i] = W1[i];
    for (int i = tid; i < F * F; i += 256) sW2[i] = W2[i];
    if (tid < F) { sb1[tid] = b1[tid]; sb2[tid] = b2[tid]; }
    __syncthreads();
    int slot = tid >> 6, j = tid & 63;
    int base = blockIdx.x * 40;
    for (int it = 0; it < 10; ++it) {
        int node = base + it * 4 + slot;
        if (j < FIN) sfeat[slot][j] = h_in[node * FIN + j];
        __syncthreads();
        float a = sb1[j];
        #pragma unroll
        for (int k = 0; k < FIN; ++k) a += sfeat[slot][k] * sW1[k * F + j];
        a = silu_f(a);
        buf[slot][j] = a;
        __syncthreads();
        float c = sb2[j];
        #pragma unroll
        for (int k = 0; k < F; ++k) c += buf[slot][k] * sW2[k * F + j];
        d_h[node * F + j] = c;
        __syncthreads();
    }
}

// ---------------- pass1: m1 = silu(feat@W1+b1), BN partial sums ----------------
// 1250 blocks x 256 thr, 128 edges/block
__global__ void pass1_kernel(const int* __restrict__ edge_src,
                             const int* __restrict__ edge_dst,
                             const float* __restrict__ cell,
                             const float* __restrict__ W1, const float* __restrict__ b1) {
    __shared__ float sW1[(2 * F + 1) * F];   // 33 KB
    __shared__ float sb1[F];
    __shared__ float sfeat[4][2 * F + 2];
    __shared__ float sred[256];
    int tid = threadIdx.x;
    for (int i = tid; i < (2 * F + 1) * F; i += 256) sW1[i] = W1[i];
    if (tid < F) sb1[tid] = b1[tid];
    __syncthreads();
    int slot = tid >> 6, j = tid & 63;
    float lsum = 0.0f, lsq = 0.0f;
    int base = blockIdx.x * 128;
    for (int it = 0; it < 32; ++it) {
        int e = base + it * 4 + slot;
        int s = edge_src[e], d = edge_dst[e];
        sfeat[slot][j]     = d_h[d * F + j];
        sfeat[slot][F + j] = d_h[s * F + j];
        if (j == 0) {
            float dv0 = d_pos[d * 3 + 0] - d_pos[s * 3 + 0] + cell[e * 3 + 0];
            float dv1 = d_pos[d * 3 + 1] - d_pos[s * 3 + 1] + cell[e * 3 + 1];
            float dv2 = d_pos[d * 3 + 2] - d_pos[s * 3 + 2] + cell[e * 3 + 2];
            d_dvec[e * 3 + 0] = dv0; d_dvec[e * 3 + 1] = dv1; d_dvec[e * 3 + 2] = dv2;
            sfeat[slot][2 * F] = dv0 + dv1 + dv2;   // dist = sum of components
        }
        __syncthreads();
        float acc = sb1[j];
        #pragma unroll
        for (int k = 0; k < 2 * F + 1; ++k) acc += sfeat[slot][k] * sW1[k * F + j];
        float m = silu_f(acc);
        d_m1[e * F + j] = m;
        lsum += m; lsq += m * m;
        __syncthreads();
    }
    sred[tid] = lsum; __syncthreads();
    if (slot == 0) atomicAdd(&d_bnsum[j], sred[j] + sred[64 + j] + sred[128 + j] + sred[192 + j]);
    __syncthreads();
    sred[tid] = lsq; __syncthreads();
    if (slot == 0) atomicAdd(&d_bnsumsq[j], sred[j] + sred[64 + j] + sred[128 + j] + sred[192 + j]);
}

// ---------------- BN finalize: fold into affine A,B; reset sums ----------------
__global__ void bn_finalize_kernel(const float* __restrict__ gamma,
                                   const float* __restrict__ beta) {
    int j = threadIdx.x;
    float mu  = d_bnsum[j]   * (1.0f / (float)EE);
    float var = d_bnsumsq[j] * (1.0f / (float)EE) - mu * mu;
    float inv = rsqrtf(var + BN_EPS);
    float A = gamma[j] * inv;
    d_bnA[j] = A;
    d_bnB[j] = beta[j] - mu * A;
    d_bnsum[j] = 0.0f; d_bnsumsq[j] = 0.0f;
}

// ---------------- pass2: normalize -> W2 -> pos MLP -> atomic scatter ----------------
__global__ void pass2_kernel(const int* __restrict__ edge_dst,
                             const float* __restrict__ W2, const float* __restrict__ b2,
                             const float* __restrict__ pW1, const float* __restrict__ pb1,
                             const float* __restrict__ pW2, const float* __restrict__ pb2) {
    __shared__ float sW2[F * F], spW1[F * F], spW2[F * DIM];
    __shared__ float sb2[F], spb1[F], spb2[DIM], sA[F], sB[F];
    __shared__ float bufA[4][F], bufB[4][F];
    int tid = threadIdx.x;
    for (int i = tid; i < F * F; i += 256) { sW2[i] = W2[i]; spW1[i] = pW1[i]; }
    for (int i = tid; i < F * DIM; i += 256) spW2[i] = pW2[i];
    if (tid < F) { sb2[tid] = b2[tid]; spb1[tid] = pb1[tid]; sA[tid] = d_bnA[tid]; sB[tid] = d_bnB[tid]; }
    if (tid < DIM) spb2[tid] = pb2[tid];
    __syncthreads();
    int slot = tid >> 6, j = tid & 63;
    int base = blockIdx.x * 128;
    for (int it = 0; it < 32; ++it) {
        int e = base + it * 4 + slot;
        bufA[slot][j] = d_m1[e * F + j] * sA[j] + sB[j];
        __syncthreads();
        float m = sb2[j];
        #pragma unroll
        for (int k = 0; k < F; ++k) m += bufA[slot][k] * sW2[k * F + j];
        bufB[slot][j] = m;
        __syncthreads();
        float t = spb1[j];
        #pragma unroll
        for (int k = 0; k < F; ++k) t += bufB[slot][k] * spW1[k * F + j];
        t = silu_f(t);
        bufA[slot][j] = t;
        __syncthreads();
        int d = edge_dst[e];
        atomicAdd(&d_aggm[d * F + j], m);
        if (j < DIM) {
            float s = spb2[j];
            #pragma unroll
            for (int k = 0; k < F; ++k) s += bufA[slot][k] * spW2[k * DIM + j];
            atomicAdd(&d_aggpm[d * DIM + j], d_dvec[e * DIM + j] * s);
        }
        __syncthreads();
    }
}

// ---------------- node update: mean-agg, pos update, update MLP ----------------
// dynamic smem (~68KB): uW1[128x64] uW2 uW3 biases buffers
#define NODE_SMEM ((2*F*F + F*F + F*F + 3*F + 4*2*F + 4*F) * (int)sizeof(float))
__global__ void node_kernel(const float* __restrict__ uW1, const float* __restrict__ ub1,
                            const float* __restrict__ uW2, const float* __restrict__ ub2,
                            const float* __restrict__ uW3, const float* __restrict__ ub3) {
    extern __shared__ float sm[];
    float* sW1 = sm;
    float* sW2 = sW1 + 2 * F * F;
    float* sW3 = sW2 + F * F;
    float* sb1 = sW3 + F * F;
    float* sb2 = sb1 + F;
    float* sb3 = sb2 + F;
    float* bufU = sb3 + F;          // 4 x 128
    float* bufV = bufU + 4 * 2 * F; // 4 x 64
    int tid = threadIdx.x;
    for (int i = tid; i < 2 * F * F; i += 256) sW1[i] = uW1[i];
    for (int i = tid; i < F * F; i += 256) { sW2[i] = uW2[i]; sW3[i] = uW3[i]; }
    if (tid < F) { sb1[tid] = ub1[tid]; sb2[tid] = ub2[tid]; sb3[tid] = ub3[tid]; }
    __syncthreads();
    int slot = tid >> 6, j = tid & 63;
    int base = blockIdx.x * 40;
    for (int it = 0; it < 10; ++it) {
        int node = base + it * 4 + slot;
        float inv = 1.0f / fmaxf((float)d_counts[node], 1.0f);
        float h  = d_h[node * F + j];
        float am = d_aggm[node * F + j] * inv;
        d_aggm[node * F + j] = 0.0f;                 // re-zero for next layer
        if (j < DIM) {
            d_pos[node * DIM + j] += d_aggpm[node * DIM + j] * inv;
            d_aggpm[node * DIM + j] = 0.0f;
        }
        bufU[slot * 2 * F + j]     = h;
        bufU[slot * 2 * F + F + j] = am;
        __syncthreads();
        float u = sb1[j];
        #pragma unroll
        for (int k = 0; k < 2 * F; ++k) u += bufU[slot * 2 * F + k] * sW1[k * F + j];
        u = silu_f(u);
        bufV[slot * F + j] = u;
        __syncthreads();
        float v = sb2[j];
        #pragma unroll
        for (int k = 0; k < F; ++k) v += bufV[slot * F + k] * sW2[k * F + j];
        v = silu_f(v);
        bufU[slot * 2 * F + j] = v;
        __syncthreads();
        float w = sb3[j];
        #pragma unroll
        for (int k = 0; k < F; ++k) w += bufU[slot * 2 * F + k] * sW3[k * F + j];
        d_h[node * F + j] = h + w;
        __syncthreads();
    }
}

// ---------------- energy MLP ----------------
__global__ void energy_kernel(const float* __restrict__ W1, const float* __restrict__ b1,
                              const float* __restrict__ W2, const float* __restrict__ b2,
                              const float* __restrict__ W3, const float* __restrict__ b3,
                              float* __restrict__ out) {
    __shared__ float sW1[F * F], sW2[F * F], sW3[F];
    __shared__ float sb1[F], sb2[F];
    __shared__ float sb3v;
    __shared__ float bufA[4][F], bufB[4][F];
    int tid = threadIdx.x;
    for (int i = tid; i < F * F; i += 256) { sW1[i] = W1[i]; sW2[i] = W2[i]; }
    if (tid < F) { sb1[tid] = b1[tid]; sb2[tid] = b2[tid]; sW3[tid] = W3[tid]; }
    if (tid == 0) sb3v = b3[0];
    __syncthreads();
    int slot = tid >> 6, j = tid & 63;
    int base = blockIdx.x * 40;
    for (int it = 0; it < 10; ++it) {
        int node = base + it * 4 + slot;
        bufA[slot][j] = d_h[node * F + j];
        __syncthreads();
        float a = sb1[j];
        #pragma unroll
        for (int k = 0; k < F; ++k) a += bufA[slot][k] * sW1[k * F + j];
        a = silu_f(a);
        bufB[slot][j] = a;
        __syncthreads();
        float c = sb2[j];
        #pragma unroll
        for (int k = 0; k < F; ++k) c += bufB[slot][k] * sW2[k * F + j];
        c = silu_f(c);
        bufA[slot][j] = c * sW3[j];
        __syncthreads();
        if (j == 0) {
            float s = sb3v;
            #pragma unroll
            for (int k = 0; k < F; ++k) s += bufA[slot][k];
            out[node] = s;
        }
        __syncthreads();
    }
}

// ---------------- launch ----------------
extern "C" void kernel_launch(void* const* d_in, const int* in_sizes, int n_in,
                              void* d_out, int out_size) {
    const float* h_in   = (const float*)d_in[0];
    const float* pos    = (const float*)d_in[1];
    const float* cell   = (const float*)d_in[2];
    const int*   esrc   = (const int*)d_in[3];
    const int*   edst   = (const int*)d_in[4];
    const float* emb_W1 = (const float*)d_in[5];
    const float* emb_b1 = (const float*)d_in[6];
    const float* emb_W2 = (const float*)d_in[7];
    const float* emb_b2 = (const float*)d_in[8];
    const float* msg_W1 = (const float*)d_in[9];
    const float* msg_b1 = (const float*)d_in[10];
    const float* bn_g   = (const float*)d_in[11];
    const float* bn_b   = (const float*)d_in[12];
    const float* msg_W2 = (const float*)d_in[13];
    const float* msg_b2 = (const float*)d_in[14];
    const float* upd_W1 = (const float*)d_in[15];
    const float* upd_b1 = (const float*)d_in[16];
    const float* upd_W2 = (const float*)d_in[17];
    const float* upd_b2 = (const float*)d_in[18];
    const float* upd_W3 = (const float*)d_in[19];
    const float* upd_b3 = (const float*)d_in[20];
    const float* pos_W1 = (const float*)d_in[21];
    const float* pos_b1 = (const float*)d_in[22];
    const float* pos_W2 = (const float*)d_in[23];
    const float* pos_b2 = (const float*)d_in[24];
    const float* en_W1  = (const float*)d_in[25];
    const float* en_b1  = (const float*)d_in[26];
    const float* en_W2  = (const float*)d_in[27];
    const float* en_b2  = (const float*)d_in[28];
    const float* en_W3  = (const float*)d_in[29];
    const float* en_b3  = (const float*)d_in[30];
    float* out = (float*)d_out;

    cudaFuncSetAttribute(node_kernel, cudaFuncAttributeMaxDynamicSharedMemorySize, NODE_SMEM);

    init_kernel<<<(NN * F + 255) / 256, 256>>>(pos);
    count_kernel<<<(EE + 255) / 256, 256>>>(edst);
    embed_kernel<<<500, 256>>>(h_in, emb_W1, emb_b1, emb_W2, emb_b2);

    for (int l = 0; l < NL; ++l) {
        pass1_kernel<<<1250, 256>>>(esrc, edst, cell,
                                    msg_W1 + l * (2 * F + 1) * F, msg_b1 + l * F);
        bn_finalize_kernel<<<1, 64>>>(bn_g + l * F, bn_b + l * F);
        pass2_kernel<<<1250, 256>>>(edst,
                                    msg_W2 + l * F * F, msg_b2 + l * F,
                                    pos_W1 + l * F * F, pos_b1 + l * F,
                                    pos_W2 + l * F * DIM, pos_b2 + l * DIM);
        node_kernel<<<500, 256, NODE_SMEM>>>(upd_W1 + l * 2 * F * F, upd_b1 + l * F,
                                             upd_W2 + l * F * F, upd_b2 + l * F,
                                             upd_W3 + l * F * F, upd_b3 + l * F);
    }
    energy_kernel<<<500, 256>>>(en_W1, en_b1, en_W2, en_b2, en_W3, en_b3, out);
}

// round 2
// speedup vs baseline: 2.5511x; 2.5511x over previous
#include <cuda_runtime.h>
#include <cuda_bf16.h>

#define NN 20000
#define EE 160000
#define FIN 9
#define F 64
#define NL 7
#define DIM 3
#define BN_EPS 1e-5f

typedef unsigned long long ull;
union F4U { float4 v; ull u[2]; float f[4]; };

// ---------------- device scratch ----------------
__device__ float d_h[NN * F];
__device__ float d_pos[NN * DIM];
__device__ float d_m1[EE * F];
__device__ float d_dvec[EE * DIM];
__device__ float d_aggm[NN * F];
__device__ float d_aggpm[NN * DIM];
__device__ int   d_counts[NN];
__device__ float d_invc[NN];
__device__ float d_bnsum[F];
__device__ float d_bnsumsq[F];
__device__ float d_bnA[F];
__device__ float d_bnBias2[F];

__device__ __forceinline__ float silu_f(float x) { return x / (1.0f + expf(-x)); }

__device__ __forceinline__ ull ffma2(ull a, ull b, ull c) {
    ull d;
    asm("fma.rn.f32x2 %0, %1, %2, %3;" : "=l"(d) : "l"(a), "l"(b), "l"(c));
    return d;
}
__device__ __forceinline__ float lane_sum(ull a) {
    float lo = __uint_as_float((unsigned)(a & 0xffffffffull));
    float hi = __uint_as_float((unsigned)(a >> 32));
    return lo + hi;
}

// Register-tiled GEMM core: 128 rows x 64 cols per 256-thread block.
// Thread (et = tid&15, jt = tid>>4) owns rows {et + 16*e0 : e0<8}, cols jt*4..+3.
// sWt is TRANSPOSED weight [64][PW] (sWt[j][k] = W[k][j]); lanes of the f32x2
// accumulator hold even-k / odd-k partial sums (merge with lane_sum).
template<int PF, int PW>
__device__ __forceinline__ void gemm_acc(const float* __restrict__ sf,
                                         const float* __restrict__ sWt,
                                         int kmax, int et, int jt, ull acc[8][4]) {
    const float* fb = sf + et * PF;
    const float* wb = sWt + (jt * 4) * PW;
    #pragma unroll 2
    for (int k0 = 0; k0 < kmax; k0 += 4) {
        ull w[4][2];
        #pragma unroll
        for (int j = 0; j < 4; ++j) {
            F4U t; t.v = *(const float4*)(wb + j * PW + k0);
            w[j][0] = t.u[0]; w[j][1] = t.u[1];
        }
        #pragma unroll
        for (int e = 0; e < 8; ++e) {
            F4U t; t.v = *(const float4*)(fb + e * 16 * PF + k0);
            #pragma unroll
            for (int j = 0; j < 4; ++j) {
                acc[e][j] = ffma2(t.u[0], w[j][0], acc[e][j]);
                acc[e][j] = ffma2(t.u[1], w[j][1], acc[e][j]);
            }
        }
    }
}

// ---------------- init ----------------
__global__ void init_kernel(const float* __restrict__ pos_in) {
    int i = blockIdx.x * blockDim.x + threadIdx.x;
    if (i < NN * F) d_aggm[i] = 0.0f;
    if (i < NN * DIM) { d_aggpm[i] = 0.0f; d_pos[i] = pos_in[i]; }
    if (i < NN) d_counts[i] = 0;
    if (i < F) { d_bnsum[i] = 0.0f; d_bnsumsq[i] = 0.0f; }
}
__global__ void count_kernel(const int* __restrict__ edge_dst) {
    int i = blockIdx.x * blockDim.x + threadIdx.x;
    if (i < EE) atomicAdd(&d_counts[edge_dst[i]], 1);
}
__global__ void inv_kernel() {
    int i = blockIdx.x * blockDim.x + threadIdx.x;
    if (i < NN) d_invc[i] = 1.0f / fmaxf((float)d_counts[i], 1.0f);
}

// ---------------- embedding ----------------
// smem: sf[128*12] sW1t[64*12] sfB[128*68] sW2t[64*68] sb1[64] sb2[64]
#define EM_SMEM ((128*12 + 64*12 + 128*68 + 64*68 + 128) * (int)sizeof(float))
__global__ void embed_kernel(const float* __restrict__ h_in,
                             const float* __restrict__ W1, const float* __restrict__ b1,
                             const float* __restrict__ W2, const float* __restrict__ b2) {
    extern __shared__ float sm[];
    float* sf   = sm;                  // 128*12
    float* sW1t = sf + 128 * 12;       // 64*12
    float* sfB  = sW1t + 64 * 12;      // 128*68
    float* sW2t = sfB + 128 * 68;      // 64*68
    float* sb1  = sW2t + 64 * 68;      // 64
    float* sb2  = sb1 + 64;            // 64
    int tid = threadIdx.x;
    int base = blockIdx.x * 128;
    for (int idx = tid; idx < 64 * 12; idx += 256) {
        int j = idx / 12, k = idx - j * 12;
        sW1t[idx] = (k < FIN) ? W1[k * 64 + j] : 0.0f;
    }
    for (int idx = tid; idx < 64 * 64; idx += 256) {
        int k = idx >> 6, j = idx & 63;
        sW2t[j * 68 + k] = W2[idx];
    }
    if (tid < 64) { sb1[tid] = b1[tid]; sb2[tid] = b2[tid]; }
    for (int idx = tid; idx < 128 * 12; idx += 256) {
        int e = idx / 12, k = idx - e * 12;
        int n = base + e;
        sf[idx] = (k < FIN && n < NN) ? h_in[n * FIN + k] : 0.0f;
    }
    __syncthreads();
    int et = tid & 15, jt = tid >> 4;
    {
        ull acc[8][4] = {};
        gemm_acc<12, 12>(sf, sW1t, 12, et, jt, acc);
        #pragma unroll
        for (int e = 0; e < 8; ++e) {
            F4U o;
            #pragma unroll
            for (int j = 0; j < 4; ++j)
                o.f[j] = silu_f(lane_sum(acc[e][j]) + sb1[jt * 4 + j]);
            *(float4*)(sfB + (et + 16 * e) * 68 + jt * 4) = o.v;
        }
    }
    __syncthreads();
    {
        ull acc[8][4] = {};
        gemm_acc<68, 68>(sfB, sW2t, 64, et, jt, acc);
        #pragma unroll
        for (int e = 0; e < 8; ++e) {
            int n = base + et + 16 * e;
            if (n < NN) {
                F4U o;
                #pragma unroll
                for (int j = 0; j < 4; ++j)
                    o.f[j] = lane_sum(acc[e][j]) + sb2[jt * 4 + j];
                *(float4*)(d_h + n * 64 + jt * 4) = o.v;
            }
        }
    }
}

// ---------------- pass1: m1 = silu(feat @ W1 + b1), BN partial sums ----------------
// smem: sf[128*132] sWt[64*132] sred[16*64] sb1[64] sidx[256(int)]
#define P1_SMEM ((128*132 + 64*132 + 16*64 + 64 + 256) * (int)sizeof(float))
__global__ void __launch_bounds__(256, 2)
pass1_kernel(const int* __restrict__ esrc, const int* __restrict__ edst,
             const float* __restrict__ cell,
             const float* __restrict__ W1, const float* __restrict__ b1) {
    extern __shared__ float sm[];
    float* sf   = sm;                    // 128*132
    float* sWt  = sf + 128 * 132;        // 64*132
    float* sred = sWt + 64 * 132;        // 16*64
    float* sb1  = sred + 16 * 64;        // 64
    int*   sidx = (int*)(sb1 + 64);      // 256
    int tid = threadIdx.x;
    int base = blockIdx.x * 128;
    for (int idx = tid; idx < 129 * 64; idx += 256) {
        int k = idx >> 6, j = idx & 63;
        sWt[j * 132 + k] = W1[idx];
    }
    if (tid < 64) sb1[tid] = b1[tid];
    if (tid < 128) { sidx[tid] = edst[base + tid]; sidx[128 + tid] = esrc[base + tid]; }
    __syncthreads();
    // gather [h[dst], h[src]] rows
    for (int idx = tid; idx < 128 * 32; idx += 256) {
        int e = idx >> 5, q = idx & 31;
        int n = (q < 16) ? sidx[e] : sidx[128 + e];
        int qq = q & 15;
        *(float4*)(sf + e * 132 + q * 4) = *(const float4*)(d_h + n * 64 + qq * 4);
    }
    if (tid < 128) {
        int d = sidx[tid], s = sidx[128 + tid];
        int ge = base + tid;
        float dv0 = d_pos[d * 3 + 0] - d_pos[s * 3 + 0] + cell[ge * 3 + 0];
        float dv1 = d_pos[d * 3 + 1] - d_pos[s * 3 + 1] + cell[ge * 3 + 1];
        float dv2 = d_pos[d * 3 + 2] - d_pos[s * 3 + 2] + cell[ge * 3 + 2];
        d_dvec[ge * 3 + 0] = dv0; d_dvec[ge * 3 + 1] = dv1; d_dvec[ge * 3 + 2] = dv2;
        sf[tid * 132 + 128] = dv0 + dv1 + dv2;
    }
    __syncthreads();
    int et = tid & 15, jt = tid >> 4;
    ull acc[8][4] = {};
    gemm_acc<132, 132>(sf, sWt, 128, et, jt, acc);
    float lsum[4] = {0, 0, 0, 0}, lsq[4] = {0, 0, 0, 0};
    #pragma unroll
    for (int e = 0; e < 8; ++e) {
        int er = et + 16 * e;
        float fk = sf[er * 132 + 128];
        F4U o;
        #pragma unroll
        for (int j = 0; j < 4; ++j) {
            float v = lane_sum(acc[e][j]) + fk * sWt[(jt * 4 + j) * 132 + 128] + sb1[jt * 4 + j];
            v = silu_f(v);
            o.f[j] = v; lsum[j] += v; lsq[j] += v * v;
        }
        *(float4*)(d_m1 + (base + er) * 64 + jt * 4) = o.v;
    }
    #pragma unroll
    for (int j = 0; j < 4; ++j) sred[et * 64 + jt * 4 + j] = lsum[j];
    __syncthreads();
    if (tid < 64) {
        float s = 0;
        #pragma unroll
        for (int r = 0; r < 16; ++r) s += sred[r * 64 + tid];
        atomicAdd(&d_bnsum[tid], s);
    }
    __syncthreads();
    #pragma unroll
    for (int j = 0; j < 4; ++j) sred[et * 64 + jt * 4 + j] = lsq[j];
    __syncthreads();
    if (tid < 64) {
        float s = 0;
        #pragma unroll
        for (int r = 0; r < 16; ++r) s += sred[r * 64 + tid];
        atomicAdd(&d_bnsumsq[tid], s);
    }
}

// ---------------- BN finalize: fold affine into W2-scale (A) + bias2 ----------------
__global__ void bn_finalize_kernel(const float* __restrict__ gamma, const float* __restrict__ beta,
                                   const float* __restrict__ W2, const float* __restrict__ b2) {
    __shared__ float sB[F];
    int j = threadIdx.x;
    float mu  = d_bnsum[j]   * (1.0f / (float)EE);
    float var = d_bnsumsq[j] * (1.0f / (float)EE) - mu * mu;
    float inv = rsqrtf(var + BN_EPS);
    float A = gamma[j] * inv;
    d_bnA[j] = A;
    sB[j] = beta[j] - mu * A;
    d_bnsum[j] = 0.0f; d_bnsumsq[j] = 0.0f;
    __syncthreads();
    float acc = b2[j];
    #pragma unroll
    for (int k = 0; k < F; ++k) acc += sB[k] * W2[k * F + j];
    d_bnBias2[j] = acc;
}

// ---------------- pass2: m = mnorm@W2+b2' ; t = silu(m@pW1+pb1) ; pm = dvec*(t@pW2+pb2) ----------------
// smem: sfA[128*68] sfB[128*68] sW2t[64*68] spW1t[64*68] spW2[192] sdv[384] sb2[64] spb1[64] spb2[4] sdst[128]
#define P2_SMEM ((128*68*2 + 64*68*2 + 192 + 384 + 64 + 64 + 4 + 128) * (int)sizeof(float))
__global__ void __launch_bounds__(256, 2)
pass2_kernel(const int* __restrict__ edst,
             const float* __restrict__ W2,
             const float* __restrict__ pW1, const float* __restrict__ pb1,
             const float* __restrict__ pW2, const float* __restrict__ pb2) {
    extern __shared__ float sm[];
    float* sfA   = sm;                   // 128*68
    float* sfB   = sfA + 128 * 68;       // 128*68
    float* sW2t  = sfB + 128 * 68;       // 64*68  (BN A folded in)
    float* spW1t = sW2t + 64 * 68;       // 64*68
    float* spW2  = spW1t + 64 * 68;      // 192
    float* sdv   = spW2 + 192;           // 384
    float* sb2   = sdv + 384;            // 64 (folded bias2)
    float* spb1  = sb2 + 64;             // 64
    float* spb2  = spb1 + 64;            // 4
    int*   sdst  = (int*)(spb2 + 4);     // 128
    int tid = threadIdx.x;
    int base = blockIdx.x * 128;
    for (int idx = tid; idx < 64 * 64; idx += 256) {
        int k = idx >> 6, j = idx & 63;
        sW2t[j * 68 + k]  = W2[idx] * d_bnA[k];
        spW1t[j * 68 + k] = pW1[idx];
    }
    for (int idx = tid; idx < 192; idx += 256) spW2[idx] = pW2[idx];
    if (tid < 64) { sb2[tid] = d_bnBias2[tid]; spb1[tid] = pb1[tid]; }
    if (tid < 3) spb2[tid] = pb2[tid];
    if (tid < 128) sdst[tid] = edst[base + tid];
    for (int idx = tid; idx < 128 * 16; idx += 256) {
        int e = idx >> 4, q = idx & 15;
        *(float4*)(sfA + e * 68 + q * 4) = *(const float4*)(d_m1 + (base + e) * 64 + q * 4);
    }
    for (int idx = tid; idx < 384; idx += 256) sdv[idx] = d_dvec[base * 3 + idx];
    __syncthreads();
    int et = tid & 15, jt = tid >> 4;
    {   // GEMM1: m = m1 @ W2A + bias2  (no activation); scatter + stage to sfB
        ull acc[8][4] = {};
        gemm_acc<68, 68>(sfA, sW2t, 64, et, jt, acc);
        #pragma unroll
        for (int e = 0; e < 8; ++e) {
            int er = et + 16 * e;
            int dn = sdst[er];
            F4U o;
            #pragma unroll
            for (int j = 0; j < 4; ++j) {
                float v = lane_sum(acc[e][j]) + sb2[jt * 4 + j];
                o.f[j] = v;
                atomicAdd(&d_aggm[dn * 64 + jt * 4 + j], v);
            }
            *(float4*)(sfB + er * 68 + jt * 4) = o.v;
        }
    }
    __syncthreads();
    {   // GEMM2: t = silu(m @ pW1 + pb1) -> sfA
        ull acc[8][4] = {};
        gemm_acc<68, 68>(sfB, spW1t, 64, et, jt, acc);
        #pragma unroll
        for (int e = 0; e < 8; ++e) {
            F4U o;
            #pragma unroll
            for (int j = 0; j < 4; ++j)
                o.f[j] = silu_f(lane_sum(acc[e][j]) + spb1[jt * 4 + j]);
            *(float4*)(sfA + (et + 16 * e) * 68 + jt * 4) = o.v;
        }
    }
    __syncthreads();
    if (tid < 128) {   // stage3: s = t @ pW2 + pb2 ; pm = dvec*s ; scatter
        float s0 = spb2[0], s1 = spb2[1], s2 = spb2[2];
        #pragma unroll
        for (int q = 0; q < 16; ++q) {
            F4U t; t.v = *(const float4*)(sfA + tid * 68 + q * 4);
            #pragma unroll
            for (int c = 0; c < 4; ++c) {
                int k = q * 4 + c;
                s0 += t.f[c] * spW2[k * 3 + 0];
                s1 += t.f[c] * spW2[k * 3 + 1];
                s2 += t.f[c] * spW2[k * 3 + 2];
            }
        }
        int dn = sdst[tid];
        atomicAdd(&d_aggpm[dn * 3 + 0], sdv[tid * 3 + 0] * s0);
        atomicAdd(&d_aggpm[dn * 3 + 1], sdv[tid * 3 + 1] * s1);
        atomicAdd(&d_aggpm[dn * 3 + 2], sdv[tid * 3 + 2] * s2);
    }
}

// ---------------- node update ----------------
// smem: sfA[128*132] sfB[128*68] sW1t[64*132] sW2t[64*68] sW3t[64*68] sb[192]
#define ND_SMEM ((128*132 + 128*68 + 64*132 + 64*68*2 + 192) * (int)sizeof(float))
__global__ void node_kernel(const float* __restrict__ uW1, const float* __restrict__ ub1,
                            const float* __restrict__ uW2, const float* __restrict__ ub2,
                            const float* __restrict__ uW3, const float* __restrict__ ub3) {
    extern __shared__ float sm[];
    float* sfA  = sm;                    // 128*132
    float* sfB  = sfA + 128 * 132;       // 128*68
    float* sW1t = sfB + 128 * 68;        // 64*132
    float* sW2t = sW1t + 64 * 132;       // 64*68
    float* sW3t = sW2t + 64 * 68;        // 64*68
    float* sb1  = sW3t + 64 * 68;        // 64
    float* sb2  = sb1 + 64;
    float* sb3  = sb2 + 64;
    int tid = threadIdx.x;
    int base = blockIdx.x * 128;
    for (int idx = tid; idx < 128 * 64; idx += 256) {
        int k = idx >> 6, j = idx & 63;
        sW1t[j * 132 + k] = uW1[idx];
    }
    for (int idx = tid; idx < 64 * 64; idx += 256) {
        int k = idx >> 6, j = idx & 63;
        sW2t[j * 68 + k] = uW2[idx];
        sW3t[j * 68 + k] = uW3[idx];
    }
    if (tid < 64) { sb1[tid] = ub1[tid]; sb2[tid] = ub2[tid]; sb3[tid] = ub3[tid]; }
    // gather [h, agg_m/cnt]; zero agg for next layer
    for (int idx = tid; idx < 128 * 32; idx += 256) {
        int e = idx >> 5, q = idx & 31;
        int n = base + e;
        F4U t;
        if (n < NN) {
            int qq = q & 15;
            if (q < 16) {
                t.v = *(const float4*)(d_h + n * 64 + qq * 4);
            } else {
                t.v = *(const float4*)(d_aggm + n * 64 + qq * 4);
                float inv = d_invc[n];
                t.f[0] *= inv; t.f[1] *= inv; t.f[2] *= inv; t.f[3] *= inv;
                *(float4*)(d_aggm + n * 64 + qq * 4) = make_float4(0.f, 0.f, 0.f, 0.f);
            }
        } else {
            t.v = make_float4(0.f, 0.f, 0.f, 0.f);
        }
        *(float4*)(sfA + e * 132 + q * 4) = t.v;
    }
    if (tid < 128) {   // pos update
        int n = base + tid;
        if (n < NN) {
            float inv = d_invc[n];
            #pragma unroll
            for (int c = 0; c < 3; ++c) {
                d_pos[n * 3 + c] += d_aggpm[n * 3 + c] * inv;
                d_aggpm[n * 3 + c] = 0.0f;
            }
        }
    }
    __syncthreads();
    int et = tid & 15, jt = tid >> 4;
    {   // u = silu([h,agg] @ uW1 + b1)
        ull acc[8][4] = {};
        gemm_acc<132, 132>(sfA, sW1t, 128, et, jt, acc);
        #pragma unroll
        for (int e = 0; e < 8; ++e) {
            F4U o;
            #pragma unroll
            for (int j = 0; j < 4; ++j)
                o.f[j] = silu_f(lane_sum(acc[e][j]) + sb1[jt * 4 + j]);
            *(float4*)(sfB + (et + 16 * e) * 68 + jt * 4) = o.v;
        }
    }
    __syncthreads();
    {   // v = silu(u @ uW2 + b2) -> sfA (pitch 132, cols 0..63)
        ull acc[8][4] = {};
        gemm_acc<68, 68>(sfB, sW2t, 64, et, jt, acc);
        #pragma unroll
        for (int e = 0; e < 8; ++e) {
            F4U o;
            #pragma unroll
            for (int j = 0; j < 4; ++j)
                o.f[j] = silu_f(lane_sum(acc[e][j]) + sb2[jt * 4 + j]);
            *(float4*)(sfA + (et + 16 * e) * 132 + jt * 4) = o.v;
        }
    }
    __syncthreads();
    {   // h += v @ uW3 + b3
        ull acc[8][4] = {};
        gemm_acc<132, 68>(sfA, sW3t, 64, et, jt, acc);
        #pragma unroll
        for (int e = 0; e < 8; ++e) {
            int n = base + et + 16 * e;
            if (n < NN) {
                F4U h; h.v = *(const float4*)(d_h + n * 64 + jt * 4);
                F4U o;
                #pragma unroll
                for (int j = 0; j < 4; ++j)
                    o.f[j] = h.f[j] + lane_sum(acc[e][j]) + sb3[jt * 4 + j];
                *(float4*)(d_h + n * 64 + jt * 4) = o.v;
            }
        }
    }
}

// ---------------- energy MLP ----------------
#define EN_SMEM ((128*68*2 + 64*68*2 + 64 + 64 + 64 + 4) * (int)sizeof(float))
__global__ void energy_kernel(const float* __restrict__ W1, const float* __restrict__ b1,
                              const float* __restrict__ W2, const float* __restrict__ b2,
                              const float* __restrict__ W3, const float* __restrict__ b3,
                              float* __restrict__ out) {
    extern __shared__ float sm[];
    float* sfA  = sm;                   // 128*68
    float* sfB  = sfA + 128 * 68;       // 128*68
    float* sW1t = sfB + 128 * 68;       // 64*68
    float* sW2t = sW1t + 64 * 68;       // 64*68
    float* sW3  = sW2t + 64 * 68;       // 64
    float* sb1  = sW3 + 64;
    float* sb2  = sb1 + 64;
    float* sb3  = sb2 + 64;             // 1
    int tid = threadIdx.x;
    int base = blockIdx.x * 128;
    for (int idx = tid; idx < 64 * 64; idx += 256) {
        int k = idx >> 6, j = idx & 63;
        sW1t[j * 68 + k] = W1[idx];
        sW2t[j * 68 + k] = W2[idx];
    }
    if (tid < 64) { sW3[tid] = W3[tid]; sb1[tid] = b1[tid]; sb2[tid] = b2[tid]; }
    if (tid == 0) sb3[0] = b3[0];
    for (int idx = tid; idx < 128 * 16; idx += 256) {
        int e = idx >> 4, q = idx & 15;
        int n = base + e;
        float4 v = (n < NN) ? *(const float4*)(d_h + n * 64 + q * 4)
                            : make_float4(0.f, 0.f, 0.f, 0.f);
        *(float4*)(sfA + e * 68 + q * 4) = v;
    }
    __syncthreads();
    int et = tid & 15, jt = tid >> 4;
    {
        ull acc[8][4] = {};
        gemm_acc<68, 68>(sfA, sW1t, 64, et, jt, acc);
        #pragma unroll
        for (int e = 0; e < 8; ++e) {
            F4U o;
            #pragma unroll
            for (int j = 0; j < 4; ++j)
                o.f[j] = silu_f(lane_sum(acc[e][j]) + sb1[jt * 4 + j]);
            *(float4*)(sfB + (et + 16 * e) * 68 + jt * 4) = o.v;
        }
    }
    __syncthreads();
    {
        ull acc[8][4] = {};
        gemm_acc<68, 68>(sfB, sW2t, 64, et, jt, acc);
        #pragma unroll
        for (int e = 0; e < 8; ++e) {
            F4U o;
            #pragma unroll
            for (int j = 0; j < 4; ++j)
                o.f[j] = silu_f(lane_sum(acc[e][j]) + sb2[jt * 4 + j]);
            *(float4*)(sfA + (et + 16 * e) * 68 + jt * 4) = o.v;
        }
    }
    __syncthreads();
    if (tid < 128) {
        int n = base + tid;
        if (n < NN) {
            float s = sb3[0];
            #pragma unroll
            for (int q = 0; q < 16; ++q) {
                F4U t; t.v = *(const float4*)(sfA + tid * 68 + q * 4);
                #pragma unroll
                for (int c = 0; c < 4; ++c) s += t.f[c] * sW3[q * 4 + c];
            }
            out[n] = s;
        }
    }
}

// ---------------- launch ----------------
extern "C" void kernel_launch(void* const* d_in, const int* in_sizes, int n_in,
                              void* d_out, int out_size) {
    const float* h_in   = (const float*)d_in[0];
    const float* pos    = (const float*)d_in[1];
    const float* cell   = (const float*)d_in[2];
    const int*   esrc   = (const int*)d_in[3];
    const int*   edst   = (const int*)d_in[4];
    const float* emb_W1 = (const float*)d_in[5];
    const float* emb_b1 = (const float*)d_in[6];
    const float* emb_W2 = (const float*)d_in[7];
    const float* emb_b2 = (const float*)d_in[8];
    const float* msg_W1 = (const float*)d_in[9];
    const float* msg_b1 = (const float*)d_in[10];
    const float* bn_g   = (const float*)d_in[11];
    const float* bn_b   = (const float*)d_in[12];
    const float* msg_W2 = (const float*)d_in[13];
    const float* msg_b2 = (const float*)d_in[14];
    const float* upd_W1 = (const float*)d_in[15];
    const float* upd_b1 = (const float*)d_in[16];
    const float* upd_W2 = (const float*)d_in[17];
    const float* upd_b2 = (const float*)d_in[18];
    const float* upd_W3 = (const float*)d_in[19];
    const float* upd_b3 = (const float*)d_in[20];
    const float* pos_W1 = (const float*)d_in[21];
    const float* pos_b1 = (const float*)d_in[22];
    const float* pos_W2 = (const float*)d_in[23];
    const float* pos_b2 = (const float*)d_in[24];
    const float* en_W1  = (const float*)d_in[25];
    const float* en_b1  = (const float*)d_in[26];
    const float* en_W2  = (const float*)d_in[27];
    const float* en_b2  = (const float*)d_in[28];
    const float* en_W3  = (const float*)d_in[29];
    const float* en_b3  = (const float*)d_in[30];
    float* out = (float*)d_out;

    static int attr_done = 0;
    if (!attr_done) {
        cudaFuncSetAttribute(embed_kernel,  cudaFuncAttributeMaxDynamicSharedMemorySize, EM_SMEM);
        cudaFuncSetAttribute(pass1_kernel,  cudaFuncAttributeMaxDynamicSharedMemorySize, P1_SMEM);
        cudaFuncSetAttribute(pass2_kernel,  cudaFuncAttributeMaxDynamicSharedMemorySize, P2_SMEM);
        cudaFuncSetAttribute(node_kernel,   cudaFuncAttributeMaxDynamicSharedMemorySize, ND_SMEM);
        cudaFuncSetAttribute(energy_kernel, cudaFuncAttributeMaxDynamicSharedMemorySize, EN_SMEM);
        attr_done = 1;
    }

    init_kernel<<<(NN * F + 255) / 256, 256>>>(pos);
    count_kernel<<<(EE + 255) / 256, 256>>>(edst);
    inv_kernel<<<(NN + 255) / 256, 256>>>();
    embed_kernel<<<157, 256, EM_SMEM>>>(h_in, emb_W1, emb_b1, emb_W2, emb_b2);

    for (int l = 0; l < NL; ++l) {
        pass1_kernel<<<1250, 256, P1_SMEM>>>(esrc, edst, cell,
                                             msg_W1 + l * (2 * F + 1) * F, msg_b1 + l * F);
        bn_finalize_kernel<<<1, 64>>>(bn_g + l * F, bn_b + l * F,
                                      msg_W2 + l * F * F, msg_b2 + l * F);
        pass2_kernel<<<1250, 256, P2_SMEM>>>(edst,
                                             msg_W2 + l * F * F,
                                             pos_W1 + l * F * F, pos_b1 + l * F,
                                             pos_W2 + l * F * DIM, pos_b2 + l * DIM);
        node_kernel<<<157, 256, ND_SMEM>>>(upd_W1 + l * 2 * F * F, upd_b1 + l * F,
                                           upd_W2 + l * F * F, upd_b2 + l * F,
                                           upd_W3 + l * F * F, upd_b3 + l * F);
    }
    energy_kernel<<<157, 256, EN_SMEM>>>(en_W1, en_b1, en_W2, en_b2, en_W3, en_b3, out);
}

// round 4
// speedup vs baseline: 2.5561x; 1.0020x over previous
#include <cuda_runtime.h>
#include <cuda_bf16.h>

#define NN 20000
#define EE 160000
#define FIN 9
#define F 64
#define NL 7
#define DIM 3
#define BN_EPS 1e-5f

typedef unsigned long long ull;
union F4U { float4 v; ull u[2]; float f[4]; };

// ---------------- device scratch ----------------
__device__ float d_h[NN * F];
__device__ float d_pos[NN * DIM];
__device__ float d_m1[EE * F];
__device__ float d_dvec[EE * DIM];
__device__ float d_aggm[NN * F];
__device__ float d_aggpm[NN * DIM];
__device__ int   d_counts[NN];
__device__ float d_invc[NN];
__device__ float d_bnsum[F];
__device__ float d_bnsumsq[F];
__device__ float d_bnA[F];
__device__ float d_bnBias2[F];

__device__ __forceinline__ float silu_f(float x) { return x / (1.0f + expf(-x)); }

__device__ __forceinline__ ull ffma2(ull a, ull b, ull c) {
    ull d;
    asm("fma.rn.f32x2 %0, %1, %2, %3;" : "=l"(d) : "l"(a), "l"(b), "l"(c));
    return d;
}
__device__ __forceinline__ float lane_sum(ull a) {
    float lo = __uint_as_float((unsigned)(a & 0xffffffffull));
    float hi = __uint_as_float((unsigned)(a >> 32));
    return lo + hi;
}

// Register-tiled GEMM core: 128 rows x 64 cols per 256-thread block.
// Thread (et = tid&15, jt = tid>>4) owns rows {et + 16*e0 : e0<8}, cols jt*4..+3.
// sWt is TRANSPOSED weight [64][PW] (sWt[j][k] = W[k][j]); lanes of the f32x2
// accumulator hold even-k / odd-k partial sums (merge with lane_sum).
template<int PF, int PW>
__device__ __forceinline__ void gemm_acc(const float* __restrict__ sf,
                                         const float* __restrict__ sWt,
                                         int kmax, int et, int jt, ull acc[8][4]) {
    const float* fb = sf + et * PF;
    const float* wb = sWt + (jt * 4) * PW;
    #pragma unroll 2
    for (int k0 = 0; k0 < kmax; k0 += 4) {
        ull w[4][2];
        #pragma unroll
        for (int j = 0; j < 4; ++j) {
            F4U t; t.v = *(const float4*)(wb + j * PW + k0);
            w[j][0] = t.u[0]; w[j][1] = t.u[1];
        }
        #pragma unroll
        for (int e = 0; e < 8; ++e) {
            F4U t; t.v = *(const float4*)(fb + e * 16 * PF + k0);
            #pragma unroll
            for (int j = 0; j < 4; ++j) {
                acc[e][j] = ffma2(t.u[0], w[j][0], acc[e][j]);
                acc[e][j] = ffma2(t.u[1], w[j][1], acc[e][j]);
            }
        }
    }
}

// ---------------- init ----------------
__global__ void init_kernel(const float* __restrict__ pos_in) {
    int i = blockIdx.x * blockDim.x + threadIdx.x;
    if (i < NN * F) d_aggm[i] = 0.0f;
    if (i < NN * DIM) { d_aggpm[i] = 0.0f; d_pos[i] = pos_in[i]; }
    if (i < NN) d_counts[i] = 0;
    if (i < F) { d_bnsum[i] = 0.0f; d_bnsumsq[i] = 0.0f; }
}
__global__ void count_kernel(const int* __restrict__ edge_dst) {
    int i = blockIdx.x * blockDim.x + threadIdx.x;
    if (i < EE) atomicAdd(&d_counts[edge_dst[i]], 1);
}
__global__ void inv_kernel() {
    int i = blockIdx.x * blockDim.x + threadIdx.x;
    if (i < NN) d_invc[i] = 1.0f / fmaxf((float)d_counts[i], 1.0f);
}

// ---------------- embedding ----------------
// smem: sf[128*12] sW1t[64*12] sfB[128*68] sW2t[64*68] sb1[64] sb2[64]
#define EM_SMEM ((128*12 + 64*12 + 128*68 + 64*68 + 128) * (int)sizeof(float))
__global__ void embed_kernel(const float* __restrict__ h_in,
                             const float* __restrict__ W1, const float* __restrict__ b1,
                             const float* __restrict__ W2, const float* __restrict__ b2) {
    extern __shared__ float sm[];
    float* sf   = sm;                  // 128*12
    float* sW1t = sf + 128 * 12;       // 64*12
    float* sfB  = sW1t + 64 * 12;      // 128*68
    float* sW2t = sfB + 128 * 68;      // 64*68
    float* sb1  = sW2t + 64 * 68;      // 64
    float* sb2  = sb1 + 64;            // 64
    int tid = threadIdx.x;
    int base = blockIdx.x * 128;
    for (int idx = tid; idx < 64 * 12; idx += 256) {
        int j = idx / 12, k = idx - j * 12;
        sW1t[idx] = (k < FIN) ? W1[k * 64 + j] : 0.0f;
    }
    for (int idx = tid; idx < 64 * 64; idx += 256) {
        int k = idx >> 6, j = idx & 63;
        sW2t[j * 68 + k] = W2[idx];
    }
    if (tid < 64) { sb1[tid] = b1[tid]; sb2[tid] = b2[tid]; }
    for (int idx = tid; idx < 128 * 12; idx += 256) {
        int e = idx / 12, k = idx - e * 12;
        int n = base + e;
        sf[idx] = (k < FIN && n < NN) ? h_in[n * FIN + k] : 0.0f;
    }
    __syncthreads();
    int et = tid & 15, jt = tid >> 4;
    {
        ull acc[8][4] = {};
        gemm_acc<12, 12>(sf, sW1t, 12, et, jt, acc);
        #pragma unroll
        for (int e = 0; e < 8; ++e) {
            F4U o;
            #pragma unroll
            for (int j = 0; j < 4; ++j)
                o.f[j] = silu_f(lane_sum(acc[e][j]) + sb1[jt * 4 + j]);
            *(float4*)(sfB + (et + 16 * e) * 68 + jt * 4) = o.v;
        }
    }
    __syncthreads();
    {
        ull acc[8][4] = {};
        gemm_acc<68, 68>(sfB, sW2t, 64, et, jt, acc);
        #pragma unroll
        for (int e = 0; e < 8; ++e) {
            int n = base + et + 16 * e;
            if (n < NN) {
                F4U o;
                #pragma unroll
                for (int j = 0; j < 4; ++j)
                    o.f[j] = lane_sum(acc[e][j]) + sb2[jt * 4 + j];
                *(float4*)(d_h + n * 64 + jt * 4) = o.v;
            }
        }
    }
}

// ---------------- pass1: m1 = silu(feat @ W1 + b1), BN partial sums ----------------
// smem: sf[128*132] sWt[64*132] sred[16*64] sb1[64] sidx[256(int)]
#define P1_SMEM ((128*132 + 64*132 + 16*64 + 64 + 256) * (int)sizeof(float))
__global__ void __launch_bounds__(256, 2)
pass1_kernel(const int* __restrict__ esrc, const int* __restrict__ edst,
             const float* __restrict__ cell,
             const float* __restrict__ W1, const float* __restrict__ b1) {
    extern __shared__ float sm[];
    float* sf   = sm;                    // 128*132
    float* sWt  = sf + 128 * 132;        // 64*132
    float* sred = sWt + 64 * 132;        // 16*64
    float* sb1  = sred + 16 * 64;        // 64
    int*   sidx = (int*)(sb1 + 64);      // 256
    int tid = threadIdx.x;
    int base = blockIdx.x * 128;
    for (int idx = tid; idx < 129 * 64; idx += 256) {
        int k = idx >> 6, j = idx & 63;
        sWt[j * 132 + k] = W1[idx];
    }
    if (tid < 64) sb1[tid] = b1[tid];
    if (tid < 128) { sidx[tid] = edst[base + tid]; sidx[128 + tid] = esrc[base + tid]; }
    __syncthreads();
    // gather [h[dst], h[src]] rows
    for (int idx = tid; idx < 128 * 32; idx += 256) {
        int e = idx >> 5, q = idx & 31;
        int n = (q < 16) ? sidx[e] : sidx[128 + e];
        int qq = q & 15;
        *(float4*)(sf + e * 132 + q * 4) = *(const float4*)(d_h + n * 64 + qq * 4);
    }
    if (tid < 128) {
        int d = sidx[tid], s = sidx[128 + tid];
        int ge = base + tid;
        float dv0 = d_pos[d * 3 + 0] - d_pos[s * 3 + 0] + cell[ge * 3 + 0];
        float dv1 = d_pos[d * 3 + 1] - d_pos[s * 3 + 1] + cell[ge * 3 + 1];
        float dv2 = d_pos[d * 3 + 2] - d_pos[s * 3 + 2] + cell[ge * 3 + 2];
        d_dvec[ge * 3 + 0] = dv0; d_dvec[ge * 3 + 1] = dv1; d_dvec[ge * 3 + 2] = dv2;
        sf[tid * 132 + 128] = dv0 + dv1 + dv2;
    }
    __syncthreads();
    int et = tid & 15, jt = tid >> 4;
    ull acc[8][4] = {};
    gemm_acc<132, 132>(sf, sWt, 128, et, jt, acc);
    float lsum[4] = {0, 0, 0, 0}, lsq[4] = {0, 0, 0, 0};
    #pragma unroll
    for (int e = 0; e < 8; ++e) {
        int er = et + 16 * e;
        float fk = sf[er * 132 + 128];
        F4U o;
        #pragma unroll
        for (int j = 0; j < 4; ++j) {
            float v = lane_sum(acc[e][j]) + fk * sWt[(jt * 4 + j) * 132 + 128] + sb1[jt * 4 + j];
            v = silu_f(v);
            o.f[j] = v; lsum[j] += v; lsq[j] += v * v;
        }
        *(float4*)(d_m1 + (base + er) * 64 + jt * 4) = o.v;
    }
    #pragma unroll
    for (int j = 0; j < 4; ++j) sred[et * 64 + jt * 4 + j] = lsum[j];
    __syncthreads();
    if (tid < 64) {
        float s = 0;
        #pragma unroll
        for (int r = 0; r < 16; ++r) s += sred[r * 64 + tid];
        atomicAdd(&d_bnsum[tid], s);
    }
    __syncthreads();
    #pragma unroll
    for (int j = 0; j < 4; ++j) sred[et * 64 + jt * 4 + j] = lsq[j];
    __syncthreads();
    if (tid < 64) {
        float s = 0;
        #pragma unroll
        for (int r = 0; r < 16; ++r) s += sred[r * 64 + tid];
        atomicAdd(&d_bnsumsq[tid], s);
    }
}

// ---------------- BN finalize: fold affine into W2-scale (A) + bias2 ----------------
__global__ void bn_finalize_kernel(const float* __restrict__ gamma, const float* __restrict__ beta,
                                   const float* __restrict__ W2, const float* __restrict__ b2) {
    __shared__ float sB[F];
    int j = threadIdx.x;
    float mu  = d_bnsum[j]   * (1.0f / (float)EE);
    float var = d_bnsumsq[j] * (1.0f / (float)EE) - mu * mu;
    float inv = rsqrtf(var + BN_EPS);
    float A = gamma[j] * inv;
    d_bnA[j] = A;
    sB[j] = beta[j] - mu * A;
    d_bnsum[j] = 0.0f; d_bnsumsq[j] = 0.0f;
    __syncthreads();
    float acc = b2[j];
    #pragma unroll
    for (int k = 0; k < F; ++k) acc += sB[k] * W2[k * F + j];
    d_bnBias2[j] = acc;
}

// ---------------- pass2: m = mnorm@W2+b2' ; t = silu(m@pW1+pb1) ; pm = dvec*(t@pW2+pb2) ----------------
// smem: sfA[128*68] sfB[128*68] sW2t[64*68] spW1t[64*68] spW2[192] sdv[384] sb2[64] spb1[64] spb2[4] sdst[128]
#define P2_SMEM ((128*68*2 + 64*68*2 + 192 + 384 + 64 + 64 + 4 + 128) * (int)sizeof(float))
__global__ void __launch_bounds__(256, 2)
pass2_kernel(const int* __restrict__ edst,
             const float* __restrict__ W2,
             const float* __restrict__ pW1, const float* __restrict__ pb1,
             const float* __restrict__ pW2, const float* __restrict__ pb2) {
    extern __shared__ float sm[];
    float* sfA   = sm;                   // 128*68
    float* sfB   = sfA + 128 * 68;       // 128*68
    float* sW2t  = sfB + 128 * 68;       // 64*68  (BN A folded in)
    float* spW1t = sW2t + 64 * 68;       // 64*68
    float* spW2  = spW1t + 64 * 68;      // 192
    float* sdv   = spW2 + 192;           // 384
    float* sb2   = sdv + 384;            // 64 (folded bias2)
    float* spb1  = sb2 + 64;             // 64
    float* spb2  = spb1 + 64;            // 4
    int*   sdst  = (int*)(spb2 + 4);     // 128
    int tid = threadIdx.x;
    int base = blockIdx.x * 128;
    for (int idx = tid; idx < 64 * 64; idx += 256) {
        int k = idx >> 6, j = idx & 63;
        sW2t[j * 68 + k]  = W2[idx] * d_bnA[k];
        spW1t[j * 68 + k] = pW1[idx];
    }
    for (int idx = tid; idx < 192; idx += 256) spW2[idx] = pW2[idx];
    if (tid < 64) { sb2[tid] = d_bnBias2[tid]; spb1[tid] = pb1[tid]; }
    if (tid < 3) spb2[tid] = pb2[tid];
    if (tid < 128) sdst[tid] = edst[base + tid];
    for (int idx = tid; idx < 128 * 16; idx += 256) {
        int e = idx >> 4, q = idx & 15;
        *(float4*)(sfA + e * 68 + q * 4) = *(const float4*)(d_m1 + (base + e) * 64 + q * 4);
    }
    for (int idx = tid; idx < 384; idx += 256) sdv[idx] = d_dvec[base * 3 + idx];
    __syncthreads();
    int et = tid & 15, jt = tid >> 4;
    {   // GEMM1: m = m1 @ W2A + bias2  (no activation); scatter + stage to sfB
        ull acc[8][4] = {};
        gemm_acc<68, 68>(sfA, sW2t, 64, et, jt, acc);
        #pragma unroll
        for (int e = 0; e < 8; ++e) {
            int er = et + 16 * e;
            int dn = sdst[er];
            F4U o;
            #pragma unroll
            for (int j = 0; j < 4; ++j) {
                float v = lane_sum(acc[e][j]) + sb2[jt * 4 + j];
                o.f[j] = v;
                atomicAdd(&d_aggm[dn * 64 + jt * 4 + j], v);
            }
            *(float4*)(sfB + er * 68 + jt * 4) = o.v;
        }
    }
    __syncthreads();
    {   // GEMM2: t = silu(m @ pW1 + pb1) -> sfA
        ull acc[8][4] = {};
        gemm_acc<68, 68>(sfB, spW1t, 64, et, jt, acc);
        #pragma unroll
        for (int e = 0; e < 8; ++e) {
            F4U o;
            #pragma unroll
            for (int j = 0; j < 4; ++j)
                o.f[j] = silu_f(lane_sum(acc[e][j]) + spb1[jt * 4 + j]);
            *(float4*)(sfA + (et + 16 * e) * 68 + jt * 4) = o.v;
        }
    }
    __syncthreads();
    if (tid < 128) {   // stage3: s = t @ pW2 + pb2 ; pm = dvec*s ; scatter
        float s0 = spb2[0], s1 = spb2[1], s2 = spb2[2];
        #pragma unroll
        for (int q = 0; q < 16; ++q) {
            F4U t; t.v = *(const float4*)(sfA + tid * 68 + q * 4);
            #pragma unroll
            for (int c = 0; c < 4; ++c) {
                int k = q * 4 + c;
                s0 += t.f[c] * spW2[k * 3 + 0];
                s1 += t.f[c] * spW2[k * 3 + 1];
                s2 += t.f[c] * spW2[k * 3 + 2];
            }
        }
        int dn = sdst[tid];
        atomicAdd(&d_aggpm[dn * 3 + 0], sdv[tid * 3 + 0] * s0);
        atomicAdd(&d_aggpm[dn * 3 + 1], sdv[tid * 3 + 1] * s1);
        atomicAdd(&d_aggpm[dn * 3 + 2], sdv[tid * 3 + 2] * s2);
    }
}

// ---------------- node update ----------------
// smem: sfA[128*132] sfB[128*68] sW1t[64*132] sW2t[64*68] sW3t[64*68] sb[192]
#define ND_SMEM ((128*132 + 128*68 + 64*132 + 64*68*2 + 192) * (int)sizeof(float))
__global__ void node_kernel(const float* __restrict__ uW1, const float* __restrict__ ub1,
                            const float* __restrict__ uW2, const float* __restrict__ ub2,
                            const float* __restrict__ uW3, const float* __restrict__ ub3) {
    extern __shared__ float sm[];
    float* sfA  = sm;                    // 128*132
    float* sfB  = sfA + 128 * 132;       // 128*68
    float* sW1t = sfB + 128 * 68;        // 64*132
    float* sW2t = sW1t + 64 * 132;       // 64*68
    float* sW3t = sW2t + 64 * 68;        // 64*68
    float* sb1  = sW3t + 64 * 68;        // 64
    float* sb2  = sb1 + 64;
    float* sb3  = sb2 + 64;
    int tid = threadIdx.x;
    int base = blockIdx.x * 128;
    for (int idx = tid; idx < 128 * 64; idx += 256) {
        int k = idx >> 6, j = idx & 63;
        sW1t[j * 132 + k] = uW1[idx];
    }
    for (int idx = tid; idx < 64 * 64; idx += 256) {
        int k = idx >> 6, j = idx & 63;
        sW2t[j * 68 + k] = uW2[idx];
        sW3t[j * 68 + k] = uW3[idx];
    }
    if (tid < 64) { sb1[tid] = ub1[tid]; sb2[tid] = ub2[tid]; sb3[tid] = ub3[tid]; }
    // gather [h, agg_m/cnt]; zero agg for next layer
    for (int idx = tid; idx < 128 * 32; idx += 256) {
        int e = idx >> 5, q = idx & 31;
        int n = base + e;
        F4U t;
        if (n < NN) {
            int qq = q & 15;
            if (q < 16) {
                t.v = *(const float4*)(d_h + n * 64 + qq * 4);
            } else {
                t.v = *(const float4*)(d_aggm + n * 64 + qq * 4);
                float inv = d_invc[n];
                t.f[0] *= inv; t.f[1] *= inv; t.f[2] *= inv; t.f[3] *= inv;
                *(float4*)(d_aggm + n * 64 + qq * 4) = make_float4(0.f, 0.f, 0.f, 0.f);
            }
        } else {
            t.v = make_float4(0.f, 0.f, 0.f, 0.f);
        }
        *(float4*)(sfA + e * 132 + q * 4) = t.v;
    }
    if (tid < 128) {   // pos update
        int n = base + tid;
        if (n < NN) {
            float inv = d_invc[n];
            #pragma unroll
            for (int c = 0; c < 3; ++c) {
                d_pos[n * 3 + c] += d_aggpm[n * 3 + c] * inv;
                d_aggpm[n * 3 + c] = 0.0f;
            }
        }
    }
    __syncthreads();
    int et = tid & 15, jt = tid >> 4;
    {   // u = silu([h,agg] @ uW1 + b1)
        ull acc[8][4] = {};
        gemm_acc<132, 132>(sfA, sW1t, 128, et, jt, acc);
        #pragma unroll
        for (int e = 0; e < 8; ++e) {
            F4U o;
            #pragma unroll
            for (int j = 0; j < 4; ++j)
                o.f[j] = silu_f(lane_sum(acc[e][j]) + sb1[jt * 4 + j]);
            *(float4*)(sfB + (et + 16 * e) * 68 + jt * 4) = o.v;
        }
    }
    __syncthreads();
    {   // v = silu(u @ uW2 + b2) -> sfA (pitch 132, cols 0..63)
        ull acc[8][4] = {};
        gemm_acc<68, 68>(sfB, sW2t, 64, et, jt, acc);
        #pragma unroll
        for (int e = 0; e < 8; ++e) {
            F4U o;
            #pragma unroll
            for (int j = 0; j < 4; ++j)
                o.f[j] = silu_f(lane_sum(acc[e][j]) + sb2[jt * 4 + j]);
            *(float4*)(sfA + (et + 16 * e) * 132 + jt * 4) = o.v;
        }
    }
    __syncthreads();
    {   // h += v @ uW3 + b3
        ull acc[8][4] = {};
        gemm_acc<132, 68>(sfA, sW3t, 64, et, jt, acc);
        #pragma unroll
        for (int e = 0; e < 8; ++e) {
            int n = base + et + 16 * e;
            if (n < NN) {
                F4U h; h.v = *(const float4*)(d_h + n * 64 + jt * 4);
                F4U o;
                #pragma unroll
                for (int j = 0; j < 4; ++j)
                    o.f[j] = h.f[j] + lane_sum(acc[e][j]) + sb3[jt * 4 + j];
                *(float4*)(d_h + n * 64 + jt * 4) = o.v;
            }
        }
    }
}

// ---------------- energy MLP ----------------
#define EN_SMEM ((128*68*2 + 64*68*2 + 64 + 64 + 64 + 4) * (int)sizeof(float))
__global__ void energy_kernel(const float* __restrict__ W1, const float* __restrict__ b1,
                              const float* __restrict__ W2, const float* __restrict__ b2,
                              const float* __restrict__ W3, const float* __restrict__ b3,
                              float* __restrict__ out) {
    extern __shared__ float sm[];
    float* sfA  = sm;                   // 128*68
    float* sfB  = sfA + 128 * 68;       // 128*68
    float* sW1t = sfB + 128 * 68;       // 64*68
    float* sW2t = sW1t + 64 * 68;       // 64*68
    float* sW3  = sW2t + 64 * 68;       // 64
    float* sb1  = sW3 + 64;
    float* sb2  = sb1 + 64;
    float* sb3  = sb2 + 64;             // 1
    int tid = threadIdx.x;
    int base = blockIdx.x * 128;
    for (int idx = tid; idx < 64 * 64; idx += 256) {
        int k = idx >> 6, j = idx & 63;
        sW1t[j * 68 + k] = W1[idx];
        sW2t[j * 68 + k] = W2[idx];
    }
    if (tid < 64) { sW3[tid] = W3[tid]; sb1[tid] = b1[tid]; sb2[tid] = b2[tid]; }
    if (tid == 0) sb3[0] = b3[0];
    for (int idx = tid; idx < 128 * 16; idx += 256) {
        int e = idx >> 4, q = idx & 15;
        int n = base + e;
        float4 v = (n < NN) ? *(const float4*)(d_h + n * 64 + q * 4)
                            : make_float4(0.f, 0.f, 0.f, 0.f);
        *(float4*)(sfA + e * 68 + q * 4) = v;
    }
    __syncthreads();
    int et = tid & 15, jt = tid >> 4;
    {
        ull acc[8][4] = {};
        gemm_acc<68, 68>(sfA, sW1t, 64, et, jt, acc);
        #pragma unroll
        for (int e = 0; e < 8; ++e) {
            F4U o;
            #pragma unroll
            for (int j = 0; j < 4; ++j)
                o.f[j] = silu_f(lane_sum(acc[e][j]) + sb1[jt * 4 + j]);
            *(float4*)(sfB + (et + 16 * e) * 68 + jt * 4) = o.v;
        }
    }
    __syncthreads();
    {
        ull acc[8][4] = {};
        gemm_acc<68, 68>(sfB, sW2t, 64, et, jt, acc);
        #pragma unroll
        for (int e = 0; e < 8; ++e) {
            F4U o;
            #pragma unroll
            for (int j = 0; j < 4; ++j)
                o.f[j] = silu_f(lane_sum(acc[e][j]) + sb2[jt * 4 + j]);
            *(float4*)(sfA + (et + 16 * e) * 68 + jt * 4) = o.v;
        }
    }
    __syncthreads();
    if (tid < 128) {
        int n = base + tid;
        if (n < NN) {
            float s = sb3[0];
            #pragma unroll
            for (int q = 0; q < 16; ++q) {
                F4U t; t.v = *(const float4*)(sfA + tid * 68 + q * 4);
                #pragma unroll
                for (int c = 0; c < 4; ++c) s += t.f[c] * sW3[q * 4 + c];
            }
            out[n] = s;
        }
    }
}

// ---------------- launch ----------------
extern "C" void kernel_launch(void* const* d_in, const int* in_sizes, int n_in,
                              void* d_out, int out_size) {
    const float* h_in   = (const float*)d_in[0];
    const float* pos    = (const float*)d_in[1];
    const float* cell   = (const float*)d_in[2];
    const int*   esrc   = (const int*)d_in[3];
    const int*   edst   = (const int*)d_in[4];
    const float* emb_W1 = (const float*)d_in[5];
    const float* emb_b1 = (const float*)d_in[6];
    const float* emb_W2 = (const float*)d_in[7];
    const float* emb_b2 = (const float*)d_in[8];
    const float* msg_W1 = (const float*)d_in[9];
    const float* msg_b1 = (const float*)d_in[10];
    const float* bn_g   = (const float*)d_in[11];
    const float* bn_b   = (const float*)d_in[12];
    const float* msg_W2 = (const float*)d_in[13];
    const float* msg_b2 = (const float*)d_in[14];
    const float* upd_W1 = (const float*)d_in[15];
    const float* upd_b1 = (const float*)d_in[16];
    const float* upd_W2 = (const float*)d_in[17];
    const float* upd_b2 = (const float*)d_in[18];
    const float* upd_W3 = (const float*)d_in[19];
    const float* upd_b3 = (const float*)d_in[20];
    const float* pos_W1 = (const float*)d_in[21];
    const float* pos_b1 = (const float*)d_in[22];
    const float* pos_W2 = (const float*)d_in[23];
    const float* pos_b2 = (const float*)d_in[24];
    const float* en_W1  = (const float*)d_in[25];
    const float* en_b1  = (const float*)d_in[26];
    const float* en_W2  = (const float*)d_in[27];
    const float* en_b2  = (const float*)d_in[28];
    const float* en_W3  = (const float*)d_in[29];
    const float* en_b3  = (const float*)d_in[30];
    float* out = (float*)d_out;

    static int attr_done = 0;
    if (!attr_done) {
        cudaFuncSetAttribute(embed_kernel,  cudaFuncAttributeMaxDynamicSharedMemorySize, EM_SMEM);
        cudaFuncSetAttribute(pass1_kernel,  cudaFuncAttributeMaxDynamicSharedMemorySize, P1_SMEM);
        cudaFuncSetAttribute(pass2_kernel,  cudaFuncAttributeMaxDynamicSharedMemorySize, P2_SMEM);
        cudaFuncSetAttribute(node_kernel,   cudaFuncAttributeMaxDynamicSharedMemorySize, ND_SMEM);
        cudaFuncSetAttribute(energy_kernel, cudaFuncAttributeMaxDynamicSharedMemorySize, EN_SMEM);
        attr_done = 1;
    }

    init_kernel<<<(NN * F + 255) / 256, 256>>>(pos);
    count_kernel<<<(EE + 255) / 256, 256>>>(edst);
    inv_kernel<<<(NN + 255) / 256, 256>>>();
    embed_kernel<<<157, 256, EM_SMEM>>>(h_in, emb_W1, emb_b1, emb_W2, emb_b2);

    for (int l = 0; l < NL; ++l) {
        pass1_kernel<<<1250, 256, P1_SMEM>>>(esrc, edst, cell,
                                             msg_W1 + l * (2 * F + 1) * F, msg_b1 + l * F);
        bn_finalize_kernel<<<1, 64>>>(bn_g + l * F, bn_b + l * F,
                                      msg_W2 + l * F * F, msg_b2 + l * F);
        pass2_kernel<<<1250, 256, P2_SMEM>>>(edst,
                                             msg_W2 + l * F * F,
                                             pos_W1 + l * F * F, pos_b1 + l * F,
                                             pos_W2 + l * F * DIM, pos_b2 + l * DIM);
        node_kernel<<<157, 256, ND_SMEM>>>(upd_W1 + l * 2 * F * F, upd_b1 + l * F,
                                           upd_W2 + l * F * F, upd_b2 + l * F,
                                           upd_W3 + l * F * F, upd_b3 + l * F);
    }
    energy_kernel<<<157, 256, EN_SMEM>>>(en_W1, en_b1, en_W2, en_b2, en_W3, en_b3, out);
}

// round 5
// speedup vs baseline: 2.8048x; 1.0973x over previous
#include <cuda_runtime.h>
#include <cuda_bf16.h>

#define NN 20000
#define EE 160000
#define FIN 9
#define F 64
#define NL 7
#define DIM 3
#define BN_EPS 1e-5f

typedef unsigned long long ull;
union F4U { float4 v; ull u[2]; float f[4]; };

// ---------------- device scratch ----------------
__device__ float d_h[NN * F];
__device__ float d_pos[NN * DIM];
__device__ float d_m1[EE * F];
__device__ float d_dvec[EE * DIM];
__device__ float d_aggm[NN * F];
__device__ float d_aggpm[NN * DIM];
__device__ int   d_counts[NN];
__device__ float d_invc[NN];
__device__ float d_bnsum[NL * F];
__device__ float d_bnsumsq[NL * F];

__device__ __forceinline__ float silu_f(float x) { return x / (1.0f + expf(-x)); }

__device__ __forceinline__ ull ffma2(ull a, ull b, ull c) {
    ull d;
    asm("fma.rn.f32x2 %0, %1, %2, %3;" : "=l"(d) : "l"(a), "l"(b), "l"(c));
    return d;
}
__device__ __forceinline__ float lane_sum(ull a) {
    float lo = __uint_as_float((unsigned)(a & 0xffffffffull));
    float hi = __uint_as_float((unsigned)(a >> 32));
    return lo + hi;
}

// 64 rows x 64 cols per 256-thread block; thread (et=tid&15, jt=tid>>4)
// owns rows {et+16*e : e<4}, cols jt*4..+3. sWt transposed [64][PW].
template<int PF, int PW>
__device__ __forceinline__ void gemm_acc4(const float* __restrict__ sf,
                                          const float* __restrict__ sWt,
                                          int kmax, int et, int jt, ull acc[4][4]) {
    const float* fb = sf + et * PF;
    const float* wb = sWt + (jt * 4) * PW;
    #pragma unroll 2
    for (int k0 = 0; k0 < kmax; k0 += 4) {
        ull w[4][2];
        #pragma unroll
        for (int j = 0; j < 4; ++j) {
            F4U t; t.v = *(const float4*)(wb + j * PW + k0);
            w[j][0] = t.u[0]; w[j][1] = t.u[1];
        }
        #pragma unroll
        for (int e = 0; e < 4; ++e) {
            F4U t; t.v = *(const float4*)(fb + e * 16 * PF + k0);
            #pragma unroll
            for (int j = 0; j < 4; ++j) {
                acc[e][j] = ffma2(t.u[0], w[j][0], acc[e][j]);
                acc[e][j] = ffma2(t.u[1], w[j][1], acc[e][j]);
            }
        }
    }
}

// 128-row variant (embed/energy keep the bigger tile)
template<int PF, int PW>
__device__ __forceinline__ void gemm_acc(const float* __restrict__ sf,
                                         const float* __restrict__ sWt,
                                         int kmax, int et, int jt, ull acc[8][4]) {
    const float* fb = sf + et * PF;
    const float* wb = sWt + (jt * 4) * PW;
    #pragma unroll 2
    for (int k0 = 0; k0 < kmax; k0 += 4) {
        ull w[4][2];
        #pragma unroll
        for (int j = 0; j < 4; ++j) {
            F4U t; t.v = *(const float4*)(wb + j * PW + k0);
            w[j][0] = t.u[0]; w[j][1] = t.u[1];
        }
        #pragma unroll
        for (int e = 0; e < 8; ++e) {
            F4U t; t.v = *(const float4*)(fb + e * 16 * PF + k0);
            #pragma unroll
            for (int j = 0; j < 4; ++j) {
                acc[e][j] = ffma2(t.u[0], w[j][0], acc[e][j]);
                acc[e][j] = ffma2(t.u[1], w[j][1], acc[e][j]);
            }
        }
    }
}

// ---------------- init ----------------
__global__ void init_kernel(const float* __restrict__ pos_in) {
    int i = blockIdx.x * blockDim.x + threadIdx.x;
    if (i < NN * F) d_aggm[i] = 0.0f;
    if (i < NN * DIM) { d_aggpm[i] = 0.0f; d_pos[i] = pos_in[i]; }
    if (i < NN) d_counts[i] = 0;
    if (i < NL * F) { d_bnsum[i] = 0.0f; d_bnsumsq[i] = 0.0f; }
}
__global__ void count_kernel(const int* __restrict__ edge_dst) {
    int i = blockIdx.x * blockDim.x + threadIdx.x;
    if (i < EE) atomicAdd(&d_counts[edge_dst[i]], 1);
}
__global__ void inv_kernel() {
    int i = blockIdx.x * blockDim.x + threadIdx.x;
    if (i < NN) d_invc[i] = 1.0f / fmaxf((float)d_counts[i], 1.0f);
}

// ---------------- embedding (unchanged, 128 rows) ----------------
#define EM_SMEM ((128*12 + 64*12 + 128*68 + 64*68 + 128) * (int)sizeof(float))
__global__ void embed_kernel(const float* __restrict__ h_in,
                             const float* __restrict__ W1, const float* __restrict__ b1,
                             const float* __restrict__ W2, const float* __restrict__ b2) {
    extern __shared__ float sm[];
    float* sf   = sm;
    float* sW1t = sf + 128 * 12;
    float* sfB  = sW1t + 64 * 12;
    float* sW2t = sfB + 128 * 68;
    float* sb1  = sW2t + 64 * 68;
    float* sb2  = sb1 + 64;
    int tid = threadIdx.x;
    int base = blockIdx.x * 128;
    for (int idx = tid; idx < 64 * 12; idx += 256) {
        int j = idx / 12, k = idx - j * 12;
        sW1t[idx] = (k < FIN) ? W1[k * 64 + j] : 0.0f;
    }
    for (int idx = tid; idx < 64 * 64; idx += 256) {
        int k = idx >> 6, j = idx & 63;
        sW2t[j * 68 + k] = W2[idx];
    }
    if (tid < 64) { sb1[tid] = b1[tid]; sb2[tid] = b2[tid]; }
    for (int idx = tid; idx < 128 * 12; idx += 256) {
        int e = idx / 12, k = idx - e * 12;
        int n = base + e;
        sf[idx] = (k < FIN && n < NN) ? h_in[n * FIN + k] : 0.0f;
    }
    __syncthreads();
    int et = tid & 15, jt = tid >> 4;
    {
        ull acc[8][4] = {};
        gemm_acc<12, 12>(sf, sW1t, 12, et, jt, acc);
        #pragma unroll
        for (int e = 0; e < 8; ++e) {
            F4U o;
            #pragma unroll
            for (int j = 0; j < 4; ++j)
                o.f[j] = silu_f(lane_sum(acc[e][j]) + sb1[jt * 4 + j]);
            *(float4*)(sfB + (et + 16 * e) * 68 + jt * 4) = o.v;
        }
    }
    __syncthreads();
    {
        ull acc[8][4] = {};
        gemm_acc<68, 68>(sfB, sW2t, 64, et, jt, acc);
        #pragma unroll
        for (int e = 0; e < 8; ++e) {
            int n = base + et + 16 * e;
            if (n < NN) {
                F4U o;
                #pragma unroll
                for (int j = 0; j < 4; ++j)
                    o.f[j] = lane_sum(acc[e][j]) + sb2[jt * 4 + j];
                *(float4*)(d_h + n * 64 + jt * 4) = o.v;
            }
        }
    }
}

// ---------------- pass1: 64 edges/block, 3 CTAs/SM ----------------
// smem: sWt[64*132] sf[64*132] sb1[64] sidx[128]
#define P1_SMEM ((64*132 + 64*132 + 64 + 128) * (int)sizeof(float))
__global__ void __launch_bounds__(256, 3)
pass1_kernel(const int* __restrict__ esrc, const int* __restrict__ edst,
             const float* __restrict__ cell,
             const float* __restrict__ W1, const float* __restrict__ b1, int l) {
    extern __shared__ float sm[];
    float* sWt  = sm;                    // 64*132
    float* sf   = sWt + 64 * 132;        // 64*132
    float* sb1  = sf + 64 * 132;         // 64
    int*   sidx = (int*)(sb1 + 64);      // 128
    int tid = threadIdx.x;
    int base = blockIdx.x * 64;
    for (int idx = tid; idx < 129 * 64; idx += 256) {
        int k = idx >> 6, j = idx & 63;
        sWt[j * 132 + k] = W1[idx];
    }
    if (tid < 64) { sb1[tid] = b1[tid]; sidx[tid] = edst[base + tid]; sidx[64 + tid] = esrc[base + tid]; }
    __syncthreads();
    for (int idx = tid; idx < 64 * 32; idx += 256) {
        int e = idx >> 5, q = idx & 31;
        int n = (q < 16) ? sidx[e] : sidx[64 + e];
        int qq = q & 15;
        *(float4*)(sf + e * 132 + q * 4) = *(const float4*)(d_h + n * 64 + qq * 4);
    }
    if (tid < 64) {
        int d = sidx[tid], s = sidx[64 + tid];
        int ge = base + tid;
        float dv0 = d_pos[d * 3 + 0] - d_pos[s * 3 + 0] + cell[ge * 3 + 0];
        float dv1 = d_pos[d * 3 + 1] - d_pos[s * 3 + 1] + cell[ge * 3 + 1];
        float dv2 = d_pos[d * 3 + 2] - d_pos[s * 3 + 2] + cell[ge * 3 + 2];
        d_dvec[ge * 3 + 0] = dv0; d_dvec[ge * 3 + 1] = dv1; d_dvec[ge * 3 + 2] = dv2;
        sf[tid * 132 + 128] = dv0 + dv1 + dv2;
    }
    __syncthreads();
    int et = tid & 15, jt = tid >> 4;
    ull acc[4][4] = {};
    gemm_acc4<132, 132>(sf, sWt, 128, et, jt, acc);
    float lsum[4] = {0, 0, 0, 0}, lsq[4] = {0, 0, 0, 0};
    #pragma unroll
    for (int e = 0; e < 4; ++e) {
        int er = et + 16 * e;
        float fk = sf[er * 132 + 128];
        F4U o;
        #pragma unroll
        for (int j = 0; j < 4; ++j) {
            float v = lane_sum(acc[e][j]) + fk * sWt[(jt * 4 + j) * 132 + 128] + sb1[jt * 4 + j];
            v = silu_f(v);
            o.f[j] = v; lsum[j] += v; lsq[j] += v * v;
        }
        *(float4*)(d_m1 + (base + er) * 64 + jt * 4) = o.v;
    }
    // warp-level reduce over the 16-lane et-group (no smem, no syncs)
    #pragma unroll
    for (int j = 0; j < 4; ++j) {
        #pragma unroll
        for (int o = 1; o < 16; o <<= 1) {
            lsum[j] += __shfl_xor_sync(0xffffffffu, lsum[j], o);
            lsq[j]  += __shfl_xor_sync(0xffffffffu, lsq[j], o);
        }
    }
    if (et == 0) {
        #pragma unroll
        for (int j = 0; j < 4; ++j) {
            atomicAdd(&d_bnsum[l * 64 + jt * 4 + j], lsum[j]);
            atomicAdd(&d_bnsumsq[l * 64 + jt * 4 + j], lsq[j]);
        }
    }
}

// ---------------- pass2: 64 edges/block, BN folded in-block, 3 CTAs/SM ----------------
// smem: sfA[64*68] sfB[64*68] sW2t[64*68] spW1t[64*68] spW2[192] sdv[192]
//       sA[64] sB[64] sbias2[64] spb1[64] spb2[4] sdst[64]
#define P2_SMEM ((64*68*4 + 192 + 192 + 64*4 + 4 + 64) * (int)sizeof(float))
__global__ void __launch_bounds__(256, 3)
pass2_kernel(const int* __restrict__ edst,
             const float* __restrict__ W2, const float* __restrict__ b2,
             const float* __restrict__ gamma, const float* __restrict__ beta,
             const float* __restrict__ pW1, const float* __restrict__ pb1,
             const float* __restrict__ pW2, const float* __restrict__ pb2, int l) {
    extern __shared__ float sm[];
    float* sfA    = sm;                    // 64*68
    float* sfB    = sfA + 64 * 68;
    float* sW2t   = sfB + 64 * 68;
    float* spW1t  = sW2t + 64 * 68;
    float* spW2   = spW1t + 64 * 68;       // 192
    float* sdv    = spW2 + 192;            // 192
    float* sA     = sdv + 192;             // 64
    float* sB     = sA + 64;               // 64
    float* sbias2 = sB + 64;               // 64
    float* spb1   = sbias2 + 64;           // 64
    float* spb2   = spb1 + 64;             // 4
    int*   sdst   = (int*)(spb2 + 4);      // 64
    int tid = threadIdx.x;
    int base = blockIdx.x * 64;
    // phase 0: BN affine from global stats
    if (tid < 64) {
        float mu  = d_bnsum[l * 64 + tid]   * (1.0f / (float)EE);
        float var = d_bnsumsq[l * 64 + tid] * (1.0f / (float)EE) - mu * mu;
        float inv = rsqrtf(var + BN_EPS);
        float A = gamma[tid] * inv;
        sA[tid] = A;
        sB[tid] = beta[tid] - mu * A;
        spb1[tid] = pb1[tid];
    }
    if (tid < 3) spb2[tid] = pb2[tid];
    if (tid >= 64 && tid < 128) sdst[tid - 64] = edst[base + tid - 64];
    for (int idx = tid; idx < 64 * 64; idx += 256) {
        int k = idx >> 6, j = idx & 63;
        sW2t[j * 68 + k]  = W2[idx];
        spW1t[j * 68 + k] = pW1[idx];
    }
    for (int idx = tid; idx < 192; idx += 256) {
        spW2[idx] = pW2[idx];
        sdv[idx] = d_dvec[base * 3 + idx];
    }
    __syncthreads();
    // phase 1: stage m1 pre-scaled by A; bias2 = b2 + B @ W2 (from gmem)
    for (int idx = tid; idx < 64 * 16; idx += 256) {
        int e = idx >> 4, q = idx & 15;
        F4U t; t.v = *(const float4*)(d_m1 + (base + e) * 64 + q * 4);
        t.f[0] *= sA[q * 4 + 0]; t.f[1] *= sA[q * 4 + 1];
        t.f[2] *= sA[q * 4 + 2]; t.f[3] *= sA[q * 4 + 3];
        *(float4*)(sfA + e * 68 + q * 4) = t.v;
    }
    if (tid < 64) {
        float acc = b2[tid];
        #pragma unroll
        for (int k = 0; k < 64; ++k) acc += sB[k] * sW2t[tid * 68 + k];
        sbias2[tid] = acc;
    }
    __syncthreads();
    int et = tid & 15, jt = tid >> 4;
    {   // GEMM1: m = (A*m1) @ W2 + bias2; scatter + stage
        ull acc[4][4] = {};
        gemm_acc4<68, 68>(sfA, sW2t, 64, et, jt, acc);
        #pragma unroll
        for (int e = 0; e < 4; ++e) {
            int er = et + 16 * e;
            int dn = sdst[er];
            F4U o;
            #pragma unroll
            for (int j = 0; j < 4; ++j) {
                float v = lane_sum(acc[e][j]) + sbias2[jt * 4 + j];
                o.f[j] = v;
                atomicAdd(&d_aggm[dn * 64 + jt * 4 + j], v);
            }
            *(float4*)(sfB + er * 68 + jt * 4) = o.v;
        }
    }
    __syncthreads();
    {   // GEMM2: t = silu(m @ pW1 + pb1)
        ull acc[4][4] = {};
        gemm_acc4<68, 68>(sfB, spW1t, 64, et, jt, acc);
        #pragma unroll
        for (int e = 0; e < 4; ++e) {
            F4U o;
            #pragma unroll
            for (int j = 0; j < 4; ++j)
                o.f[j] = silu_f(lane_sum(acc[e][j]) + spb1[jt * 4 + j]);
            *(float4*)(sfA + (et + 16 * e) * 68 + jt * 4) = o.v;
        }
    }
    __syncthreads();
    if (tid < 64) {
        float s0 = spb2[0], s1 = spb2[1], s2 = spb2[2];
        #pragma unroll
        for (int q = 0; q < 16; ++q) {
            F4U t; t.v = *(const float4*)(sfA + tid * 68 + q * 4);
            #pragma unroll
            for (int c = 0; c < 4; ++c) {
                int k = q * 4 + c;
                s0 += t.f[c] * spW2[k * 3 + 0];
                s1 += t.f[c] * spW2[k * 3 + 1];
                s2 += t.f[c] * spW2[k * 3 + 2];
            }
        }
        int dn = sdst[tid];
        atomicAdd(&d_aggpm[dn * 3 + 0], sdv[tid * 3 + 0] * s0);
        atomicAdd(&d_aggpm[dn * 3 + 1], sdv[tid * 3 + 1] * s1);
        atomicAdd(&d_aggpm[dn * 3 + 2], sdv[tid * 3 + 2] * s2);
    }
}

// ---------------- node: 64 nodes/block, W1 staged in halves, 2 CTAs/SM ----------------
// smem: sfA[64*132] sfB[64*68] sWa[64*68] sW2t[64*68] sW3t[64*68] sb[192]
#define ND_SMEM ((64*132 + 64*68*4 + 192) * (int)sizeof(float))
__global__ void __launch_bounds__(256, 2)
node_kernel(const float* __restrict__ uW1, const float* __restrict__ ub1,
            const float* __restrict__ uW2, const float* __restrict__ ub2,
            const float* __restrict__ uW3, const float* __restrict__ ub3) {
    extern __shared__ float sm[];
    float* sfA  = sm;                    // 64*132
    float* sfB  = sfA + 64 * 132;        // 64*68
    float* sWa  = sfB + 64 * 68;         // 64*68 (W1 half, restaged)
    float* sW2t = sWa + 64 * 68;         // 64*68
    float* sW3t = sW2t + 64 * 68;        // 64*68
    float* sb1  = sW3t + 64 * 68;        // 64
    float* sb2  = sb1 + 64;
    float* sb3  = sb2 + 64;
    int tid = threadIdx.x;
    int base = blockIdx.x * 64;
    for (int idx = tid; idx < 64 * 64; idx += 256) {
        int k = idx >> 6, j = idx & 63;
        sWa[j * 68 + k]  = uW1[idx];          // W1 rows 0..63
        sW2t[j * 68 + k] = uW2[idx];
        sW3t[j * 68 + k] = uW3[idx];
    }
    if (tid < 64) { sb1[tid] = ub1[tid]; sb2[tid] = ub2[tid]; sb3[tid] = ub3[tid]; }
    for (int idx = tid; idx < 64 * 32; idx += 256) {
        int e = idx >> 5, q = idx & 31;
        int n = base + e;
        F4U t;
        if (n < NN) {
            int qq = q & 15;
            if (q < 16) {
                t.v = *(const float4*)(d_h + n * 64 + qq * 4);
            } else {
                t.v = *(const float4*)(d_aggm + n * 64 + qq * 4);
                float inv = d_invc[n];
                t.f[0] *= inv; t.f[1] *= inv; t.f[2] *= inv; t.f[3] *= inv;
                *(float4*)(d_aggm + n * 64 + qq * 4) = make_float4(0.f, 0.f, 0.f, 0.f);
            }
        } else {
            t.v = make_float4(0.f, 0.f, 0.f, 0.f);
        }
        *(float4*)(sfA + e * 132 + q * 4) = t.v;
    }
    if (tid < 64) {
        int n = base + tid;
        if (n < NN) {
            float inv = d_invc[n];
            #pragma unroll
            for (int c = 0; c < 3; ++c) {
                d_pos[n * 3 + c] += d_aggpm[n * 3 + c] * inv;
                d_aggpm[n * 3 + c] = 0.0f;
            }
        }
    }
    __syncthreads();
    int et = tid & 15, jt = tid >> 4;
    ull acc[4][4] = {};
    gemm_acc4<132, 68>(sfA, sWa, 64, et, jt, acc);          // k 0..63 (h)
    __syncthreads();
    for (int idx = tid; idx < 64 * 64; idx += 256) {        // restage W1 rows 64..127
        int k = idx >> 6, j = idx & 63;
        sWa[j * 68 + k] = uW1[(64 + k) * 64 + j];
    }
    __syncthreads();
    gemm_acc4<132, 68>(sfA + 64, sWa, 64, et, jt, acc);     // k 64..127 (agg)
    #pragma unroll
    for (int e = 0; e < 4; ++e) {
        F4U o;
        #pragma unroll
        for (int j = 0; j < 4; ++j)
            o.f[j] = silu_f(lane_sum(acc[e][j]) + sb1[jt * 4 + j]);
        *(float4*)(sfB + (et + 16 * e) * 68 + jt * 4) = o.v;
    }
    __syncthreads();
    {   // v = silu(u @ uW2 + b2) -> sfA cols 0..63 (pitch 132)
        ull a2[4][4] = {};
        gemm_acc4<68, 68>(sfB, sW2t, 64, et, jt, a2);
        #pragma unroll
        for (int e = 0; e < 4; ++e) {
            F4U o;
            #pragma unroll
            for (int j = 0; j < 4; ++j)
                o.f[j] = silu_f(lane_sum(a2[e][j]) + sb2[jt * 4 + j]);
            *(float4*)(sfA + (et + 16 * e) * 132 + jt * 4) = o.v;
        }
    }
    __syncthreads();
    {   // h += v @ uW3 + b3
        ull a3[4][4] = {};
        gemm_acc4<132, 68>(sfA, sW3t, 64, et, jt, a3);
        #pragma unroll
        for (int e = 0; e < 4; ++e) {
            int n = base + et + 16 * e;
            if (n < NN) {
                F4U h; h.v = *(const float4*)(d_h + n * 64 + jt * 4);
                F4U o;
                #pragma unroll
                for (int j = 0; j < 4; ++j)
                    o.f[j] = h.f[j] + lane_sum(a3[e][j]) + sb3[jt * 4 + j];
                *(float4*)(d_h + n * 64 + jt * 4) = o.v;
            }
        }
    }
}

// ---------------- energy MLP (unchanged, 128 rows) ----------------
#define EN_SMEM ((128*68*2 + 64*68*2 + 64 + 64 + 64 + 4) * (int)sizeof(float))
__global__ void energy_kernel(const float* __restrict__ W1, const float* __restrict__ b1,
                              const float* __restrict__ W2, const float* __restrict__ b2,
                              const float* __restrict__ W3, const float* __restrict__ b3,
                              float* __restrict__ out) {
    extern __shared__ float sm[];
    float* sfA  = sm;
    float* sfB  = sfA + 128 * 68;
    float* sW1t = sfB + 128 * 68;
    float* sW2t = sW1t + 64 * 68;
    float* sW3  = sW2t + 64 * 68;
    float* sb1  = sW3 + 64;
    float* sb2  = sb1 + 64;
    float* sb3  = sb2 + 64;
    int tid = threadIdx.x;
    int base = blockIdx.x * 128;
    for (int idx = tid; idx < 64 * 64; idx += 256) {
        int k = idx >> 6, j = idx & 63;
        sW1t[j * 68 + k] = W1[idx];
        sW2t[j * 68 + k] = W2[idx];
    }
    if (tid < 64) { sW3[tid] = W3[tid]; sb1[tid] = b1[tid]; sb2[tid] = b2[tid]; }
    if (tid == 0) sb3[0] = b3[0];
    for (int idx = tid; idx < 128 * 16; idx += 256) {
        int e = idx >> 4, q = idx & 15;
        int n = base + e;
        float4 v = (n < NN) ? *(const float4*)(d_h + n * 64 + q * 4)
                            : make_float4(0.f, 0.f, 0.f, 0.f);
        *(float4*)(sfA + e * 68 + q * 4) = v;
    }
    __syncthreads();
    int et = tid & 15, jt = tid >> 4;
    {
        ull acc[8][4] = {};
        gemm_acc<68, 68>(sfA, sW1t, 64, et, jt, acc);
        #pragma unroll
        for (int e = 0; e < 8; ++e) {
            F4U o;
            #pragma unroll
            for (int j = 0; j < 4; ++j)
                o.f[j] = silu_f(lane_sum(acc[e][j]) + sb1[jt * 4 + j]);
            *(float4*)(sfB + (et + 16 * e) * 68 + jt * 4) = o.v;
        }
    }
    __syncthreads();
    {
        ull acc[8][4] = {};
        gemm_acc<68, 68>(sfB, sW2t, 64, et, jt, acc);
        #pragma unroll
        for (int e = 0; e < 8; ++e) {
            F4U o;
            #pragma unroll
            for (int j = 0; j < 4; ++j)
                o.f[j] = silu_f(lane_sum(acc[e][j]) + sb2[jt * 4 + j]);
            *(float4*)(sfA + (et + 16 * e) * 68 + jt * 4) = o.v;
        }
    }
    __syncthreads();
    if (tid < 128) {
        int n = base + tid;
        if (n < NN) {
            float s = sb3[0];
            #pragma unroll
            for (int q = 0; q < 16; ++q) {
                F4U t; t.v = *(const float4*)(sfA + tid * 68 + q * 4);
                #pragma unroll
                for (int c = 0; c < 4; ++c) s += t.f[c] * sW3[q * 4 + c];
            }
            out[n] = s;
        }
    }
}

// ---------------- launch ----------------
extern "C" void kernel_launch(void* const* d_in, const int* in_sizes, int n_in,
                              void* d_out, int out_size) {
    const float* h_in   = (const float*)d_in[0];
    const float* pos    = (const float*)d_in[1];
    const float* cell   = (const float*)d_in[2];
    const int*   esrc   = (const int*)d_in[3];
    const int*   edst   = (const int*)d_in[4];
    const float* emb_W1 = (const float*)d_in[5];
    const float* emb_b1 = (const float*)d_in[6];
    const float* emb_W2 = (const float*)d_in[7];
    const float* emb_b2 = (const float*)d_in[8];
    const float* msg_W1 = (const float*)d_in[9];
    const float* msg_b1 = (const float*)d_in[10];
    const float* bn_g   = (const float*)d_in[11];
    const float* bn_b   = (const float*)d_in[12];
    const float* msg_W2 = (const float*)d_in[13];
    const float* msg_b2 = (const float*)d_in[14];
    const float* upd_W1 = (const float*)d_in[15];
    const float* upd_b1 = (const float*)d_in[16];
    const float* upd_W2 = (const float*)d_in[17];
    const float* upd_b2 = (const float*)d_in[18];
    const float* upd_W3 = (const float*)d_in[19];
    const float* upd_b3 = (const float*)d_in[20];
    const float* pos_W1 = (const float*)d_in[21];
    const float* pos_b1 = (const float*)d_in[22];
    const float* pos_W2 = (const float*)d_in[23];
    const float* pos_b2 = (const float*)d_in[24];
    const float* en_W1  = (const float*)d_in[25];
    const float* en_b1  = (const float*)d_in[26];
    const float* en_W2  = (const float*)d_in[27];
    const float* en_b2  = (const float*)d_in[28];
    const float* en_W3  = (const float*)d_in[29];
    const float* en_b3  = (const float*)d_in[30];
    float* out = (float*)d_out;

    static int attr_done = 0;
    if (!attr_done) {
        cudaFuncSetAttribute(embed_kernel,  cudaFuncAttributeMaxDynamicSharedMemorySize, EM_SMEM);
        cudaFuncSetAttribute(pass1_kernel,  cudaFuncAttributeMaxDynamicSharedMemorySize, P1_SMEM);
        cudaFuncSetAttribute(pass2_kernel,  cudaFuncAttributeMaxDynamicSharedMemorySize, P2_SMEM);
        cudaFuncSetAttribute(node_kernel,   cudaFuncAttributeMaxDynamicSharedMemorySize, ND_SMEM);
        cudaFuncSetAttribute(energy_kernel, cudaFuncAttributeMaxDynamicSharedMemorySize, EN_SMEM);
        attr_done = 1;
    }

    init_kernel<<<(NN * F + 255) / 256, 256>>>(pos);
    count_kernel<<<(EE + 255) / 256, 256>>>(edst);
    inv_kernel<<<(NN + 255) / 256, 256>>>();
    embed_kernel<<<157, 256, EM_SMEM>>>(h_in, emb_W1, emb_b1, emb_W2, emb_b2);

    for (int l = 0; l < NL; ++l) {
        pass1_kernel<<<2500, 256, P1_SMEM>>>(esrc, edst, cell,
                                             msg_W1 + l * (2 * F + 1) * F, msg_b1 + l * F, l);
        pass2_kernel<<<2500, 256, P2_SMEM>>>(edst,
                                             msg_W2 + l * F * F, msg_b2 + l * F,
                                             bn_g + l * F, bn_b + l * F,
                                             pos_W1 + l * F * F, pos_b1 + l * F,
                                             pos_W2 + l * F * DIM, pos_b2 + l * DIM, l);
        node_kernel<<<313, 256, ND_SMEM>>>(upd_W1 + l * 2 * F * F, upd_b1 + l * F,
                                           upd_W2 + l * F * F, upd_b2 + l * F,
                                           upd_W3 + l * F * F, upd_b3 + l * F);
    }
    energy_kernel<<<157, 256, EN_SMEM>>>(en_W1, en_b1, en_W2, en_b2, en_W3, en_b3, out);
}

// round 6
// speedup vs baseline: 2.9730x; 1.0599x over previous
#include <cuda_runtime.h>
#include <cuda_bf16.h>

#define NN 20000
#define EE 160000
#define FIN 9
#define F 64
#define NL 7
#define DIM 3
#define BN_EPS 1e-5f

typedef unsigned long long ull;
union F4U { float4 v; ull u[2]; float f[4]; };

// ---------------- device scratch ----------------
__device__ float d_h[NN * F];
__device__ float d_pos[NN * DIM];
__device__ float d_m1[EE * F];
__device__ float d_dvec[EE * DIM];
__device__ float d_summ1[NN * F];     // scatter-sum of m1 per dst node
__device__ float d_aggpm[NN * DIM];
__device__ int   d_counts[NN];
__device__ float d_invc[NN];
__device__ float d_bnsum[NL * F];
__device__ float d_bnsumsq[NL * F];
__device__ float d_bnA[F];
__device__ float d_bnB[F];
__device__ float d_Wc[F * F];         // diag(A) * W2 @ pW1
__device__ float d_bc[F];

__device__ __forceinline__ float silu_f(float x) { return x / (1.0f + expf(-x)); }

__device__ __forceinline__ ull ffma2(ull a, ull b, ull c) {
    ull d;
    asm("fma.rn.f32x2 %0, %1, %2, %3;" : "=l"(d) : "l"(a), "l"(b), "l"(c));
    return d;
}
__device__ __forceinline__ float lane_sum(ull a) {
    float lo = __uint_as_float((unsigned)(a & 0xffffffffull));
    float hi = __uint_as_float((unsigned)(a >> 32));
    return lo + hi;
}
__device__ __forceinline__ void red_add_v4(float* p, float a, float b, float c, float d) {
    asm volatile("red.global.add.v4.f32 [%0], {%1,%2,%3,%4};"
                 :: "l"(p), "f"(a), "f"(b), "f"(c), "f"(d) : "memory");
}

// 64 rows x 64 cols per 256-thread block; thread (et=tid&15, jt=tid>>4)
// owns rows {et+16*e : e<4}, cols jt*4..+3. sWt transposed [64][PW].
template<int PF, int PW>
__device__ __forceinline__ void gemm_acc4(const float* __restrict__ sf,
                                          const float* __restrict__ sWt,
                                          int kmax, int et, int jt, ull acc[4][4]) {
    const float* fb = sf + et * PF;
    const float* wb = sWt + (jt * 4) * PW;
    #pragma unroll 2
    for (int k0 = 0; k0 < kmax; k0 += 4) {
        ull w[4][2];
        #pragma unroll
        for (int j = 0; j < 4; ++j) {
            F4U t; t.v = *(const float4*)(wb + j * PW + k0);
            w[j][0] = t.u[0]; w[j][1] = t.u[1];
        }
        #pragma unroll
        for (int e = 0; e < 4; ++e) {
            F4U t; t.v = *(const float4*)(fb + e * 16 * PF + k0);
            #pragma unroll
            for (int j = 0; j < 4; ++j) {
                acc[e][j] = ffma2(t.u[0], w[j][0], acc[e][j]);
                acc[e][j] = ffma2(t.u[1], w[j][1], acc[e][j]);
            }
        }
    }
}

// ---------------- init ----------------
__global__ void init_kernel(const float* __restrict__ pos_in) {
    int i = blockIdx.x * blockDim.x + threadIdx.x;
    if (i < NN * F) d_summ1[i] = 0.0f;
    if (i < NN * DIM) { d_aggpm[i] = 0.0f; d_pos[i] = pos_in[i]; }
    if (i < NN) d_counts[i] = 0;
    if (i < NL * F) { d_bnsum[i] = 0.0f; d_bnsumsq[i] = 0.0f; }
}
__global__ void count_kernel(const int* __restrict__ edge_dst) {
    int i = blockIdx.x * blockDim.x + threadIdx.x;
    if (i < EE) atomicAdd(&d_counts[edge_dst[i]], 1);
}
__global__ void inv_kernel() {
    int i = blockIdx.x * blockDim.x + threadIdx.x;
    if (i < NN) d_invc[i] = 1.0f / fmaxf((float)d_counts[i], 1.0f);
}

// ---------------- embedding: 64 nodes/block ----------------
#define EM_SMEM ((64*12 + 64*12 + 64*68 + 64*68 + 128) * (int)sizeof(float))
__global__ void embed_kernel(const float* __restrict__ h_in,
                             const float* __restrict__ W1, const float* __restrict__ b1,
                             const float* __restrict__ W2, const float* __restrict__ b2) {
    extern __shared__ float sm[];
    float* sf   = sm;                  // 64*12
    float* sW1t = sf + 64 * 12;        // 64*12
    float* sfB  = sW1t + 64 * 12;      // 64*68
    float* sW2t = sfB + 64 * 68;       // 64*68
    float* sb1  = sW2t + 64 * 68;
    float* sb2  = sb1 + 64;
    int tid = threadIdx.x;
    int base = blockIdx.x * 64;
    for (int idx = tid; idx < 64 * 12; idx += 256) {
        int j = idx / 12, k = idx - j * 12;
        sW1t[idx] = (k < FIN) ? W1[k * 64 + j] : 0.0f;
    }
    for (int idx = tid; idx < 64 * 64; idx += 256) {
        int k = idx >> 6, j = idx & 63;
        sW2t[j * 68 + k] = W2[idx];
    }
    if (tid < 64) { sb1[tid] = b1[tid]; sb2[tid] = b2[tid]; }
    for (int idx = tid; idx < 64 * 12; idx += 256) {
        int e = idx / 12, k = idx - e * 12;
        int n = base + e;
        sf[idx] = (k < FIN && n < NN) ? h_in[n * FIN + k] : 0.0f;
    }
    __syncthreads();
    int et = tid & 15, jt = tid >> 4;
    {
        ull acc[4][4] = {};
        gemm_acc4<12, 12>(sf, sW1t, 12, et, jt, acc);
        #pragma unroll
        for (int e = 0; e < 4; ++e) {
            F4U o;
            #pragma unroll
            for (int j = 0; j < 4; ++j)
                o.f[j] = silu_f(lane_sum(acc[e][j]) + sb1[jt * 4 + j]);
            *(float4*)(sfB + (et + 16 * e) * 68 + jt * 4) = o.v;
        }
    }
    __syncthreads();
    {
        ull acc[4][4] = {};
        gemm_acc4<68, 68>(sfB, sW2t, 64, et, jt, acc);
        #pragma unroll
        for (int e = 0; e < 4; ++e) {
            int n = base + et + 16 * e;
            if (n < NN) {
                F4U o;
                #pragma unroll
                for (int j = 0; j < 4; ++j)
                    o.f[j] = lane_sum(acc[e][j]) + sb2[jt * 4 + j];
                *(float4*)(d_h + n * 64 + jt * 4) = o.v;
            }
        }
    }
}

// ---------------- pass1: GEMM(129x64)+silu -> m1 store + v4-red scatter + BN stats ----------------
#define P1_SMEM ((64*132 + 64*132 + 64 + 128) * (int)sizeof(float))
__global__ void __launch_bounds__(256, 3)
pass1_kernel(const int* __restrict__ esrc, const int* __restrict__ edst,
             const float* __restrict__ cell,
             const float* __restrict__ W1, const float* __restrict__ b1, int l) {
    extern __shared__ float sm[];
    float* sWt  = sm;                    // 64*132
    float* sf   = sWt + 64 * 132;        // 64*132
    float* sb1  = sf + 64 * 132;         // 64
    int*   sidx = (int*)(sb1 + 64);      // 128
    int tid = threadIdx.x;
    int base = blockIdx.x * 64;
    for (int idx = tid; idx < 129 * 64; idx += 256) {
        int k = idx >> 6, j = idx & 63;
        sWt[j * 132 + k] = W1[idx];
    }
    if (tid < 64) { sb1[tid] = b1[tid]; sidx[tid] = edst[base + tid]; sidx[64 + tid] = esrc[base + tid]; }
    __syncthreads();
    for (int idx = tid; idx < 64 * 32; idx += 256) {
        int e = idx >> 5, q = idx & 31;
        int n = (q < 16) ? sidx[e] : sidx[64 + e];
        int qq = q & 15;
        *(float4*)(sf + e * 132 + q * 4) = *(const float4*)(d_h + n * 64 + qq * 4);
    }
    if (tid < 64) {
        int d = sidx[tid], s = sidx[64 + tid];
        int ge = base + tid;
        float dv0 = d_pos[d * 3 + 0] - d_pos[s * 3 + 0] + cell[ge * 3 + 0];
        float dv1 = d_pos[d * 3 + 1] - d_pos[s * 3 + 1] + cell[ge * 3 + 1];
        float dv2 = d_pos[d * 3 + 2] - d_pos[s * 3 + 2] + cell[ge * 3 + 2];
        d_dvec[ge * 3 + 0] = dv0; d_dvec[ge * 3 + 1] = dv1; d_dvec[ge * 3 + 2] = dv2;
        sf[tid * 132 + 128] = dv0 + dv1 + dv2;
    }
    __syncthreads();
    int et = tid & 15, jt = tid >> 4;
    ull acc[4][4] = {};
    gemm_acc4<132, 132>(sf, sWt, 128, et, jt, acc);
    float lsum[4] = {0, 0, 0, 0}, lsq[4] = {0, 0, 0, 0};
    #pragma unroll
    for (int e = 0; e < 4; ++e) {
        int er = et + 16 * e;
        float fk = sf[er * 132 + 128];
        int dn = sidx[er];
        F4U o;
        #pragma unroll
        for (int j = 0; j < 4; ++j) {
            float v = lane_sum(acc[e][j]) + fk * sWt[(jt * 4 + j) * 132 + 128] + sb1[jt * 4 + j];
            v = silu_f(v);
            o.f[j] = v; lsum[j] += v; lsq[j] += v * v;
        }
        *(float4*)(d_m1 + (base + er) * 64 + jt * 4) = o.v;
        red_add_v4(d_summ1 + dn * 64 + jt * 4, o.f[0], o.f[1], o.f[2], o.f[3]);
    }
    #pragma unroll
    for (int j = 0; j < 4; ++j) {
        #pragma unroll
        for (int o = 1; o < 16; o <<= 1) {
            lsum[j] += __shfl_xor_sync(0xffffffffu, lsum[j], o);
            lsq[j]  += __shfl_xor_sync(0xffffffffu, lsq[j], o);
        }
    }
    if (et == 0) {
        #pragma unroll
        for (int j = 0; j < 4; ++j) {
            atomicAdd(&d_bnsum[l * 64 + jt * 4 + j], lsum[j]);
            atomicAdd(&d_bnsumsq[l * 64 + jt * 4 + j], lsq[j]);
        }
    }
}

// ---------------- prep: A,B, Wc = diag(A)*W2@pW1, bc = (B@W2+b2)@pW1+pb1 ----------------
__global__ void prep_kernel(const float* __restrict__ gamma, const float* __restrict__ beta,
                            const float* __restrict__ W2, const float* __restrict__ b2,
                            const float* __restrict__ pW1, const float* __restrict__ pb1, int l) {
    __shared__ float sW2[64 * 64], spW1[64 * 64];
    __shared__ float sA[64], sB[64], sv[64];
    int tid = threadIdx.x;
    for (int idx = tid; idx < 64 * 64; idx += 1024) {
        sW2[idx] = W2[idx];
        spW1[idx] = pW1[idx];
    }
    if (tid < 64) {
        float mu  = d_bnsum[l * 64 + tid]   * (1.0f / (float)EE);
        float var = d_bnsumsq[l * 64 + tid] * (1.0f / (float)EE) - mu * mu;
        float inv = rsqrtf(var + BN_EPS);
        float A = gamma[tid] * inv;
        float B = beta[tid] - mu * A;
        sA[tid] = A; sB[tid] = B;
        d_bnA[tid] = A; d_bnB[tid] = B;
    }
    __syncthreads();
    if (tid < 64) {   // v = B@W2 + b2
        float acc = b2[tid];
        #pragma unroll 8
        for (int k = 0; k < 64; ++k) acc += sB[k] * sW2[k * 64 + tid];
        sv[tid] = acc;
    }
    // Wc[k][j] = A[k] * sum_q W2[k][q] pW1[q][j]
    for (int idx = tid; idx < 64 * 64; idx += 1024) {
        int k = idx >> 6, j = idx & 63;
        float acc = 0.0f;
        #pragma unroll 8
        for (int q = 0; q < 64; ++q) acc += sW2[k * 64 + q] * spW1[q * 64 + j];
        d_Wc[idx] = sA[k] * acc;
    }
    __syncthreads();
    if (tid < 64) {   // bc = v@pW1 + pb1
        float acc = pb1[tid];
        #pragma unroll 8
        for (int q = 0; q < 64; ++q) acc += sv[q] * spW1[q * 64 + tid];
        d_bc[tid] = acc;
    }
}

// ---------------- pass2: t = silu(m1@Wc+bc); s=t@pW2+pb2; scatter pm ----------------
#define P2_SMEM ((64*68*3 + 192 + 192 + 64 + 4 + 64) * (int)sizeof(float))
__global__ void __launch_bounds__(256, 4)
pass2_kernel(const int* __restrict__ edst,
             const float* __restrict__ pW2, const float* __restrict__ pb2) {
    extern __shared__ float sm[];
    float* sfA  = sm;                    // 64*68  (m1)
    float* sfB  = sfA + 64 * 68;         // 64*68  (t)
    float* sWct = sfB + 64 * 68;         // 64*68
    float* spW2 = sWct + 64 * 68;        // 192
    float* sdv  = spW2 + 192;            // 192
    float* sbc  = sdv + 192;             // 64
    float* spb2 = sbc + 64;              // 4
    int*   sdst = (int*)(spb2 + 4);      // 64
    int tid = threadIdx.x;
    int base = blockIdx.x * 64;
    for (int idx = tid; idx < 64 * 64; idx += 256) {
        int k = idx >> 6, j = idx & 63;
        sWct[j * 68 + k] = d_Wc[idx];
    }
    if (tid < 64) { sbc[tid] = d_bc[tid]; sdst[tid] = edst[base + tid]; }
    if (tid < 3) spb2[tid] = pb2[tid];
    for (int idx = tid; idx < 192; idx += 256) {
        spW2[idx] = pW2[idx];
        sdv[idx] = d_dvec[base * 3 + idx];
    }
    for (int idx = tid; idx < 64 * 16; idx += 256) {
        int e = idx >> 4, q = idx & 15;
        *(float4*)(sfA + e * 68 + q * 4) = *(const float4*)(d_m1 + (base + e) * 64 + q * 4);
    }
    __syncthreads();
    int et = tid & 15, jt = tid >> 4;
    {
        ull acc[4][4] = {};
        gemm_acc4<68, 68>(sfA, sWct, 64, et, jt, acc);
        #pragma unroll
        for (int e = 0; e < 4; ++e) {
            F4U o;
            #pragma unroll
            for (int j = 0; j < 4; ++j)
                o.f[j] = silu_f(lane_sum(acc[e][j]) + sbc[jt * 4 + j]);
            *(float4*)(sfB + (et + 16 * e) * 68 + jt * 4) = o.v;
        }
    }
    __syncthreads();
    if (tid < 64) {
        float s0 = spb2[0], s1 = spb2[1], s2 = spb2[2];
        #pragma unroll
        for (int q = 0; q < 16; ++q) {
            F4U t; t.v = *(const float4*)(sfB + tid * 68 + q * 4);
            #pragma unroll
            for (int c = 0; c < 4; ++c) {
                int k = q * 4 + c;
                s0 += t.f[c] * spW2[k * 3 + 0];
                s1 += t.f[c] * spW2[k * 3 + 1];
                s2 += t.f[c] * spW2[k * 3 + 2];
            }
        }
        int dn = sdst[tid];
        atomicAdd(&d_aggpm[dn * 3 + 0], sdv[tid * 3 + 0] * s0);
        atomicAdd(&d_aggpm[dn * 3 + 1], sdv[tid * 3 + 1] * s1);
        atomicAdd(&d_aggpm[dn * 3 + 2], sdv[tid * 3 + 2] * s2);
    }
}

// ---------------- node: aggm GEMM + pos update + update MLP ----------------
// smem: sfA[64*132] sfB[64*68] sWa[64*68] sW2t[64*68] sW3t[64*68]
//       sb1,sb2,sb3[192] sAm,sBm,sb2m,sfnz[256]
#define ND_SMEM ((64*132 + 64*68*4 + 192 + 256) * (int)sizeof(float))
__global__ void __launch_bounds__(256, 2)
node_kernel(const float* __restrict__ mW2, const float* __restrict__ mb2,
            const float* __restrict__ uW1, const float* __restrict__ ub1,
            const float* __restrict__ uW2, const float* __restrict__ ub2,
            const float* __restrict__ uW3, const float* __restrict__ ub3) {
    extern __shared__ float sm[];
    float* sfA  = sm;                    // 64*132  ([mnormless h | agg])
    float* sfB  = sfA + 64 * 132;        // 64*68
    float* sWa  = sfB + 64 * 68;         // 64*68 (restaged 3x)
    float* sW2t = sWa + 64 * 68;         // 64*68
    float* sW3t = sW2t + 64 * 68;        // 64*68
    float* sb1  = sW3t + 64 * 68;        // 64
    float* sb2  = sb1 + 64;
    float* sb3  = sb2 + 64;
    float* sAm  = sb3 + 64;              // 64
    float* sBm  = sAm + 64;              // 64
    float* sb2m = sBm + 64;              // 64
    float* sfnz = sb2m + 64;             // 64
    int tid = threadIdx.x;
    int base = blockIdx.x * 64;
    for (int idx = tid; idx < 64 * 64; idx += 256) {
        int k = idx >> 6, j = idx & 63;
        sWa[j * 68 + k]  = mW2[idx];     // msg W2 first
        sW2t[j * 68 + k] = uW2[idx];
        sW3t[j * 68 + k] = uW3[idx];
    }
    if (tid < 64) {
        sb1[tid] = ub1[tid]; sb2[tid] = ub2[tid]; sb3[tid] = ub3[tid];
        sAm[tid] = d_bnA[tid]; sBm[tid] = d_bnB[tid]; sb2m[tid] = mb2[tid];
    }
    __syncthreads();
    // stage h into sfA[:,0:64]; mnorm into sfB; zero summ1
    for (int idx = tid; idx < 64 * 16; idx += 256) {
        int e = idx >> 4, q = idx & 15;
        int n = base + e;
        float4 hv = make_float4(0.f, 0.f, 0.f, 0.f);
        F4U t; t.v = make_float4(0.f, 0.f, 0.f, 0.f);
        if (n < NN) {
            hv = *(const float4*)(d_h + n * 64 + q * 4);
            t.v = *(const float4*)(d_summ1 + n * 64 + q * 4);
            *(float4*)(d_summ1 + n * 64 + q * 4) = make_float4(0.f, 0.f, 0.f, 0.f);
            float inv = d_invc[n];
            float f = (d_counts[n] > 0) ? 1.0f : 0.0f;
            #pragma unroll
            for (int c = 0; c < 4; ++c)
                t.f[c] = sAm[q * 4 + c] * (t.f[c] * inv) + f * sBm[q * 4 + c];
        }
        *(float4*)(sfA + e * 132 + q * 4) = hv;
        *(float4*)(sfB + e * 68 + q * 4) = t.v;
    }
    if (tid < 64) {
        int n = base + tid;
        float f = 0.0f;
        if (n < NN) {
            f = (d_counts[n] > 0) ? 1.0f : 0.0f;
            float inv = d_invc[n];
            #pragma unroll
            for (int c = 0; c < 3; ++c) {
                d_pos[n * 3 + c] += d_aggpm[n * 3 + c] * inv;
                d_aggpm[n * 3 + c] = 0.0f;
            }
        }
        sfnz[tid] = f;
    }
    __syncthreads();
    int et = tid & 15, jt = tid >> 4;
    {   // agg = mnorm @ mW2 + f*mb2 -> sfA[:,64:128]
        ull a0[4][4] = {};
        gemm_acc4<68, 68>(sfB, sWa, 64, et, jt, a0);
        #pragma unroll
        for (int e = 0; e < 4; ++e) {
            int er = et + 16 * e;
            float f = sfnz[er];
            F4U o;
            #pragma unroll
            for (int j = 0; j < 4; ++j)
                o.f[j] = lane_sum(a0[e][j]) + f * sb2m[jt * 4 + j];
            *(float4*)(sfA + er * 132 + 64 + jt * 4) = o.v;
        }
    }
    __syncthreads();
    for (int idx = tid; idx < 64 * 64; idx += 256) {   // stage uW1 rows 0..63
        int k = idx >> 6, j = idx & 63;
        sWa[j * 68 + k] = uW1[idx];
    }
    __syncthreads();
    ull a1[4][4] = {};
    gemm_acc4<132, 68>(sfA, sWa, 64, et, jt, a1);       // k 0..63 (h)
    __syncthreads();
    for (int idx = tid; idx < 64 * 64; idx += 256) {   // stage uW1 rows 64..127
        int k = idx >> 6, j = idx & 63;
        sWa[j * 68 + k] = uW1[(64 + k) * 64 + j];
    }
    __syncthreads();
    gemm_acc4<132, 68>(sfA + 64, sWa, 64, et, jt, a1);  // k 64..127 (agg)
    #pragma unroll
    for (int e = 0; e < 4; ++e) {
        F4U o;
        #pragma unroll
        for (int j = 0; j < 4; ++j)
            o.f[j] = silu_f(lane_sum(a1[e][j]) + sb1[jt * 4 + j]);
        *(float4*)(sfB + (et + 16 * e) * 68 + jt * 4) = o.v;
    }
    __syncthreads();
    {   // v = silu(u @ uW2 + b2) -> sfA[:,0:64]
        ull a2[4][4] = {};
        gemm_acc4<68, 68>(sfB, sW2t, 64, et, jt, a2);
        #pragma unroll
        for (int e = 0; e < 4; ++e) {
            F4U o;
            #pragma unroll
            for (int j = 0; j < 4; ++j)
                o.f[j] = silu_f(lane_sum(a2[e][j]) + sb2[jt * 4 + j]);
            *(float4*)(sfA + (et + 16 * e) * 132 + jt * 4) = o.v;
        }
    }
    __syncthreads();
    {   // h += v @ uW3 + b3
        ull a3[4][4] = {};
        gemm_acc4<132, 68>(sfA, sW3t, 64, et, jt, a3);
        #pragma unroll
        for (int e = 0; e < 4; ++e) {
            int n = base + et + 16 * e;
            if (n < NN) {
                F4U h; h.v = *(const float4*)(d_h + n * 64 + jt * 4);
                F4U o;
                #pragma unroll
                for (int j = 0; j < 4; ++j)
                    o.f[j] = h.f[j] + lane_sum(a3[e][j]) + sb3[jt * 4 + j];
                *(float4*)(d_h + n * 64 + jt * 4) = o.v;
            }
        }
    }
}

// ---------------- energy MLP: 64 nodes/block ----------------
#define EN_SMEM ((64*68*2 + 64*68*2 + 64 + 64 + 64 + 4) * (int)sizeof(float))
__global__ void energy_kernel(const float* __restrict__ W1, const float* __restrict__ b1,
                              const float* __restrict__ W2, const float* __restrict__ b2,
                              const float* __restrict__ W3, const float* __restrict__ b3,
                              float* __restrict__ out) {
    extern __shared__ float sm[];
    float* sfA  = sm;                   // 64*68
    float* sfB  = sfA + 64 * 68;        // 64*68
    float* sW1t = sfB + 64 * 68;        // 64*68
    float* sW2t = sW1t + 64 * 68;       // 64*68
    float* sW3  = sW2t + 64 * 68;       // 64
    float* sb1  = sW3 + 64;
    float* sb2  = sb1 + 64;
    float* sb3  = sb2 + 64;
    int tid = threadIdx.x;
    int base = blockIdx.x * 64;
    for (int idx = tid; idx < 64 * 64; idx += 256) {
        int k = idx >> 6, j = idx & 63;
        sW1t[j * 68 + k] = W1[idx];
        sW2t[j * 68 + k] = W2[idx];
    }
    if (tid < 64) { sW3[tid] = W3[tid]; sb1[tid] = b1[tid]; sb2[tid] = b2[tid]; }
    if (tid == 0) sb3[0] = b3[0];
    for (int idx = tid; idx < 64 * 16; idx += 256) {
        int e = idx >> 4, q = idx & 15;
        int n = base + e;
        float4 v = (n < NN) ? *(const float4*)(d_h + n * 64 + q * 4)
                            : make_float4(0.f, 0.f, 0.f, 0.f);
        *(float4*)(sfA + e * 68 + q * 4) = v;
    }
    __syncthreads();
    int et = tid & 15, jt = tid >> 4;
    {
        ull acc[4][4] = {};
        gemm_acc4<68, 68>(sfA, sW1t, 64, et, jt, acc);
        #pragma unroll
        for (int e = 0; e < 4; ++e) {
            F4U o;
            #pragma unroll
            for (int j = 0; j < 4; ++j)
                o.f[j] = silu_f(lane_sum(acc[e][j]) + sb1[jt * 4 + j]);
            *(float4*)(sfB + (et + 16 * e) * 68 + jt * 4) = o.v;
        }
    }
    __syncthreads();
    {
        ull acc[4][4] = {};
        gemm_acc4<68, 68>(sfB, sW2t, 64, et, jt, acc);
        #pragma unroll
        for (int e = 0; e < 4; ++e) {
            F4U o;
            #pragma unroll
            for (int j = 0; j < 4; ++j)
                o.f[j] = silu_f(lane_sum(acc[e][j]) + sb2[jt * 4 + j]);
            *(float4*)(sfA + (et + 16 * e) * 68 + jt * 4) = o.v;
        }
    }
    __syncthreads();
    if (tid < 64) {
        int n = base + tid;
        if (n < NN) {
            float s = sb3[0];
            #pragma unroll
            for (int q = 0; q < 16; ++q) {
                F4U t; t.v = *(const float4*)(sfA + tid * 68 + q * 4);
                #pragma unroll
                for (int c = 0; c < 4; ++c) s += t.f[c] * sW3[q * 4 + c];
            }
            out[n] = s;
        }
    }
}

// ---------------- launch ----------------
extern "C" void kernel_launch(void* const* d_in, const int* in_sizes, int n_in,
                              void* d_out, int out_size) {
    const float* h_in   = (const float*)d_in[0];
    const float* pos    = (const float*)d_in[1];
    const float* cell   = (const float*)d_in[2];
    const int*   esrc   = (const int*)d_in[3];
    const int*   edst   = (const int*)d_in[4];
    const float* emb_W1 = (const float*)d_in[5];
    const float* emb_b1 = (const float*)d_in[6];
    const float* emb_W2 = (const float*)d_in[7];
    const float* emb_b2 = (const float*)d_in[8];
    const float* msg_W1 = (const float*)d_in[9];
    const float* msg_b1 = (const float*)d_in[10];
    const float* bn_g   = (const float*)d_in[11];
    const float* bn_b   = (const float*)d_in[12];
    const float* msg_W2 = (const float*)d_in[13];
    const float* msg_b2 = (const float*)d_in[14];
    const float* upd_W1 = (const float*)d_in[15];
    const float* upd_b1 = (const float*)d_in[16];
    const float* upd_W2 = (const float*)d_in[17];
    const float* upd_b2 = (const float*)d_in[18];
    const float* upd_W3 = (const float*)d_in[19];
    const float* upd_b3 = (const float*)d_in[20];
    const float* pos_W1 = (const float*)d_in[21];
    const float* pos_b1 = (const float*)d_in[22];
    const float* pos_W2 = (const float*)d_in[23];
    const float* pos_b2 = (const float*)d_in[24];
    const float* en_W1  = (const float*)d_in[25];
    const float* en_b1  = (const float*)d_in[26];
    const float* en_W2  = (const float*)d_in[27];
    const float* en_b2  = (const float*)d_in[28];
    const float* en_W3  = (const float*)d_in[29];
    const float* en_b3  = (const float*)d_in[30];
    float* out = (float*)d_out;

    static int attr_done = 0;
    if (!attr_done) {
        cudaFuncSetAttribute(embed_kernel,  cudaFuncAttributeMaxDynamicSharedMemorySize, EM_SMEM);
        cudaFuncSetAttribute(pass1_kernel,  cudaFuncAttributeMaxDynamicSharedMemorySize, P1_SMEM);
        cudaFuncSetAttribute(pass2_kernel,  cudaFuncAttributeMaxDynamicSharedMemorySize, P2_SMEM);
        cudaFuncSetAttribute(node_kernel,   cudaFuncAttributeMaxDynamicSharedMemorySize, ND_SMEM);
        cudaFuncSetAttribute(energy_kernel, cudaFuncAttributeMaxDynamicSharedMemorySize, EN_SMEM);
        attr_done = 1;
    }

    init_kernel<<<(NN * F + 255) / 256, 256>>>(pos);
    count_kernel<<<(EE + 255) / 256, 256>>>(edst);
    inv_kernel<<<(NN + 255) / 256, 256>>>();
    embed_kernel<<<313, 256, EM_SMEM>>>(h_in, emb_W1, emb_b1, emb_W2, emb_b2);

    for (int l = 0; l < NL; ++l) {
        pass1_kernel<<<2500, 256, P1_SMEM>>>(esrc, edst, cell,
                                             msg_W1 + l * (2 * F + 1) * F, msg_b1 + l * F, l);
        prep_kernel<<<1, 1024>>>(bn_g + l * F, bn_b + l * F,
                                 msg_W2 + l * F * F, msg_b2 + l * F,
                                 pos_W1 + l * F * F, pos_b1 + l * F, l);
        pass2_kernel<<<2500, 256, P2_SMEM>>>(edst,
                                             pos_W2 + l * F * DIM, pos_b2 + l * DIM);
        node_kernel<<<313, 256, ND_SMEM>>>(msg_W2 + l * F * F, msg_b2 + l * F,
                                           upd_W1 + l * 2 * F * F, upd_b1 + l * F,
                                           upd_W2 + l * F * F, upd_b2 + l * F,
                                           upd_W3 + l * F * F, upd_b3 + l * F);
    }
    energy_kernel<<<313, 256, EN_SMEM>>>(en_W1, en_b1, en_W2, en_b2, en_W3, en_b3, out);
}

// round 7
// speedup vs baseline: 3.1653x; 1.0647x over previous
#include <cuda_runtime.h>
#include <cuda_bf16.h>

#define NN 20000
#define EE 160000
#define FIN 9
#define F 64
#define NL 7
#define DIM 3
#define BN_EPS 1e-5f
#define NT_EDGE 2500

typedef unsigned long long ull;
union F4U { float4 v; ull u[2]; float f[4]; };

// ---------------- device scratch ----------------
__device__ float d_h[NN * F];
__device__ float d_pos[NN * DIM];
__device__ float d_m1[EE * F];
__device__ float d_dvec[EE * DIM];
__device__ float d_summ1[NN * F];
__device__ float d_aggpm[NN * DIM];
__device__ int   d_counts[NN];
__device__ float d_invc[NN];
__device__ float d_bnsum[NL * F];
__device__ float d_bnsumsq[NL * F];
__device__ float d_bnA[F];
__device__ float d_bnB[F];
__device__ float d_Wc[F * F];
__device__ float d_bc[F];

__device__ __forceinline__ float silu_f(float x) { return x / (1.0f + expf(-x)); }

__device__ __forceinline__ ull ffma2(ull a, ull b, ull c) {
    ull d;
    asm("fma.rn.f32x2 %0, %1, %2, %3;" : "=l"(d) : "l"(a), "l"(b), "l"(c));
    return d;
}
__device__ __forceinline__ float lane_sum(ull a) {
    float lo = __uint_as_float((unsigned)(a & 0xffffffffull));
    float hi = __uint_as_float((unsigned)(a >> 32));
    return lo + hi;
}
__device__ __forceinline__ void red_add_v4(float* p, float a, float b, float c, float d) {
    asm volatile("red.global.add.v4.f32 [%0], {%1,%2,%3,%4};"
                 :: "l"(p), "f"(a), "f"(b), "f"(c), "f"(d) : "memory");
}

// 64 rows x 64 cols; thread (et=tid&15, jt=tid>>4) owns rows {et+16e}, cols jt*4..+3
template<int PF, int PW>
__device__ __forceinline__ void gemm_acc4(const float* __restrict__ sf,
                                          const float* __restrict__ sWt,
                                          int kmax, int et, int jt, ull acc[4][4]) {
    const float* fb = sf + et * PF;
    const float* wb = sWt + (jt * 4) * PW;
    #pragma unroll 2
    for (int k0 = 0; k0 < kmax; k0 += 4) {
        ull w[4][2];
        #pragma unroll
        for (int j = 0; j < 4; ++j) {
            F4U t; t.v = *(const float4*)(wb + j * PW + k0);
            w[j][0] = t.u[0]; w[j][1] = t.u[1];
        }
        #pragma unroll
        for (int e = 0; e < 4; ++e) {
            F4U t; t.v = *(const float4*)(fb + e * 16 * PF + k0);
            #pragma unroll
            for (int j = 0; j < 4; ++j) {
                acc[e][j] = ffma2(t.u[0], w[j][0], acc[e][j]);
                acc[e][j] = ffma2(t.u[1], w[j][1], acc[e][j]);
            }
        }
    }
}

// ---------------- init ----------------
__global__ void init_kernel(const float* __restrict__ pos_in) {
    int i = blockIdx.x * blockDim.x + threadIdx.x;
    if (i < NN * F) d_summ1[i] = 0.0f;
    if (i < NN * DIM) { d_aggpm[i] = 0.0f; d_pos[i] = pos_in[i]; }
    if (i < NN) d_counts[i] = 0;
    if (i < NL * F) { d_bnsum[i] = 0.0f; d_bnsumsq[i] = 0.0f; }
}
__global__ void count_kernel(const int* __restrict__ edge_dst) {
    int i = blockIdx.x * blockDim.x + threadIdx.x;
    if (i < EE) atomicAdd(&d_counts[edge_dst[i]], 1);
}
__global__ void inv_kernel() {
    int i = blockIdx.x * blockDim.x + threadIdx.x;
    if (i < NN) d_invc[i] = 1.0f / fmaxf((float)d_counts[i], 1.0f);
}

// ---------------- embedding: 64 nodes/block ----------------
#define EM_SMEM ((64*12 + 64*12 + 64*68 + 64*68 + 128) * (int)sizeof(float))
__global__ void embed_kernel(const float* __restrict__ h_in,
                             const float* __restrict__ W1, const float* __restrict__ b1,
                             const float* __restrict__ W2, const float* __restrict__ b2) {
    extern __shared__ float sm[];
    float* sf   = sm;
    float* sW1t = sf + 64 * 12;
    float* sfB  = sW1t + 64 * 12;
    float* sW2t = sfB + 64 * 68;
    float* sb1  = sW2t + 64 * 68;
    float* sb2  = sb1 + 64;
    int tid = threadIdx.x;
    int base = blockIdx.x * 64;
    for (int idx = tid; idx < 64 * 12; idx += 256) {
        int j = idx / 12, k = idx - j * 12;
        sW1t[idx] = (k < FIN) ? W1[k * 64 + j] : 0.0f;
    }
    for (int idx = tid; idx < 64 * 64; idx += 256) {
        int k = idx >> 6, j = idx & 63;
        sW2t[j * 68 + k] = W2[idx];
    }
    if (tid < 64) { sb1[tid] = b1[tid]; sb2[tid] = b2[tid]; }
    for (int idx = tid; idx < 64 * 12; idx += 256) {
        int e = idx / 12, k = idx - e * 12;
        int n = base + e;
        sf[idx] = (k < FIN && n < NN) ? h_in[n * FIN + k] : 0.0f;
    }
    __syncthreads();
    int et = tid & 15, jt = tid >> 4;
    {
        ull acc[4][4] = {};
        gemm_acc4<12, 12>(sf, sW1t, 12, et, jt, acc);
        #pragma unroll
        for (int e = 0; e < 4; ++e) {
            F4U o;
            #pragma unroll
            for (int j = 0; j < 4; ++j)
                o.f[j] = silu_f(lane_sum(acc[e][j]) + sb1[jt * 4 + j]);
            *(float4*)(sfB + (et + 16 * e) * 68 + jt * 4) = o.v;
        }
    }
    __syncthreads();
    {
        ull acc[4][4] = {};
        gemm_acc4<68, 68>(sfB, sW2t, 64, et, jt, acc);
        #pragma unroll
        for (int e = 0; e < 4; ++e) {
            int n = base + et + 16 * e;
            if (n < NN) {
                F4U o;
                #pragma unroll
                for (int j = 0; j < 4; ++j)
                    o.f[j] = lane_sum(acc[e][j]) + sb2[jt * 4 + j];
                *(float4*)(d_h + n * 64 + jt * 4) = o.v;
            }
        }
    }
}

// ---------------- pass1: persistent tiles; weights staged ONCE per block ----------------
#define P1_SMEM ((64*132 + 64*132 + 64 + 128) * (int)sizeof(float))
__global__ void __launch_bounds__(256, 3)
pass1_kernel(const int* __restrict__ esrc, const int* __restrict__ edst,
             const float* __restrict__ cell,
             const float* __restrict__ W1, const float* __restrict__ b1, int l) {
    extern __shared__ float sm[];
    float* sWt  = sm;                    // 64*132
    float* sf   = sWt + 64 * 132;        // 64*132
    float* sb1  = sf + 64 * 132;         // 64
    int*   sidx = (int*)(sb1 + 64);      // 128
    int tid = threadIdx.x;
    for (int idx = tid; idx < 129 * 64; idx += 256) {
        int k = idx >> 6, j = idx & 63;
        sWt[j * 132 + k] = W1[idx];
    }
    if (tid < 64) sb1[tid] = b1[tid];
    int et = tid & 15, jt = tid >> 4;
    float bnsum_loc[4] = {0, 0, 0, 0}, bnsq_loc[4] = {0, 0, 0, 0};

    for (int t = blockIdx.x; t < NT_EDGE; t += gridDim.x) {
        int base = t * 64;
        __syncthreads();   // prev tile's GEMM done before restaging
        if (tid < 64) { sidx[tid] = edst[base + tid]; sidx[64 + tid] = esrc[base + tid]; }
        __syncthreads();
        for (int idx = tid; idx < 64 * 32; idx += 256) {
            int e = idx >> 5, q = idx & 31;
            int n = (q < 16) ? sidx[e] : sidx[64 + e];
            int qq = q & 15;
            *(float4*)(sf + e * 132 + q * 4) = *(const float4*)(d_h + n * 64 + qq * 4);
        }
        if (tid < 64) {
            int d = sidx[tid], s = sidx[64 + tid];
            int ge = base + tid;
            float dv0 = d_pos[d * 3 + 0] - d_pos[s * 3 + 0] + cell[ge * 3 + 0];
            float dv1 = d_pos[d * 3 + 1] - d_pos[s * 3 + 1] + cell[ge * 3 + 1];
            float dv2 = d_pos[d * 3 + 2] - d_pos[s * 3 + 2] + cell[ge * 3 + 2];
            d_dvec[ge * 3 + 0] = dv0; d_dvec[ge * 3 + 1] = dv1; d_dvec[ge * 3 + 2] = dv2;
            sf[tid * 132 + 128] = dv0 + dv1 + dv2;
        }
        __syncthreads();
        ull acc[4][4] = {};
        gemm_acc4<132, 132>(sf, sWt, 128, et, jt, acc);
        #pragma unroll
        for (int e = 0; e < 4; ++e) {
            int er = et + 16 * e;
            float fk = sf[er * 132 + 128];
            int dn = sidx[er];
            F4U o;
            #pragma unroll
            for (int j = 0; j < 4; ++j) {
                float v = lane_sum(acc[e][j]) + fk * sWt[(jt * 4 + j) * 132 + 128] + sb1[jt * 4 + j];
                v = silu_f(v);
                o.f[j] = v; bnsum_loc[j] += v; bnsq_loc[j] += v * v;
            }
            *(float4*)(d_m1 + (base + er) * 64 + jt * 4) = o.v;
            red_add_v4(d_summ1 + dn * 64 + jt * 4, o.f[0], o.f[1], o.f[2], o.f[3]);
        }
    }
    // per-block BN reduction once at the end
    #pragma unroll
    for (int j = 0; j < 4; ++j) {
        #pragma unroll
        for (int o = 1; o < 16; o <<= 1) {
            bnsum_loc[j] += __shfl_xor_sync(0xffffffffu, bnsum_loc[j], o);
            bnsq_loc[j]  += __shfl_xor_sync(0xffffffffu, bnsq_loc[j], o);
        }
    }
    if (et == 0) {
        #pragma unroll
        for (int j = 0; j < 4; ++j) {
            atomicAdd(&d_bnsum[l * 64 + jt * 4 + j], bnsum_loc[j]);
            atomicAdd(&d_bnsumsq[l * 64 + jt * 4 + j], bnsq_loc[j]);
        }
    }
}

// ---------------- prep ----------------
__global__ void prep_kernel(const float* __restrict__ gamma, const float* __restrict__ beta,
                            const float* __restrict__ W2, const float* __restrict__ b2,
                            const float* __restrict__ pW1, const float* __restrict__ pb1, int l) {
    __shared__ float sW2[64 * 64], spW1[64 * 64];
    __shared__ float sA[64], sB[64], sv[64];
    int tid = threadIdx.x;
    for (int idx = tid; idx < 64 * 64; idx += 1024) {
        sW2[idx] = W2[idx];
        spW1[idx] = pW1[idx];
    }
    if (tid < 64) {
        float mu  = d_bnsum[l * 64 + tid]   * (1.0f / (float)EE);
        float var = d_bnsumsq[l * 64 + tid] * (1.0f / (float)EE) - mu * mu;
        float inv = rsqrtf(var + BN_EPS);
        float A = gamma[tid] * inv;
        float B = beta[tid] - mu * A;
        sA[tid] = A; sB[tid] = B;
        d_bnA[tid] = A; d_bnB[tid] = B;
    }
    __syncthreads();
    if (tid < 64) {
        float acc = b2[tid];
        #pragma unroll 8
        for (int k = 0; k < 64; ++k) acc += sB[k] * sW2[k * 64 + tid];
        sv[tid] = acc;
    }
    for (int idx = tid; idx < 64 * 64; idx += 1024) {
        int k = idx >> 6, j = idx & 63;
        float acc = 0.0f;
        #pragma unroll 8
        for (int q = 0; q < 64; ++q) acc += sW2[k * 64 + q] * spW1[q * 64 + j];
        d_Wc[idx] = sA[k] * acc;
    }
    __syncthreads();
    if (tid < 64) {
        float acc = pb1[tid];
        #pragma unroll 8
        for (int q = 0; q < 64; ++q) acc += sv[q] * spW1[q * 64 + tid];
        d_bc[tid] = acc;
    }
}

// ---------------- pass2: persistent tiles ----------------
#define P2_SMEM ((64*68*3 + 192 + 192 + 64 + 4 + 64) * (int)sizeof(float))
__global__ void __launch_bounds__(256, 4)
pass2_kernel(const int* __restrict__ edst,
             const float* __restrict__ pW2, const float* __restrict__ pb2) {
    extern __shared__ float sm[];
    float* sfA  = sm;                    // 64*68  (m1)
    float* sfB  = sfA + 64 * 68;         // 64*68  (t)
    float* sWct = sfB + 64 * 68;         // 64*68
    float* spW2 = sWct + 64 * 68;        // 192
    float* sdv  = spW2 + 192;            // 192
    float* sbc  = sdv + 192;             // 64
    float* spb2 = sbc + 64;              // 4
    int*   sdst = (int*)(spb2 + 4);      // 64
    int tid = threadIdx.x;
    for (int idx = tid; idx < 64 * 64; idx += 256) {
        int k = idx >> 6, j = idx & 63;
        sWct[j * 68 + k] = d_Wc[idx];
    }
    if (tid < 64) sbc[tid] = d_bc[tid];
    if (tid < 3) spb2[tid] = pb2[tid];
    for (int idx = tid; idx < 192; idx += 256) spW2[idx] = pW2[idx];
    int et = tid & 15, jt = tid >> 4;

    for (int t = blockIdx.x; t < NT_EDGE; t += gridDim.x) {
        int base = t * 64;
        __syncthreads();
        if (tid < 64) sdst[tid] = edst[base + tid];
        for (int idx = tid; idx < 192; idx += 256) sdv[idx] = d_dvec[base * 3 + idx];
        for (int idx = tid; idx < 64 * 16; idx += 256) {
            int e = idx >> 4, q = idx & 15;
            *(float4*)(sfA + e * 68 + q * 4) = *(const float4*)(d_m1 + (base + e) * 64 + q * 4);
        }
        __syncthreads();
        {
            ull acc[4][4] = {};
            gemm_acc4<68, 68>(sfA, sWct, 64, et, jt, acc);
            #pragma unroll
            for (int e = 0; e < 4; ++e) {
                F4U o;
                #pragma unroll
                for (int j = 0; j < 4; ++j)
                    o.f[j] = silu_f(lane_sum(acc[e][j]) + sbc[jt * 4 + j]);
                *(float4*)(sfB + (et + 16 * e) * 68 + jt * 4) = o.v;
            }
        }
        __syncthreads();
        if (tid < 64) {
            float s0 = spb2[0], s1 = spb2[1], s2 = spb2[2];
            #pragma unroll
            for (int q = 0; q < 16; ++q) {
                F4U tt; tt.v = *(const float4*)(sfB + tid * 68 + q * 4);
                #pragma unroll
                for (int c = 0; c < 4; ++c) {
                    int k = q * 4 + c;
                    s0 += tt.f[c] * spW2[k * 3 + 0];
                    s1 += tt.f[c] * spW2[k * 3 + 1];
                    s2 += tt.f[c] * spW2[k * 3 + 2];
                }
            }
            int dn = sdst[tid];
            atomicAdd(&d_aggpm[dn * 3 + 0], sdv[tid * 3 + 0] * s0);
            atomicAdd(&d_aggpm[dn * 3 + 1], sdv[tid * 3 + 1] * s1);
            atomicAdd(&d_aggpm[dn * 3 + 2], sdv[tid * 3 + 2] * s2);
        }
    }
}

// ---------------- node: persistent tiles (restaged uW1 halves per tile kept) ----------------
#define ND_SMEM ((64*132 + 64*68*5 + 192 + 256) * (int)sizeof(float))
__global__ void __launch_bounds__(256, 2)
node_kernel(const float* __restrict__ mW2, const float* __restrict__ mb2,
            const float* __restrict__ uW1, const float* __restrict__ ub1,
            const float* __restrict__ uW2, const float* __restrict__ ub2,
            const float* __restrict__ uW3, const float* __restrict__ ub3, int ntiles) {
    extern __shared__ float sm[];
    float* sfA  = sm;                    // 64*132
    float* sfB  = sfA + 64 * 132;        // 64*68
    float* sWm  = sfB + 64 * 68;         // 64*68 (mW2)
    float* sW1a = sWm + 64 * 68;         // 64*68 (uW1 rows 0..63)
    float* sW2t = sW1a + 64 * 68;        // 64*68
    float* sW3t = sW2t + 64 * 68;        // 64*68
    float* sb1  = sW3t + 64 * 68;        // 64
    float* sb2  = sb1 + 64;
    float* sb3  = sb2 + 64;
    float* sAm  = sb3 + 64;
    float* sBm  = sAm + 64;
    float* sb2m = sBm + 64;
    float* sfnz = sb2m + 64;
    int tid = threadIdx.x;
    for (int idx = tid; idx < 64 * 64; idx += 256) {
        int k = idx >> 6, j = idx & 63;
        sWm[j * 68 + k]  = mW2[idx];
        sW1a[j * 68 + k] = uW1[idx];
        sW2t[j * 68 + k] = uW2[idx];
        sW3t[j * 68 + k] = uW3[idx];
    }
    if (tid < 64) {
        sb1[tid] = ub1[tid]; sb2[tid] = ub2[tid]; sb3[tid] = ub3[tid];
        sAm[tid] = d_bnA[tid]; sBm[tid] = d_bnB[tid]; sb2m[tid] = mb2[tid];
    }
    int et = tid & 15, jt = tid >> 4;

    for (int t = blockIdx.x; t < ntiles; t += gridDim.x) {
        int base = t * 64;
        __syncthreads();
        for (int idx = tid; idx < 64 * 16; idx += 256) {
            int e = idx >> 4, q = idx & 15;
            int n = base + e;
            float4 hv = make_float4(0.f, 0.f, 0.f, 0.f);
            F4U tt; tt.v = make_float4(0.f, 0.f, 0.f, 0.f);
            if (n < NN) {
                hv = *(const float4*)(d_h + n * 64 + q * 4);
                tt.v = *(const float4*)(d_summ1 + n * 64 + q * 4);
                *(float4*)(d_summ1 + n * 64 + q * 4) = make_float4(0.f, 0.f, 0.f, 0.f);
                float inv = d_invc[n];
                float f = (d_counts[n] > 0) ? 1.0f : 0.0f;
                #pragma unroll
                for (int c = 0; c < 4; ++c)
                    tt.f[c] = sAm[q * 4 + c] * (tt.f[c] * inv) + f * sBm[q * 4 + c];
            }
            *(float4*)(sfA + e * 132 + q * 4) = hv;
            *(float4*)(sfB + e * 68 + q * 4) = tt.v;
        }
        if (tid < 64) {
            int n = base + tid;
            float f = 0.0f;
            if (n < NN) {
                f = (d_counts[n] > 0) ? 1.0f : 0.0f;
                float inv = d_invc[n];
                #pragma unroll
                for (int c = 0; c < 3; ++c) {
                    d_pos[n * 3 + c] += d_aggpm[n * 3 + c] * inv;
                    d_aggpm[n * 3 + c] = 0.0f;
                }
            }
            sfnz[tid] = f;
        }
        __syncthreads();
        {   // agg = mnorm @ mW2 + f*mb2 -> sfA[:,64:128]
            ull a0[4][4] = {};
            gemm_acc4<68, 68>(sfB, sWm, 64, et, jt, a0);
            #pragma unroll
            for (int e = 0; e < 4; ++e) {
                int er = et + 16 * e;
                float f = sfnz[er];
                F4U o;
                #pragma unroll
                for (int j = 0; j < 4; ++j)
                    o.f[j] = lane_sum(a0[e][j]) + f * sb2m[jt * 4 + j];
                *(float4*)(sfA + er * 132 + 64 + jt * 4) = o.v;
            }
        }
        __syncthreads();
        ull a1[4][4] = {};
        gemm_acc4<132, 68>(sfA, sW1a, 64, et, jt, a1);       // k 0..63 (h)
        // second half of uW1 read directly from gmem (L1/L2-hot, broadcast)
        {
            const float* fb = sfA + et * 132 + 64;
            #pragma unroll 2
            for (int k0 = 0; k0 < 64; k0 += 4) {
                ull w[4][2];
                #pragma unroll
                for (int j = 0; j < 4; ++j) {
                    F4U tw;
                    tw.f[0] = uW1[(64 + k0 + 0) * 64 + jt * 4 + j];
                    tw.f[1] = uW1[(64 + k0 + 1) * 64 + jt * 4 + j];
                    tw.f[2] = uW1[(64 + k0 + 2) * 64 + jt * 4 + j];
                    tw.f[3] = uW1[(64 + k0 + 3) * 64 + jt * 4 + j];
                    w[j][0] = tw.u[0]; w[j][1] = tw.u[1];
                }
                #pragma unroll
                for (int e = 0; e < 4; ++e) {
                    F4U tf; tf.v = *(const float4*)(fb + e * 16 * 132 + k0);
                    #pragma unroll
                    for (int j = 0; j < 4; ++j) {
                        a1[e][j] = ffma2(tf.u[0], w[j][0], a1[e][j]);
                        a1[e][j] = ffma2(tf.u[1], w[j][1], a1[e][j]);
                    }
                }
            }
        }
        __syncthreads();
        #pragma unroll
        for (int e = 0; e < 4; ++e) {
            F4U o;
            #pragma unroll
            for (int j = 0; j < 4; ++j)
                o.f[j] = silu_f(lane_sum(a1[e][j]) + sb1[jt * 4 + j]);
            *(float4*)(sfB + (et + 16 * e) * 68 + jt * 4) = o.v;
        }
        __syncthreads();
        {   // v = silu(u @ uW2 + b2) -> sfA[:,0:64]
            ull a2[4][4] = {};
            gemm_acc4<68, 68>(sfB, sW2t, 64, et, jt, a2);
            #pragma unroll
            for (int e = 0; e < 4; ++e) {
                F4U o;
                #pragma unroll
                for (int j = 0; j < 4; ++j)
                    o.f[j] = silu_f(lane_sum(a2[e][j]) + sb2[jt * 4 + j]);
                *(float4*)(sfA + (et + 16 * e) * 132 + jt * 4) = o.v;
            }
        }
        __syncthreads();
        {   // h += v @ uW3 + b3
            ull a3[4][4] = {};
            gemm_acc4<132, 68>(sfA, sW3t, 64, et, jt, a3);
            #pragma unroll
            for (int e = 0; e < 4; ++e) {
                int n = base + et + 16 * e;
                if (n < NN) {
                    F4U h; h.v = *(const float4*)(d_h + n * 64 + jt * 4);
                    F4U o;
                    #pragma unroll
                    for (int j = 0; j < 4; ++j)
                        o.f[j] = h.f[j] + lane_sum(a3[e][j]) + sb3[jt * 4 + j];
                    *(float4*)(d_h + n * 64 + jt * 4) = o.v;
                }
            }
        }
    }
}

// ---------------- energy MLP ----------------
#define EN_SMEM ((64*68*2 + 64*68*2 + 64 + 64 + 64 + 4) * (int)sizeof(float))
__global__ void energy_kernel(const float* __restrict__ W1, const float* __restrict__ b1,
                              const float* __restrict__ W2, const float* __restrict__ b2,
                              const float* __restrict__ W3, const float* __restrict__ b3,
                              float* __restrict__ out) {
    extern __shared__ float sm[];
    float* sfA  = sm;
    float* sfB  = sfA + 64 * 68;
    float* sW1t = sfB + 64 * 68;
    float* sW2t = sW1t + 64 * 68;
    float* sW3  = sW2t + 64 * 68;
    float* sb1  = sW3 + 64;
    float* sb2  = sb1 + 64;
    float* sb3  = sb2 + 64;
    int tid = threadIdx.x;
    int base = blockIdx.x * 64;
    for (int idx = tid; idx < 64 * 64; idx += 256) {
        int k = idx >> 6, j = idx & 63;
        sW1t[j * 68 + k] = W1[idx];
        sW2t[j * 68 + k] = W2[idx];
    }
    if (tid < 64) { sW3[tid] = W3[tid]; sb1[tid] = b1[tid]; sb2[tid] = b2[tid]; }
    if (tid == 0) sb3[0] = b3[0];
    for (int idx = tid; idx < 64 * 16; idx += 256) {
        int e = idx >> 4, q = idx & 15;
        int n = base + e;
        float4 v = (n < NN) ? *(const float4*)(d_h + n * 64 + q * 4)
                            : make_float4(0.f, 0.f, 0.f, 0.f);
        *(float4*)(sfA + e * 68 + q * 4) = v;
    }
    __syncthreads();
    int et = tid & 15, jt = tid >> 4;
    {
        ull acc[4][4] = {};
        gemm_acc4<68, 68>(sfA, sW1t, 64, et, jt, acc);
        #pragma unroll
        for (int e = 0; e < 4; ++e) {
            F4U o;
            #pragma unroll
            for (int j = 0; j < 4; ++j)
                o.f[j] = silu_f(lane_sum(acc[e][j]) + sb1[jt * 4 + j]);
            *(float4*)(sfB + (et + 16 * e) * 68 + jt * 4) = o.v;
        }
    }
    __syncthreads();
    {
        ull acc[4][4] = {};
        gemm_acc4<68, 68>(sfB, sW2t, 64, et, jt, acc);
        #pragma unroll
        for (int e = 0; e < 4; ++e) {
            F4U o;
            #pragma unroll
            for (int j = 0; j < 4; ++j)
                o.f[j] = silu_f(lane_sum(acc[e][j]) + sb2[jt * 4 + j]);
            *(float4*)(sfA + (et + 16 * e) * 68 + jt * 4) = o.v;
        }
    }
    __syncthreads();
    if (tid < 64) {
        int n = base + tid;
        if (n < NN) {
            float s = sb3[0];
            #pragma unroll
            for (int q = 0; q < 16; ++q) {
                F4U t; t.v = *(const float4*)(sfA + tid * 68 + q * 4);
                #pragma unroll
                for (int c = 0; c < 4; ++c) s += t.f[c] * sW3[q * 4 + c];
            }
            out[n] = s;
        }
    }
}

// ---------------- launch ----------------
extern "C" void kernel_launch(void* const* d_in, const int* in_sizes, int n_in,
                              void* d_out, int out_size) {
    const float* h_in   = (const float*)d_in[0];
    const float* pos    = (const float*)d_in[1];
    const float* cell   = (const float*)d_in[2];
    const int*   esrc   = (const int*)d_in[3];
    const int*   edst   = (const int*)d_in[4];
    const float* emb_W1 = (const float*)d_in[5];
    const float* emb_b1 = (const float*)d_in[6];
    const float* emb_W2 = (const float*)d_in[7];
    const float* emb_b2 = (const float*)d_in[8];
    const float* msg_W1 = (const float*)d_in[9];
    const float* msg_b1 = (const float*)d_in[10];
    const float* bn_g   = (const float*)d_in[11];
    const float* bn_b   = (const float*)d_in[12];
    const float* msg_W2 = (const float*)d_in[13];
    const float* msg_b2 = (const float*)d_in[14];
    const float* upd_W1 = (const float*)d_in[15];
    const float* upd_b1 = (const float*)d_in[16];
    const float* upd_W2 = (const float*)d_in[17];
    const float* upd_b2 = (const float*)d_in[18];
    const float* upd_W3 = (const float*)d_in[19];
    const float* upd_b3 = (const float*)d_in[20];
    const float* pos_W1 = (const float*)d_in[21];
    const float* pos_b1 = (const float*)d_in[22];
    const float* pos_W2 = (const float*)d_in[23];
    const float* pos_b2 = (const float*)d_in[24];
    const float* en_W1  = (const float*)d_in[25];
    const float* en_b1  = (const float*)d_in[26];
    const float* en_W2  = (const float*)d_in[27];
    const float* en_b2  = (const float*)d_in[28];
    const float* en_W3  = (const float*)d_in[29];
    const float* en_b3  = (const float*)d_in[30];
    float* out = (float*)d_out;

    static int attr_done = 0;
    if (!attr_done) {
        cudaFuncSetAttribute(embed_kernel,  cudaFuncAttributeMaxDynamicSharedMemorySize, EM_SMEM);
        cudaFuncSetAttribute(pass1_kernel,  cudaFuncAttributeMaxDynamicSharedMemorySize, P1_SMEM);
        cudaFuncSetAttribute(pass2_kernel,  cudaFuncAttributeMaxDynamicSharedMemorySize, P2_SMEM);
        cudaFuncSetAttribute(node_kernel,   cudaFuncAttributeMaxDynamicSharedMemorySize, ND_SMEM);
        cudaFuncSetAttribute(energy_kernel, cudaFuncAttributeMaxDynamicSharedMemorySize, EN_SMEM);
        attr_done = 1;
    }

    const int P1_GRID = 148 * 3;   // persistent, 3 CTAs/SM
    const int P2_GRID = 148 * 4;   // persistent, 4 CTAs/SM
    const int ND_TILES = (NN + 63) / 64;   // 313
    const int ND_GRID = 148 * 2;   // persistent, 2 CTAs/SM

    init_kernel<<<(NN * F + 255) / 256, 256>>>(pos);
    count_kernel<<<(EE + 255) / 256, 256>>>(edst);
    inv_kernel<<<(NN + 255) / 256, 256>>>();
    embed_kernel<<<313, 256, EM_SMEM>>>(h_in, emb_W1, emb_b1, emb_W2, emb_b2);

    for (int l = 0; l < NL; ++l) {
        pass1_kernel<<<P1_GRID, 256, P1_SMEM>>>(esrc, edst, cell,
                                                msg_W1 + l * (2 * F + 1) * F, msg_b1 + l * F, l);
        prep_kernel<<<1, 1024>>>(bn_g + l * F, bn_b + l * F,
                                 msg_W2 + l * F * F, msg_b2 + l * F,
                                 pos_W1 + l * F * F, pos_b1 + l * F, l);
        pass2_kernel<<<P2_GRID, 256, P2_SMEM>>>(edst,
                                                pos_W2 + l * F * DIM, pos_b2 + l * DIM);
        node_kernel<<<ND_GRID, 256, ND_SMEM>>>(msg_W2 + l * F * F, msg_b2 + l * F,
                                               upd_W1 + l * 2 * F * F, upd_b1 + l * F,
                                               upd_W2 + l * F * F, upd_b2 + l * F,
                                               upd_W3 + l * F * F, upd_b3 + l * F, ND_TILES);
    }
    energy_kernel<<<313, 256, EN_SMEM>>>(en_W1, en_b1, en_W2, en_b2, en_W3, en_b3, out);
}

// round 10
// speedup vs baseline: 3.3586x; 1.0611x over previous
#include <cuda_runtime.h>
#include <cuda_bf16.h>
#include <mma.h>
#include <cstdint>

namespace wm = nvcuda::wmma;

#define NN 20000
#define EE 160000
#define FIN 9
#define F 64
#define NL 7
#define DIM 3
#define BN_EPS 1e-5f
#define NT_EDGE 2500

typedef unsigned long long ull;
union F4U { float4 v; ull u[2]; float f[4]; };

// ---------------- device scratch ----------------
__device__ float d_h[NN * F];
__device__ __nv_bfloat16 d_hhi[NN * F];
__device__ __nv_bfloat16 d_hlo[NN * F];
__device__ float d_pos[NN * DIM];
__device__ __nv_bfloat16 d_m1hi[EE * F];
__device__ __nv_bfloat16 d_m1lo[EE * F];
__device__ float d_dvec[EE * DIM];
__device__ float d_summ1[NN * F];
__device__ float d_aggpm[NN * DIM];
__device__ int   d_counts[NN];
__device__ float d_invc[NN];
__device__ float d_bnsum[NL * F];
__device__ float d_bnsumsq[NL * F];
__device__ float d_bnA[F];
__device__ float d_bnB[F];
__device__ float d_bc[F];
__device__ __nv_bfloat16 d_w1hi[NL * F * 128];   // [l][j][k]  (col-major KxN for wmma B)
__device__ __nv_bfloat16 d_w1lo[NL * F * 128];
__device__ __nv_bfloat16 d_wchi[F * F];          // [j][k]
__device__ __nv_bfloat16 d_wclo[F * F];

__device__ __forceinline__ float silu_f(float x) { return x / (1.0f + expf(-x)); }

__device__ __forceinline__ ull ffma2(ull a, ull b, ull c) {
    ull d;
    asm("fma.rn.f32x2 %0, %1, %2, %3;" : "=l"(d) : "l"(a), "l"(b), "l"(c));
    return d;
}
__device__ __forceinline__ float lane_sum(ull a) {
    float lo = __uint_as_float((unsigned)(a & 0xffffffffull));
    float hi = __uint_as_float((unsigned)(a >> 32));
    return lo + hi;
}
__device__ __forceinline__ void red_add_v4(float* p, float a, float b, float c, float d) {
    asm volatile("red.global.add.v4.f32 [%0], {%1,%2,%3,%4};"
                 :: "l"(p), "f"(a), "f"(b), "f"(c), "f"(d) : "memory");
}
__device__ __forceinline__ unsigned pack_bf(__nv_bfloat16 a, __nv_bfloat16 b) {
    __nv_bfloat162 t(a, b); return *(unsigned*)&t;
}

// ---------------- FFMA2 GEMM core ----------------
template<int PF, int PW>
__device__ __forceinline__ void gemm_acc4(const float* __restrict__ sf,
                                          const float* __restrict__ sWt,
                                          int kmax, int et, int jt, ull acc[4][4]) {
    const float* fb = sf + et * PF;
    const float* wb = sWt + (jt * 4) * PW;
    #pragma unroll 2
    for (int k0 = 0; k0 < kmax; k0 += 4) {
        ull w[4][2];
        #pragma unroll
        for (int j = 0; j < 4; ++j) {
            F4U t; t.v = *(const float4*)(wb + j * PW + k0);
            w[j][0] = t.u[0]; w[j][1] = t.u[1];
        }
        #pragma unroll
        for (int e = 0; e < 4; ++e) {
            F4U t; t.v = *(const float4*)(fb + e * 16 * PF + k0);
            #pragma unroll
            for (int j = 0; j < 4; ++j) {
                acc[e][j] = ffma2(t.u[0], w[j][0], acc[e][j]);
                acc[e][j] = ffma2(t.u[1], w[j][1], acc[e][j]);
            }
        }
    }
}

// ---------------- init ----------------
__global__ void init_kernel(const float* __restrict__ pos_in) {
    int i = blockIdx.x * blockDim.x + threadIdx.x;
    if (i < NN * F) d_summ1[i] = 0.0f;
    if (i < NN * DIM) { d_aggpm[i] = 0.0f; d_pos[i] = pos_in[i]; }
    if (i < NN) d_counts[i] = 0;
    if (i < NL * F) { d_bnsum[i] = 0.0f; d_bnsumsq[i] = 0.0f; }
}
__global__ void count_kernel(const int* __restrict__ edge_dst) {
    int i = blockIdx.x * blockDim.x + threadIdx.x;
    if (i < EE) atomicAdd(&d_counts[edge_dst[i]], 1);
}
__global__ void inv_kernel() {
    int i = blockIdx.x * blockDim.x + threadIdx.x;
    if (i < NN) d_invc[i] = 1.0f / fmaxf((float)d_counts[i], 1.0f);
}
// all layers' msg_W1 -> bf16 hi/lo, [l][j][k] layout (rows 0..127 only)
__global__ void wconv_kernel(const float* __restrict__ msg_W1) {
    int idx = blockIdx.x * blockDim.x + threadIdx.x;
    if (idx >= NL * F * 128) return;
    int l = idx >> 13, r = idx & 8191;
    int j = r >> 7, k = r & 127;
    float v = msg_W1[l * 8256 + k * 64 + j];
    __nv_bfloat16 h = __float2bfloat16(v);
    d_w1hi[idx] = h;
    d_w1lo[idx] = __float2bfloat16(v - __bfloat162float(h));
}

// ---------------- embedding (FFMA2) + h hi/lo emission ----------------
#define EM_SMEM ((64*12 + 64*12 + 64*68 + 64*68 + 128) * (int)sizeof(float))
__global__ void embed_kernel(const float* __restrict__ h_in,
                             const float* __restrict__ W1, const float* __restrict__ b1,
                             const float* __restrict__ W2, const float* __restrict__ b2) {
    extern __shared__ float sm[];
    float* sf   = sm;
    float* sW1t = sf + 64 * 12;
    float* sfB  = sW1t + 64 * 12;
    float* sW2t = sfB + 64 * 68;
    float* sb1  = sW2t + 64 * 68;
    float* sb2  = sb1 + 64;
    int tid = threadIdx.x;
    int base = blockIdx.x * 64;
    for (int idx = tid; idx < 64 * 12; idx += 256) {
        int j = idx / 12, k = idx - j * 12;
        sW1t[idx] = (k < FIN) ? W1[k * 64 + j] : 0.0f;
    }
    for (int idx = tid; idx < 64 * 64; idx += 256) {
        int k = idx >> 6, j = idx & 63;
        sW2t[j * 68 + k] = W2[idx];
    }
    if (tid < 64) { sb1[tid] = b1[tid]; sb2[tid] = b2[tid]; }
    for (int idx = tid; idx < 64 * 12; idx += 256) {
        int e = idx / 12, k = idx - e * 12;
        int n = base + e;
        sf[idx] = (k < FIN && n < NN) ? h_in[n * FIN + k] : 0.0f;
    }
    __syncthreads();
    int et = tid & 15, jt = tid >> 4;
    {
        ull acc[4][4] = {};
        gemm_acc4<12, 12>(sf, sW1t, 12, et, jt, acc);
        #pragma unroll
        for (int e = 0; e < 4; ++e) {
            F4U o;
            #pragma unroll
            for (int j = 0; j < 4; ++j)
                o.f[j] = silu_f(lane_sum(acc[e][j]) + sb1[jt * 4 + j]);
            *(float4*)(sfB + (et + 16 * e) * 68 + jt * 4) = o.v;
        }
    }
    __syncthreads();
    {
        ull acc[4][4] = {};
        gemm_acc4<68, 68>(sfB, sW2t, 64, et, jt, acc);
        #pragma unroll
        for (int e = 0; e < 4; ++e) {
            int n = base + et + 16 * e;
            if (n < NN) {
                F4U o;
                #pragma unroll
                for (int j = 0; j < 4; ++j)
                    o.f[j] = lane_sum(acc[e][j]) + sb2[jt * 4 + j];
                *(float4*)(d_h + n * 64 + jt * 4) = o.v;
                __nv_bfloat16 hb[4]; float lo[4];
                #pragma unroll
                for (int j = 0; j < 4; ++j) {
                    hb[j] = __float2bfloat16(o.f[j]);
                    lo[j] = o.f[j] - __bfloat162float(hb[j]);
                }
                uint2 H, L;
                H.x = pack_bf(hb[0], hb[1]); H.y = pack_bf(hb[2], hb[3]);
                L.x = pack_bf(__float2bfloat16(lo[0]), __float2bfloat16(lo[1]));
                L.y = pack_bf(__float2bfloat16(lo[2]), __float2bfloat16(lo[3]));
                *(uint2*)(d_hhi + n * 64 + jt * 4) = H;
                *(uint2*)(d_hlo + n * 64 + jt * 4) = L;
            }
        }
    }
}

// ---------------- pass1: wmma bf16 hi/lo, 64 edges/tile, persistent ----------------
// byte offsets: Ahi 0 (17408) Alo 17408 Bhi 34816 Blo 52224 Acc 69632(f,17408)
//               w129 87040 sb1 87296 sdist 87552 sdst 87808 ssrc 88064
#define P1_SMEM 88320
__global__ void __launch_bounds__(256)
pass1_wmma(const int* __restrict__ esrc, const int* __restrict__ edst,
           const float* __restrict__ cell,
           const float* __restrict__ W1, const float* __restrict__ b1, int l) {
    extern __shared__ char smem[];
    __nv_bfloat16* sAhi = (__nv_bfloat16*)(smem);
    __nv_bfloat16* sAlo = (__nv_bfloat16*)(smem + 17408);
    __nv_bfloat16* sBhi = (__nv_bfloat16*)(smem + 34816);
    __nv_bfloat16* sBlo = (__nv_bfloat16*)(smem + 52224);
    float* sAcc  = (float*)(smem + 69632);
    float* w129  = (float*)(smem + 87040);
    float* sb1   = (float*)(smem + 87296);
    float* sdist = (float*)(smem + 87552);
    int*   sdst  = (int*)(smem + 87808);
    int*   ssrc  = (int*)(smem + 88064);
    int tid = threadIdx.x;
    // stage weights once per block
    for (int i = tid; i < 64 * 16; i += 256) {
        int j = i >> 4, c = i & 15;
        *(uint4*)(sBhi + j * 136 + c * 8) = ((const uint4*)(d_w1hi + l * 8192 + j * 128))[c];
        *(uint4*)(sBlo + j * 136 + c * 8) = ((const uint4*)(d_w1lo + l * 8192 + j * 128))[c];
    }
    if (tid < 64) { w129[tid] = W1[128 * 64 + tid]; sb1[tid] = b1[tid]; }
    int w = tid >> 5, rg = w >> 1, nh = w & 1;

    for (int t = blockIdx.x; t < NT_EDGE; t += gridDim.x) {
        int base = t * 64;
        __syncthreads();   // previous tile fully consumed
        if (tid < 64) {
            int ge = base + tid;
            int dn = edst[ge], sn = esrc[ge];
            sdst[tid] = dn; ssrc[tid] = sn;
            float dv0 = d_pos[dn * 3 + 0] - d_pos[sn * 3 + 0] + cell[ge * 3 + 0];
            float dv1 = d_pos[dn * 3 + 1] - d_pos[sn * 3 + 1] + cell[ge * 3 + 1];
            float dv2 = d_pos[dn * 3 + 2] - d_pos[sn * 3 + 2] + cell[ge * 3 + 2];
            d_dvec[ge * 3 + 0] = dv0; d_dvec[ge * 3 + 1] = dv1; d_dvec[ge * 3 + 2] = dv2;
            sdist[tid] = dv0 + dv1 + dv2;
        }
        __syncthreads();
        // gather A: row e = edge, k0..63 = h[dst], k64..127 = h[src]
        for (int idx = tid; idx < 64 * 32; idx += 256) {
            int e = idx >> 5, q = idx & 31, c = q & 7;
            int n = (q & 8) ? ssrc[e] : sdst[e];
            const uint4* src = (q & 16) ? (const uint4*)(d_hlo + n * 64)
                                        : (const uint4*)(d_hhi + n * 64);
            __nv_bfloat16* dp = ((q & 16) ? sAlo : sAhi) + e * 136 + ((q & 8) ? 64 : 0) + c * 8;
            *(uint4*)dp = src[c];
        }
        __syncthreads();
        // MMA: warp (rg, nh): rows 16rg..+15, cols 32nh..+31 (2 n-tiles)
        {
            wm::fragment<wm::accumulator, 16, 16, 16, float> c0, c1;
            wm::fill_fragment(c0, 0.0f);
            wm::fill_fragment(c1, 0.0f);
            const __nv_bfloat16* Ah = sAhi + rg * 16 * 136;
            const __nv_bfloat16* Al = sAlo + rg * 16 * 136;
            const __nv_bfloat16* B0h = sBhi + (nh * 32) * 136;
            const __nv_bfloat16* B1h = sBhi + (nh * 32 + 16) * 136;
            const __nv_bfloat16* B0l = sBlo + (nh * 32) * 136;
            const __nv_bfloat16* B1l = sBlo + (nh * 32 + 16) * 136;
            #pragma unroll
            for (int kt = 0; kt < 8; ++kt) {
                wm::fragment<wm::matrix_a, 16, 16, 16, __nv_bfloat16, wm::row_major> ah, al;
                wm::load_matrix_sync(ah, Ah + kt * 16, 136);
                wm::load_matrix_sync(al, Al + kt * 16, 136);
                wm::fragment<wm::matrix_b, 16, 16, 16, __nv_bfloat16, wm::col_major> b;
                wm::load_matrix_sync(b, B0h + kt * 16, 136);
                wm::mma_sync(c0, ah, b, c0);
                wm::mma_sync(c0, al, b, c0);
                wm::load_matrix_sync(b, B1h + kt * 16, 136);
                wm::mma_sync(c1, ah, b, c1);
                wm::mma_sync(c1, al, b, c1);
                wm::load_matrix_sync(b, B0l + kt * 16, 136);
                wm::mma_sync(c0, ah, b, c0);
                wm::load_matrix_sync(b, B1l + kt * 16, 136);
                wm::mma_sync(c1, ah, b, c1);
            }
            wm::store_matrix_sync(sAcc + rg * 16 * 68 + nh * 32, c0, 68, wm::mem_row_major);
            wm::store_matrix_sync(sAcc + rg * 16 * 68 + nh * 32 + 16, c1, 68, wm::mem_row_major);
        }
        __syncthreads();
        // epilogue: 4 threads/edge, thread p handles cols p*16..p*16+15
        {
            int e = tid & 63, p = tid >> 6;
            int ge = base + e;
            int dn = sdst[e];
            float dist = sdist[e];
            int j0 = p * 16;
            float mv[16];
            __nv_bfloat16 hb[16], lb[16];
            #pragma unroll
            for (int jj = 0; jj < 16; ++jj) {
                int j = j0 + jj;
                float v = sAcc[e * 68 + j] + dist * w129[j] + sb1[j];
                v = silu_f(v);
                mv[jj] = v;
                hb[jj] = __float2bfloat16(v);
                lb[jj] = __float2bfloat16(v - __bfloat162float(hb[jj]));
            }
            uint4 H0, H1, L0, L1;
            H0.x = pack_bf(hb[0], hb[1]);  H0.y = pack_bf(hb[2], hb[3]);
            H0.z = pack_bf(hb[4], hb[5]);  H0.w = pack_bf(hb[6], hb[7]);
            H1.x = pack_bf(hb[8], hb[9]);  H1.y = pack_bf(hb[10], hb[11]);
            H1.z = pack_bf(hb[12], hb[13]); H1.w = pack_bf(hb[14], hb[15]);
            L0.x = pack_bf(lb[0], lb[1]);  L0.y = pack_bf(lb[2], lb[3]);
            L0.z = pack_bf(lb[4], lb[5]);  L0.w = pack_bf(lb[6], lb[7]);
            L1.x = pack_bf(lb[8], lb[9]);  L1.y = pack_bf(lb[10], lb[11]);
            L1.z = pack_bf(lb[12], lb[13]); L1.w = pack_bf(lb[14], lb[15]);
            ((uint4*)(d_m1hi + (size_t)ge * 64))[p * 2]     = H0;
            ((uint4*)(d_m1hi + (size_t)ge * 64))[p * 2 + 1] = H1;
            ((uint4*)(d_m1lo + (size_t)ge * 64))[p * 2]     = L0;
            ((uint4*)(d_m1lo + (size_t)ge * 64))[p * 2 + 1] = L1;
            red_add_v4(d_summ1 + dn * 64 + j0,      mv[0],  mv[1],  mv[2],  mv[3]);
            red_add_v4(d_summ1 + dn * 64 + j0 + 4,  mv[4],  mv[5],  mv[6],  mv[7]);
            red_add_v4(d_summ1 + dn * 64 + j0 + 8,  mv[8],  mv[9],  mv[10], mv[11]);
            red_add_v4(d_summ1 + dn * 64 + j0 + 12, mv[12], mv[13], mv[14], mv[15]);
        }
    }
}

// ---------------- bnstats: bnsum from summ1, bnsumsq from m1 hi/lo ----------------
__global__ void bnstats_kernel(int l) {
    __shared__ float ssum[64], ssq[64];
    int tid = threadIdx.x;
    if (tid < 64) { ssum[tid] = 0.0f; ssq[tid] = 0.0f; }
    __syncthreads();
    int jp = tid & 31;
    int r0 = blockIdx.x * 8 + (tid >> 5);
    int rstep = gridDim.x * 8;
    float sq0 = 0, sq1 = 0;
    for (int row = r0; row < EE; row += rstep) {
        unsigned hw = ((const unsigned*)d_m1hi)[row * 32 + jp];
        unsigned lw = ((const unsigned*)d_m1lo)[row * 32 + jp];
        __nv_bfloat162 hb = *(__nv_bfloat162*)&hw, lb = *(__nv_bfloat162*)&lw;
        float v0 = __bfloat162float(hb.x) + __bfloat162float(lb.x);
        float v1 = __bfloat162float(hb.y) + __bfloat162float(lb.y);
        sq0 += v0 * v0; sq1 += v1 * v1;
    }
    float s0 = 0, s1 = 0;
    for (int row = r0; row < NN; row += rstep) {
        float2 v = ((const float2*)d_summ1)[row * 32 + jp];
        s0 += v.x; s1 += v.y;
    }
    atomicAdd(&ssq[jp * 2], sq0);  atomicAdd(&ssq[jp * 2 + 1], sq1);
    atomicAdd(&ssum[jp * 2], s0);  atomicAdd(&ssum[jp * 2 + 1], s1);
    __syncthreads();
    if (tid < 64) {
        atomicAdd(&d_bnsumsq[l * 64 + tid], ssq[tid]);
        atomicAdd(&d_bnsum[l * 64 + tid], ssum[tid]);
    }
}

// ---------------- prep: BN affine; Wc=diag(A)W2@pW1 (bf16 hi/lo); bc ----------------
__global__ void prep_kernel(const float* __restrict__ gamma, const float* __restrict__ beta,
                            const float* __restrict__ W2, const float* __restrict__ b2,
                            const float* __restrict__ pW1, const float* __restrict__ pb1, int l) {
    __shared__ float sW2[64 * 64], spW1[64 * 64];
    __shared__ float sA[64], sB[64], sv[64];
    int tid = threadIdx.x;
    for (int idx = tid; idx < 64 * 64; idx += 1024) {
        sW2[idx] = W2[idx];
        spW1[idx] = pW1[idx];
    }
    if (tid < 64) {
        float mu  = d_bnsum[l * 64 + tid]   * (1.0f / (float)EE);
        float var = d_bnsumsq[l * 64 + tid] * (1.0f / (float)EE) - mu * mu;
        float inv = rsqrtf(var + BN_EPS);
        float A = gamma[tid] * inv;
        float B = beta[tid] - mu * A;
        sA[tid] = A; sB[tid] = B;
        d_bnA[tid] = A; d_bnB[tid] = B;
    }
    __syncthreads();
    if (tid < 64) {
        float acc = b2[tid];
        #pragma unroll 8
        for (int k = 0; k < 64; ++k) acc += sB[k] * sW2[k * 64 + tid];
        sv[tid] = acc;
    }
    for (int idx = tid; idx < 64 * 64; idx += 1024) {
        int k = idx >> 6, j = idx & 63;
        float acc = 0.0f;
        #pragma unroll 8
        for (int q = 0; q < 64; ++q) acc += sW2[k * 64 + q] * spW1[q * 64 + j];
        float v = sA[k] * acc;
        __nv_bfloat16 h = __float2bfloat16(v);
        d_wchi[j * 64 + k] = h;
        d_wclo[j * 64 + k] = __float2bfloat16(v - __bfloat162float(h));
    }
    __syncthreads();
    if (tid < 64) {
        float acc = pb1[tid];
        #pragma unroll 8
        for (int q = 0; q < 64; ++q) acc += sv[q] * spW1[q * 64 + tid];
        d_bc[tid] = acc;
    }
}

// ---------------- pass2: wmma bf16 hi/lo, 64 edges/tile, persistent ----------------
// byte offsets: Ahi 0 (9216) Alo 9216 Bhi 18432 Blo 27648 Acc 36864(f,17408)
//               sbc 54272 spW2 54528 spb2 55296 sdv 55312 sdst 56080
#define P2_SMEM 56336
__global__ void __launch_bounds__(256)
pass2_wmma(const int* __restrict__ edst,
           const float* __restrict__ pW2, const float* __restrict__ pb2) {
    extern __shared__ char smem[];
    __nv_bfloat16* sAhi = (__nv_bfloat16*)(smem);
    __nv_bfloat16* sAlo = (__nv_bfloat16*)(smem + 9216);
    __nv_bfloat16* sBhi = (__nv_bfloat16*)(smem + 18432);
    __nv_bfloat16* sBlo = (__nv_bfloat16*)(smem + 27648);
    float* sAcc = (float*)(smem + 36864);
    float* sbc  = (float*)(smem + 54272);
    float* spW2 = (float*)(smem + 54528);
    float* spb2 = (float*)(smem + 55296);
    float* sdv  = (float*)(smem + 55312);
    int*   sdst = (int*)(smem + 56080);
    int tid = threadIdx.x;
    for (int i = tid; i < 64 * 8; i += 256) {
        int j = i >> 3, c = i & 7;
        *(uint4*)(sBhi + j * 72 + c * 8) = ((const uint4*)(d_wchi + j * 64))[c];
        *(uint4*)(sBlo + j * 72 + c * 8) = ((const uint4*)(d_wclo + j * 64))[c];
    }
    if (tid < 64) sbc[tid] = d_bc[tid];
    for (int i = tid; i < 192; i += 256) spW2[i] = pW2[i];
    if (tid < 3) spb2[tid] = pb2[tid];
    int w = tid >> 5, rg = w >> 1, nh = w & 1;

    for (int t = blockIdx.x; t < NT_EDGE; t += gridDim.x) {
        int base = t * 64;
        __syncthreads();
        if (tid < 64) sdst[tid] = edst[base + tid];
        for (int i = tid; i < 192; i += 256) sdv[i] = d_dvec[base * 3 + i];
        for (int idx = tid; idx < 64 * 16; idx += 256) {
            int e = idx >> 4, q = idx & 15, c = q & 7;
            const uint4* src = (q & 8) ? (const uint4*)(d_m1lo + (size_t)(base + e) * 64)
                                       : (const uint4*)(d_m1hi + (size_t)(base + e) * 64);
            __nv_bfloat16* dp = ((q & 8) ? sAlo : sAhi) + e * 72 + c * 8;
            *(uint4*)dp = src[c];
        }
        __syncthreads();
        {
            wm::fragment<wm::accumulator, 16, 16, 16, float> c0, c1;
            wm::fill_fragment(c0, 0.0f);
            wm::fill_fragment(c1, 0.0f);
            const __nv_bfloat16* Ah = sAhi + rg * 16 * 72;
            const __nv_bfloat16* Al = sAlo + rg * 16 * 72;
            const __nv_bfloat16* B0h = sBhi + (nh * 32) * 72;
            const __nv_bfloat16* B1h = sBhi + (nh * 32 + 16) * 72;
            const __nv_bfloat16* B0l = sBlo + (nh * 32) * 72;
            const __nv_bfloat16* B1l = sBlo + (nh * 32 + 16) * 72;
            #pragma unroll
            for (int kt = 0; kt < 4; ++kt) {
                wm::fragment<wm::matrix_a, 16, 16, 16, __nv_bfloat16, wm::row_major> ah, al;
                wm::load_matrix_sync(ah, Ah + kt * 16, 72);
                wm::load_matrix_sync(al, Al + kt * 16, 72);
                wm::fragment<wm::matrix_b, 16, 16, 16, __nv_bfloat16, wm::col_major> b;
                wm::load_matrix_sync(b, B0h + kt * 16, 72);
                wm::mma_sync(c0, ah, b, c0);
                wm::mma_sync(c0, al, b, c0);
                wm::load_matrix_sync(b, B1h + kt * 16, 72);
                wm::mma_sync(c1, ah, b, c1);
                wm::mma_sync(c1, al, b, c1);
                wm::load_matrix_sync(b, B0l + kt * 16, 72);
                wm::mma_sync(c0, ah, b, c0);
                wm::load_matrix_sync(b, B1l + kt * 16, 72);
                wm::mma_sync(c1, ah, b, c1);
            }
            wm::store_matrix_sync(sAcc + rg * 16 * 68 + nh * 32, c0, 68, wm::mem_row_major);
            wm::store_matrix_sync(sAcc + rg * 16 * 68 + nh * 32 + 16, c1, 68, wm::mem_row_major);
        }
        __syncthreads();
        if (tid < 64) {
            float s0 = spb2[0], s1 = spb2[1], s2 = spb2[2];
            #pragma unroll
            for (int q = 0; q < 16; ++q) {
                F4U tt; tt.v = *(const float4*)(sAcc + tid * 68 + q * 4);
                #pragma unroll
                for (int c = 0; c < 4; ++c) {
                    int j = q * 4 + c;
                    float v = silu_f(tt.f[c] + sbc[j]);
                    s0 += v * spW2[j * 3 + 0];
                    s1 += v * spW2[j * 3 + 1];
                    s2 += v * spW2[j * 3 + 2];
                }
            }
            int dn = sdst[tid];
            atomicAdd(&d_aggpm[dn * 3 + 0], sdv[tid * 3 + 0] * s0);
            atomicAdd(&d_aggpm[dn * 3 + 1], sdv[tid * 3 + 1] * s1);
            atomicAdd(&d_aggpm[dn * 3 + 2], sdv[tid * 3 + 2] * s2);
        }
    }
}

// ---------------- node (FFMA2, persistent) + h hi/lo emission ----------------
#define ND_SMEM ((64*132 + 64*68*5 + 192 + 256) * (int)sizeof(float))
__global__ void __launch_bounds__(256, 2)
node_kernel(const float* __restrict__ mW2, const float* __restrict__ mb2,
            const float* __restrict__ uW1, const float* __restrict__ ub1,
            const float* __restrict__ uW2, const float* __restrict__ ub2,
            const float* __restrict__ uW3, const float* __restrict__ ub3, int ntiles) {
    extern __shared__ float sm[];
    float* sfA  = sm;                    // 64*132
    float* sfB  = sfA + 64 * 132;        // 64*68
    float* sWm  = sfB + 64 * 68;
    float* sW1a = sWm + 64 * 68;
    float* sW2t = sW1a + 64 * 68;
    float* sW3t = sW2t + 64 * 68;
    float* sb1  = sW3t + 64 * 68;
    float* sb2  = sb1 + 64;
    float* sb3  = sb2 + 64;
    float* sAm  = sb3 + 64;
    float* sBm  = sAm + 64;
    float* sb2m = sBm + 64;
    float* sfnz = sb2m + 64;
    int tid = threadIdx.x;
    for (int idx = tid; idx < 64 * 64; idx += 256) {
        int k = idx >> 6, j = idx & 63;
        sWm[j * 68 + k]  = mW2[idx];
        sW1a[j * 68 + k] = uW1[idx];
        sW2t[j * 68 + k] = uW2[idx];
        sW3t[j * 68 + k] = uW3[idx];
    }
    if (tid < 64) {
        sb1[tid] = ub1[tid]; sb2[tid] = ub2[tid]; sb3[tid] = ub3[tid];
        sAm[tid] = d_bnA[tid]; sBm[tid] = d_bnB[tid]; sb2m[tid] = mb2[tid];
    }
    int et = tid & 15, jt = tid >> 4;

    for (int t = blockIdx.x; t < ntiles; t += gridDim.x) {
        int base = t * 64;
        __syncthreads();
        for (int idx = tid; idx < 64 * 16; idx += 256) {
            int e = idx >> 4, q = idx & 15;
            int n = base + e;
            float4 hv = make_float4(0.f, 0.f, 0.f, 0.f);
            F4U tt; tt.v = make_float4(0.f, 0.f, 0.f, 0.f);
            if (n < NN) {
                hv = *(const float4*)(d_h + n * 64 + q * 4);
                tt.v = *(const float4*)(d_summ1 + n * 64 + q * 4);
                *(float4*)(d_summ1 + n * 64 + q * 4) = make_float4(0.f, 0.f, 0.f, 0.f);
                float inv = d_invc[n];
                float f = (d_counts[n] > 0) ? 1.0f : 0.0f;
                #pragma unroll
                for (int c = 0; c < 4; ++c)
                    tt.f[c] = sAm[q * 4 + c] * (tt.f[c] * inv) + f * sBm[q * 4 + c];
            }
            *(float4*)(sfA + e * 132 + q * 4) = hv;
            *(float4*)(sfB + e * 68 + q * 4) = tt.v;
        }
        if (tid < 64) {
            int n = base + tid;
            float f = 0.0f;
            if (n < NN) {
                f = (d_counts[n] > 0) ? 1.0f : 0.0f;
                float inv = d_invc[n];
                #pragma unroll
                for (int c = 0; c < 3; ++c) {
                    d_pos[n * 3 + c] += d_aggpm[n * 3 + c] * inv;
                    d_aggpm[n * 3 + c] = 0.0f;
                }
            }
            sfnz[tid] = f;
        }
        __syncthreads();
        {   // agg = mnorm @ mW2 + f*mb2 -> sfA[:,64:128]
            ull a0[4][4] = {};
            gemm_acc4<68, 68>(sfB, sWm, 64, et, jt, a0);
            #pragma unroll
            for (int e = 0; e < 4; ++e) {
                int er = et + 16 * e;
                float f = sfnz[er];
                F4U o;
                #pragma unroll
                for (int j = 0; j < 4; ++j)
                    o.f[j] = lane_sum(a0[e][j]) + f * sb2m[jt * 4 + j];
                *(float4*)(sfA + er * 132 + 64 + jt * 4) = o.v;
            }
        }
        __syncthreads();
        ull a1[4][4] = {};
        gemm_acc4<132, 68>(sfA, sW1a, 64, et, jt, a1);
        {   // uW1 rows 64..127 direct from gmem (L2-hot broadcast)
            const float* fb = sfA + et * 132 + 64;
            #pragma unroll 2
            for (int k0 = 0; k0 < 64; k0 += 4) {
                ull w[4][2];
                #pragma unroll
                for (int j = 0; j < 4; ++j) {
                    F4U tw;
                    tw.f[0] = uW1[(64 + k0 + 0) * 64 + jt * 4 + j];
                    tw.f[1] = uW1[(64 + k0 + 1) * 64 + jt * 4 + j];
                    tw.f[2] = uW1[(64 + k0 + 2) * 64 + jt * 4 + j];
                    tw.f[3] = uW1[(64 + k0 + 3) * 64 + jt * 4 + j];
                    w[j][0] = tw.u[0]; w[j][1] = tw.u[1];
                }
                #pragma unroll
                for (int e = 0; e < 4; ++e) {
                    F4U tf; tf.v = *(const float4*)(fb + e * 16 * 132 + k0);
                    #pragma unroll
                    for (int j = 0; j < 4; ++j) {
                        a1[e][j] = ffma2(tf.u[0], w[j][0], a1[e][j]);
                        a1[e][j] = ffma2(tf.u[1], w[j][1], a1[e][j]);
                    }
                }
            }
        }
        __syncthreads();
        #pragma unroll
        for (int e = 0; e < 4; ++e) {
            F4U o;
            #pragma unroll
            for (int j = 0; j < 4; ++j)
                o.f[j] = silu_f(lane_sum(a1[e][j]) + sb1[jt * 4 + j]);
            *(float4*)(sfB + (et + 16 * e) * 68 + jt * 4) = o.v;
        }
        __syncthreads();
        {
            ull a2[4][4] = {};
            gemm_acc4<68, 68>(sfB, sW2t, 64, et, jt, a2);
            #pragma unroll
            for (int e = 0; e < 4; ++e) {
                F4U o;
                #pragma unroll
                for (int j = 0; j < 4; ++j)
                    o.f[j] = silu_f(lane_sum(a2[e][j]) + sb2[jt * 4 + j]);
                *(float4*)(sfA + (et + 16 * e) * 132 + jt * 4) = o.v;
            }
        }
        __syncthreads();
        {
            ull a3[4][4] = {};
            gemm_acc4<132, 68>(sfA, sW3t, 64, et, jt, a3);
            #pragma unroll
            for (int e = 0; e < 4; ++e) {
                int n = base + et + 16 * e;
                if (n < NN) {
                    F4U h; h.v = *(const float4*)(d_h + n * 64 + jt * 4);
                    F4U o;
                    #pragma unroll
                    for (int j = 0; j < 4; ++j)
                        o.f[j] = h.f[j] + lane_sum(a3[e][j]) + sb3[jt * 4 + j];
                    *(float4*)(d_h + n * 64 + jt * 4) = o.v;
                    __nv_bfloat16 hb[4]; float lo[4];
                    #pragma unroll
                    for (int j = 0; j < 4; ++j) {
                        hb[j] = __float2bfloat16(o.f[j]);
                        lo[j] = o.f[j] - __bfloat162float(hb[j]);
                    }
                    uint2 H, L;
                    H.x = pack_bf(hb[0], hb[1]); H.y = pack_bf(hb[2], hb[3]);
                    L.x = pack_bf(__float2bfloat16(lo[0]), __float2bfloat16(lo[1]));
                    L.y = pack_bf(__float2bfloat16(lo[2]), __float2bfloat16(lo[3]));
                    *(uint2*)(d_hhi + n * 64 + jt * 4) = H;
                    *(uint2*)(d_hlo + n * 64 + jt * 4) = L;
                }
            }
        }
    }
}

// ---------------- energy MLP ----------------
#define EN_SMEM ((64*68*2 + 64*68*2 + 64 + 64 + 64 + 4) * (int)sizeof(float))
__global__ void energy_kernel(const float* __restrict__ W1, const float* __restrict__ b1,
                              const float* __restrict__ W2, const float* __restrict__ b2,
                              const float* __restrict__ W3, const float* __restrict__ b3,
                              float* __restrict__ out) {
    extern __shared__ float sm[];
    float* sfA  = sm;
    float* sfB  = sfA + 64 * 68;
    float* sW1t = sfB + 64 * 68;
    float* sW2t = sW1t + 64 * 68;
    float* sW3  = sW2t + 64 * 68;
    float* sb1  = sW3 + 64;
    float* sb2  = sb1 + 64;
    float* sb3  = sb2 + 64;
    int tid = threadIdx.x;
    int base = blockIdx.x * 64;
    for (int idx = tid; idx < 64 * 64; idx += 256) {
        int k = idx >> 6, j = idx & 63;
        sW1t[j * 68 + k] = W1[idx];
        sW2t[j * 68 + k] = W2[idx];
    }
    if (tid < 64) { sW3[tid] = W3[tid]; sb1[tid] = b1[tid]; sb2[tid] = b2[tid]; }
    if (tid == 0) sb3[0] = b3[0];
    for (int idx = tid; idx < 64 * 16; idx += 256) {
        int e = idx >> 4, q = idx & 15;
        int n = base + e;
        float4 v = (n < NN) ? *(const float4*)(d_h + n * 64 + q * 4)
                            : make_float4(0.f, 0.f, 0.f, 0.f);
        *(float4*)(sfA + e * 68 + q * 4) = v;
    }
    __syncthreads();
    int et = tid & 15, jt = tid >> 4;
    {
        ull acc[4][4] = {};
        gemm_acc4<68, 68>(sfA, sW1t, 64, et, jt, acc);
        #pragma unroll
        for (int e = 0; e < 4; ++e) {
            F4U o;
            #pragma unroll
            for (int j = 0; j < 4; ++j)
                o.f[j] = silu_f(lane_sum(acc[e][j]) + sb1[jt * 4 + j]);
            *(float4*)(sfB + (et + 16 * e) * 68 + jt * 4) = o.v;
        }
    }
    __syncthreads();
    {
        ull acc[4][4] = {};
        gemm_acc4<68, 68>(sfB, sW2t, 64, et, jt, acc);
        #pragma unroll
        for (int e = 0; e < 4; ++e) {
            F4U o;
            #pragma unroll
            for (int j = 0; j < 4; ++j)
                o.f[j] = silu_f(lane_sum(acc[e][j]) + sb2[jt * 4 + j]);
            *(float4*)(sfA + (et + 16 * e) * 68 + jt * 4) = o.v;
        }
    }
    __syncthreads();
    if (tid < 64) {
        int n = base + tid;
        if (n < NN) {
            float s = sb3[0];
            #pragma unroll
            for (int q = 0; q < 16; ++q) {
                F4U t; t.v = *(const float4*)(sfA + tid * 68 + q * 4);
                #pragma unroll
                for (int c = 0; c < 4; ++c) s += t.f[c] * sW3[q * 4 + c];
            }
            out[n] = s;
        }
    }
}

// ---------------- launch ----------------
extern "C" void kernel_launch(void* const* d_in, const int* in_sizes, int n_in,
                              void* d_out, int out_size) {
    const float* h_in   = (const float*)d_in[0];
    const float* pos    = (const float*)d_in[1];
    const float* cell   = (const float*)d_in[2];
    const int*   esrc   = (const int*)d_in[3];
    const int*   edst   = (const int*)d_in[4];
    const float* emb_W1 = (const float*)d_in[5];
    const float* emb_b1 = (const float*)d_in[6];
    const float* emb_W2 = (const float*)d_in[7];
    const float* emb_b2 = (const float*)d_in[8];
    const float* msg_W1 = (const float*)d_in[9];
    const float* msg_b1 = (const float*)d_in[10];
    const float* bn_g   = (const float*)d_in[11];
    const float* bn_b   = (const float*)d_in[12];
    const float* msg_W2 = (const float*)d_in[13];
    const float* msg_b2 = (const float*)d_in[14];
    const float* upd_W1 = (const float*)d_in[15];
    const float* upd_b1 = (const float*)d_in[16];
    const float* upd_W2 = (const float*)d_in[17];
    const float* upd_b2 = (const float*)d_in[18];
    const float* upd_W3 = (const float*)d_in[19];
    const float* upd_b3 = (const float*)d_in[20];
    const float* pos_W1 = (const float*)d_in[21];
    const float* pos_b1 = (const float*)d_in[22];
    const float* pos_W2 = (const float*)d_in[23];
    const float* pos_b2 = (const float*)d_in[24];
    const float* en_W1  = (const float*)d_in[25];
    const float* en_b1  = (const float*)d_in[26];
    const float* en_W2  = (const float*)d_in[27];
    const float* en_b2  = (const float*)d_in[28];
    const float* en_W3  = (const float*)d_in[29];
    const float* en_b3  = (const float*)d_in[30];
    float* out = (float*)d_out;

    static int attr_done = 0;
    if (!attr_done) {
        cudaFuncSetAttribute(embed_kernel,  cudaFuncAttributeMaxDynamicSharedMemorySize, EM_SMEM);
        cudaFuncSetAttribute(pass1_wmma,    cudaFuncAttributeMaxDynamicSharedMemorySize, P1_SMEM);
        cudaFuncSetAttribute(pass2_wmma,    cudaFuncAttributeMaxDynamicSharedMemorySize, P2_SMEM);
        cudaFuncSetAttribute(node_kernel,   cudaFuncAttributeMaxDynamicSharedMemorySize, ND_SMEM);
        cudaFuncSetAttribute(energy_kernel, cudaFuncAttributeMaxDynamicSharedMemorySize, EN_SMEM);
        attr_done = 1;
    }

    const int P1_GRID = 148 * 2;
    const int P2_GRID = 148 * 4;
    const int ND_TILES = (NN + 63) / 64;
    const int ND_GRID = 148 * 2;

    init_kernel<<<(NN * F + 255) / 256, 256>>>(pos);
    count_kernel<<<(EE + 255) / 256, 256>>>(edst);
    inv_kernel<<<(NN + 255) / 256, 256>>>();
    wconv_kernel<<<(NL * F * 128 + 255) / 256, 256>>>(msg_W1);
    embed_kernel<<<313, 256, EM_SMEM>>>(h_in, emb_W1, emb_b1, emb_W2, emb_b2);

    for (int l = 0; l < NL; ++l) {
        pass1_wmma<<<P1_GRID, 256, P1_SMEM>>>(esrc, edst, cell,
                                              msg_W1 + l * (2 * F + 1) * F, msg_b1 + l * F, l);
        bnstats_kernel<<<256, 256>>>(l);
        prep_kernel<<<1, 1024>>>(bn_g + l * F, bn_b + l * F,
                                 msg_W2 + l * F * F, msg_b2 + l * F,
                                 pos_W1 + l * F * F, pos_b1 + l * F, l);
        pass2_wmma<<<P2_GRID, 256, P2_SMEM>>>(edst,
                                              pos_W2 + l * F * DIM, pos_b2 + l * DIM);
        node_kernel<<<ND_GRID, 256, ND_SMEM>>>(msg_W2 + l * F * F, msg_b2 + l * F,
                                               upd_W1 + l * 2 * F * F, upd_b1 + l * F,
                                               upd_W2 + l * F * F, upd_b2 + l * F,
                                               upd_W3 + l * F * F, upd_b3 + l * F, ND_TILES);
    }
    energy_kernel<<<313, 256, EN_SMEM>>>(en_W1, en_b1, en_W2, en_b2, en_W3, en_b3, out);
}

// round 11
// speedup vs baseline: 3.4272x; 1.0204x over previous
#include <cuda_runtime.h>
#include <cuda_bf16.h>
#include <mma.h>
#include <cstdint>

namespace wm = nvcuda::wmma;

#define NN 20000
#define EE 160000
#define FIN 9
#define F 64
#define NL 7
#define DIM 3
#define BN_EPS 1e-5f
#define NT_T128 1250

typedef unsigned long long ull;
union F4U { float4 v; ull u[2]; float f[4]; };

// ---------------- device scratch ----------------
__device__ float d_h[NN * F];
__device__ __nv_bfloat16 d_hhi[NN * F];
__device__ __nv_bfloat16 d_hlo[NN * F];
__device__ float d_pos[NN * DIM];
__device__ __nv_bfloat16 d_m1hi[EE * F];
__device__ __nv_bfloat16 d_m1lo[EE * F];
__device__ float d_dvec[EE * DIM];
__device__ float d_summ1[NN * F];
__device__ float d_aggpm[NN * DIM];
__device__ int   d_counts[NN];
__device__ float d_invc[NN];
__device__ float d_bnsum[NL * F];
__device__ float d_bnsumsq[NL * F];
__device__ float d_bnA[F];
__device__ float d_bnB[F];
__device__ float d_bc[F];
__device__ __nv_bfloat16 d_w1hi[NL * F * 128];   // [l][j][k]  (col-major KxN for wmma B)
__device__ __nv_bfloat16 d_w1lo[NL * F * 128];
__device__ __nv_bfloat16 d_wchi[F * F];          // [j][k]
__device__ __nv_bfloat16 d_wclo[F * F];

__device__ __forceinline__ float silu_f(float x) { return x / (1.0f + expf(-x)); }

__device__ __forceinline__ ull ffma2(ull a, ull b, ull c) {
    ull d;
    asm("fma.rn.f32x2 %0, %1, %2, %3;" : "=l"(d) : "l"(a), "l"(b), "l"(c));
    return d;
}
__device__ __forceinline__ float lane_sum(ull a) {
    float lo = __uint_as_float((unsigned)(a & 0xffffffffull));
    float hi = __uint_as_float((unsigned)(a >> 32));
    return lo + hi;
}
__device__ __forceinline__ void red_add_v4(float* p, float a, float b, float c, float d) {
    asm volatile("red.global.add.v4.f32 [%0], {%1,%2,%3,%4};"
                 :: "l"(p), "f"(a), "f"(b), "f"(c), "f"(d) : "memory");
}
__device__ __forceinline__ unsigned pack_bf(__nv_bfloat16 a, __nv_bfloat16 b) {
    __nv_bfloat162 t(a, b); return *(unsigned*)&t;
}

// ---------------- FFMA2 GEMM core ----------------
template<int PF, int PW>
__device__ __forceinline__ void gemm_acc4(const float* __restrict__ sf,
                                          const float* __restrict__ sWt,
                                          int kmax, int et, int jt, ull acc[4][4]) {
    const float* fb = sf + et * PF;
    const float* wb = sWt + (jt * 4) * PW;
    #pragma unroll 2
    for (int k0 = 0; k0 < kmax; k0 += 4) {
        ull w[4][2];
        #pragma unroll
        for (int j = 0; j < 4; ++j) {
            F4U t; t.v = *(const float4*)(wb + j * PW + k0);
            w[j][0] = t.u[0]; w[j][1] = t.u[1];
        }
        #pragma unroll
        for (int e = 0; e < 4; ++e) {
            F4U t; t.v = *(const float4*)(fb + e * 16 * PF + k0);
            #pragma unroll
            for (int j = 0; j < 4; ++j) {
                acc[e][j] = ffma2(t.u[0], w[j][0], acc[e][j]);
                acc[e][j] = ffma2(t.u[1], w[j][1], acc[e][j]);
            }
        }
    }
}

// ---------------- init ----------------
__global__ void init_kernel(const float* __restrict__ pos_in) {
    int i = blockIdx.x * blockDim.x + threadIdx.x;
    if (i < NN * F) d_summ1[i] = 0.0f;
    if (i < NN * DIM) { d_aggpm[i] = 0.0f; d_pos[i] = pos_in[i]; }
    if (i < NN) d_counts[i] = 0;
    if (i < NL * F) { d_bnsum[i] = 0.0f; d_bnsumsq[i] = 0.0f; }
}
__global__ void count_kernel(const int* __restrict__ edge_dst) {
    int i = blockIdx.x * blockDim.x + threadIdx.x;
    if (i < EE) atomicAdd(&d_counts[edge_dst[i]], 1);
}
__global__ void inv_kernel() {
    int i = blockIdx.x * blockDim.x + threadIdx.x;
    if (i < NN) d_invc[i] = 1.0f / fmaxf((float)d_counts[i], 1.0f);
}
// all layers' msg_W1 -> bf16 hi/lo, [l][j][k] layout (rows 0..127 only)
__global__ void wconv_kernel(const float* __restrict__ msg_W1) {
    int idx = blockIdx.x * blockDim.x + threadIdx.x;
    if (idx >= NL * F * 128) return;
    int l = idx >> 13, r = idx & 8191;
    int j = r >> 7, k = r & 127;
    float v = msg_W1[l * 8256 + k * 64 + j];
    __nv_bfloat16 h = __float2bfloat16(v);
    d_w1hi[idx] = h;
    d_w1lo[idx] = __float2bfloat16(v - __bfloat162float(h));
}

// ---------------- embedding (FFMA2) + h hi/lo emission ----------------
#define EM_SMEM ((64*12 + 64*12 + 64*68 + 64*68 + 128) * (int)sizeof(float))
__global__ void embed_kernel(const float* __restrict__ h_in,
                             const float* __restrict__ W1, const float* __restrict__ b1,
                             const float* __restrict__ W2, const float* __restrict__ b2) {
    extern __shared__ float sm[];
    float* sf   = sm;
    float* sW1t = sf + 64 * 12;
    float* sfB  = sW1t + 64 * 12;
    float* sW2t = sfB + 64 * 68;
    float* sb1  = sW2t + 64 * 68;
    float* sb2  = sb1 + 64;
    int tid = threadIdx.x;
    int base = blockIdx.x * 64;
    for (int idx = tid; idx < 64 * 12; idx += 256) {
        int j = idx / 12, k = idx - j * 12;
        sW1t[idx] = (k < FIN) ? W1[k * 64 + j] : 0.0f;
    }
    for (int idx = tid; idx < 64 * 64; idx += 256) {
        int k = idx >> 6, j = idx & 63;
        sW2t[j * 68 + k] = W2[idx];
    }
    if (tid < 64) { sb1[tid] = b1[tid]; sb2[tid] = b2[tid]; }
    for (int idx = tid; idx < 64 * 12; idx += 256) {
        int e = idx / 12, k = idx - e * 12;
        int n = base + e;
        sf[idx] = (k < FIN && n < NN) ? h_in[n * FIN + k] : 0.0f;
    }
    __syncthreads();
    int et = tid & 15, jt = tid >> 4;
    {
        ull acc[4][4] = {};
        gemm_acc4<12, 12>(sf, sW1t, 12, et, jt, acc);
        #pragma unroll
        for (int e = 0; e < 4; ++e) {
            F4U o;
            #pragma unroll
            for (int j = 0; j < 4; ++j)
                o.f[j] = silu_f(lane_sum(acc[e][j]) + sb1[jt * 4 + j]);
            *(float4*)(sfB + (et + 16 * e) * 68 + jt * 4) = o.v;
        }
    }
    __syncthreads();
    {
        ull acc[4][4] = {};
        gemm_acc4<68, 68>(sfB, sW2t, 64, et, jt, acc);
        #pragma unroll
        for (int e = 0; e < 4; ++e) {
            int n = base + et + 16 * e;
            if (n < NN) {
                F4U o;
                #pragma unroll
                for (int j = 0; j < 4; ++j)
                    o.f[j] = lane_sum(acc[e][j]) + sb2[jt * 4 + j];
                *(float4*)(d_h + n * 64 + jt * 4) = o.v;
                __nv_bfloat16 hb[4]; float lo[4];
                #pragma unroll
                for (int j = 0; j < 4; ++j) {
                    hb[j] = __float2bfloat16(o.f[j]);
                    lo[j] = o.f[j] - __bfloat162float(hb[j]);
                }
                uint2 H, L;
                H.x = pack_bf(hb[0], hb[1]); H.y = pack_bf(hb[2], hb[3]);
                L.x = pack_bf(__float2bfloat16(lo[0]), __float2bfloat16(lo[1]));
                L.y = pack_bf(__float2bfloat16(lo[2]), __float2bfloat16(lo[3]));
                *(uint2*)(d_hhi + n * 64 + jt * 4) = H;
                *(uint2*)(d_hlo + n * 64 + jt * 4) = L;
            }
        }
    }
}

// ---------------- pass1: wmma bf16 hi/lo, 128 edges/tile, 32x32 warp tiles ----------------
// bytes: Ahi 0 (34816) Alo 34816 Bhi 69632 (17408) Blo 87040 -> 104448
//        Acc reuses Ahi region (128*68*4 = 34816)
//        w129 104448 sb1 104704 sdist 104960 sdst 105472 ssrc 105984 -> 106496
#define P1_SMEM 106496
__global__ void __launch_bounds__(256, 2)
pass1_wmma(const int* __restrict__ esrc, const int* __restrict__ edst,
           const float* __restrict__ cell,
           const float* __restrict__ W1, const float* __restrict__ b1, int l) {
    extern __shared__ char smem[];
    __nv_bfloat16* sAhi = (__nv_bfloat16*)(smem);
    __nv_bfloat16* sAlo = (__nv_bfloat16*)(smem + 34816);
    __nv_bfloat16* sBhi = (__nv_bfloat16*)(smem + 69632);
    __nv_bfloat16* sBlo = (__nv_bfloat16*)(smem + 87040);
    float* sAcc  = (float*)(smem);                 // reuse A-hi after MMA
    float* w129  = (float*)(smem + 104448);
    float* sb1   = (float*)(smem + 104704);
    float* sdist = (float*)(smem + 104960);
    int*   sdst  = (int*)(smem + 105472);
    int*   ssrc  = (int*)(smem + 105984);
    int tid = threadIdx.x;
    for (int i = tid; i < 64 * 16; i += 256) {
        int j = i >> 4, c = i & 15;
        *(uint4*)(sBhi + j * 136 + c * 8) = ((const uint4*)(d_w1hi + l * 8192 + j * 128))[c];
        *(uint4*)(sBlo + j * 136 + c * 8) = ((const uint4*)(d_w1lo + l * 8192 + j * 128))[c];
    }
    if (tid < 64) { w129[tid] = W1[128 * 64 + tid]; sb1[tid] = b1[tid]; }
    int w = tid >> 5, rg = w >> 1, nh = w & 1;

    for (int t = blockIdx.x; t < NT_T128; t += gridDim.x) {
        int base = t * 128;
        __syncthreads();   // previous tile's epilogue reads of sAcc done
        if (tid < 128) {
            int ge = base + tid;
            int dn = edst[ge], sn = esrc[ge];
            sdst[tid] = dn; ssrc[tid] = sn;
            float dv0 = d_pos[dn * 3 + 0] - d_pos[sn * 3 + 0] + cell[ge * 3 + 0];
            float dv1 = d_pos[dn * 3 + 1] - d_pos[sn * 3 + 1] + cell[ge * 3 + 1];
            float dv2 = d_pos[dn * 3 + 2] - d_pos[sn * 3 + 2] + cell[ge * 3 + 2];
            d_dvec[ge * 3 + 0] = dv0; d_dvec[ge * 3 + 1] = dv1; d_dvec[ge * 3 + 2] = dv2;
            sdist[tid] = dv0 + dv1 + dv2;
        }
        __syncthreads();
        // gather A: row e, k0..63 = h[dst], k64..127 = h[src]
        for (int idx = tid; idx < 128 * 32; idx += 256) {
            int e = idx >> 5, q = idx & 31, c = q & 7;
            int n = (q & 8) ? ssrc[e] : sdst[e];
            const uint4* src = (q & 16) ? (const uint4*)(d_hlo + n * 64)
                                        : (const uint4*)(d_hhi + n * 64);
            __nv_bfloat16* dp = ((q & 16) ? sAlo : sAhi) + e * 136 + ((q & 8) ? 64 : 0) + c * 8;
            *(uint4*)dp = src[c];
        }
        __syncthreads();
        // MMA: warp (rg, nh) -> rows 32rg..+31, cols 32nh..+31
        wm::fragment<wm::accumulator, 16, 16, 16, float> c00, c01, c10, c11;
        wm::fill_fragment(c00, 0.0f); wm::fill_fragment(c01, 0.0f);
        wm::fill_fragment(c10, 0.0f); wm::fill_fragment(c11, 0.0f);
        {
            const __nv_bfloat16* Ah = sAhi + rg * 32 * 136;
            const __nv_bfloat16* Al = sAlo + rg * 32 * 136;
            const __nv_bfloat16* B0h = sBhi + (nh * 32) * 136;
            const __nv_bfloat16* B1h = sBhi + (nh * 32 + 16) * 136;
            const __nv_bfloat16* B0l = sBlo + (nh * 32) * 136;
            const __nv_bfloat16* B1l = sBlo + (nh * 32 + 16) * 136;
            #pragma unroll
            for (int kt = 0; kt < 8; ++kt) {
                wm::fragment<wm::matrix_a, 16, 16, 16, __nv_bfloat16, wm::row_major> ah0, ah1, al0, al1;
                wm::load_matrix_sync(ah0, Ah + kt * 16, 136);
                wm::load_matrix_sync(ah1, Ah + 16 * 136 + kt * 16, 136);
                wm::load_matrix_sync(al0, Al + kt * 16, 136);
                wm::load_matrix_sync(al1, Al + 16 * 136 + kt * 16, 136);
                wm::fragment<wm::matrix_b, 16, 16, 16, __nv_bfloat16, wm::col_major> b;
                wm::load_matrix_sync(b, B0h + kt * 16, 136);
                wm::mma_sync(c00, ah0, b, c00);
                wm::mma_sync(c10, ah1, b, c10);
                wm::mma_sync(c00, al0, b, c00);
                wm::mma_sync(c10, al1, b, c10);
                wm::load_matrix_sync(b, B1h + kt * 16, 136);
                wm::mma_sync(c01, ah0, b, c01);
                wm::mma_sync(c11, ah1, b, c11);
                wm::mma_sync(c01, al0, b, c01);
                wm::mma_sync(c11, al1, b, c11);
                wm::load_matrix_sync(b, B0l + kt * 16, 136);
                wm::mma_sync(c00, ah0, b, c00);
                wm::mma_sync(c10, ah1, b, c10);
                wm::load_matrix_sync(b, B1l + kt * 16, 136);
                wm::mma_sync(c01, ah0, b, c01);
                wm::mma_sync(c11, ah1, b, c11);
            }
        }
        __syncthreads();   // A reads done everywhere before acc overwrites A-hi
        wm::store_matrix_sync(sAcc + (rg * 32) * 68 + nh * 32, c00, 68, wm::mem_row_major);
        wm::store_matrix_sync(sAcc + (rg * 32) * 68 + nh * 32 + 16, c01, 68, wm::mem_row_major);
        wm::store_matrix_sync(sAcc + (rg * 32 + 16) * 68 + nh * 32, c10, 68, wm::mem_row_major);
        wm::store_matrix_sync(sAcc + (rg * 32 + 16) * 68 + nh * 32 + 16, c11, 68, wm::mem_row_major);
        __syncthreads();
        // epilogue: 2 threads/edge, 32 cols each
        {
            int e = tid & 127, p = tid >> 7;
            int ge = base + e;
            int dn = sdst[e];
            float dist = sdist[e];
            #pragma unroll
            for (int c = 0; c < 4; ++c) {
                int jb = p * 32 + c * 8;
                float mv[8];
                __nv_bfloat16 hb[8], lb[8];
                #pragma unroll
                for (int jj = 0; jj < 8; ++jj) {
                    int j = jb + jj;
                    float v = sAcc[e * 68 + j] + dist * w129[j] + sb1[j];
                    v = silu_f(v);
                    mv[jj] = v;
                    hb[jj] = __float2bfloat16(v);
                    lb[jj] = __float2bfloat16(v - __bfloat162float(hb[jj]));
                }
                uint4 H, L;
                H.x = pack_bf(hb[0], hb[1]); H.y = pack_bf(hb[2], hb[3]);
                H.z = pack_bf(hb[4], hb[5]); H.w = pack_bf(hb[6], hb[7]);
                L.x = pack_bf(lb[0], lb[1]); L.y = pack_bf(lb[2], lb[3]);
                L.z = pack_bf(lb[4], lb[5]); L.w = pack_bf(lb[6], lb[7]);
                ((uint4*)(d_m1hi + (size_t)ge * 64))[jb >> 3] = H;
                ((uint4*)(d_m1lo + (size_t)ge * 64))[jb >> 3] = L;
                red_add_v4(d_summ1 + dn * 64 + jb,     mv[0], mv[1], mv[2], mv[3]);
                red_add_v4(d_summ1 + dn * 64 + jb + 4, mv[4], mv[5], mv[6], mv[7]);
            }
        }
    }
}

// ---------------- bnstats: bnsum from summ1, bnsumsq from m1 hi/lo ----------------
__global__ void bnstats_kernel(int l) {
    __shared__ float ssum[64], ssq[64];
    int tid = threadIdx.x;
    if (tid < 64) { ssum[tid] = 0.0f; ssq[tid] = 0.0f; }
    __syncthreads();
    int jp = tid & 31;
    int r0 = blockIdx.x * 8 + (tid >> 5);
    int rstep = gridDim.x * 8;
    float sq0 = 0, sq1 = 0;
    for (int row = r0; row < EE; row += rstep) {
        unsigned hw = ((const unsigned*)d_m1hi)[row * 32 + jp];
        unsigned lw = ((const unsigned*)d_m1lo)[row * 32 + jp];
        __nv_bfloat162 hb = *(__nv_bfloat162*)&hw, lb = *(__nv_bfloat162*)&lw;
        float v0 = __bfloat162float(hb.x) + __bfloat162float(lb.x);
        float v1 = __bfloat162float(hb.y) + __bfloat162float(lb.y);
        sq0 += v0 * v0; sq1 += v1 * v1;
    }
    float s0 = 0, s1 = 0;
    for (int row = r0; row < NN; row += rstep) {
        float2 v = ((const float2*)d_summ1)[row * 32 + jp];
        s0 += v.x; s1 += v.y;
    }
    atomicAdd(&ssq[jp * 2], sq0);  atomicAdd(&ssq[jp * 2 + 1], sq1);
    atomicAdd(&ssum[jp * 2], s0);  atomicAdd(&ssum[jp * 2 + 1], s1);
    __syncthreads();
    if (tid < 64) {
        atomicAdd(&d_bnsumsq[l * 64 + tid], ssq[tid]);
        atomicAdd(&d_bnsum[l * 64 + tid], ssum[tid]);
    }
}

// ---------------- prep: BN affine; Wc=diag(A)W2@pW1 (bf16 hi/lo); bc ----------------
__global__ void prep_kernel(const float* __restrict__ gamma, const float* __restrict__ beta,
                            const float* __restrict__ W2, const float* __restrict__ b2,
                            const float* __restrict__ pW1, const float* __restrict__ pb1, int l) {
    __shared__ float sW2[64 * 64], spW1[64 * 64];
    __shared__ float sA[64], sB[64], sv[64];
    int tid = threadIdx.x;
    for (int idx = tid; idx < 64 * 64; idx += 1024) {
        sW2[idx] = W2[idx];
        spW1[idx] = pW1[idx];
    }
    if (tid < 64) {
        float mu  = d_bnsum[l * 64 + tid]   * (1.0f / (float)EE);
        float var = d_bnsumsq[l * 64 + tid] * (1.0f / (float)EE) - mu * mu;
        float inv = rsqrtf(var + BN_EPS);
        float A = gamma[tid] * inv;
        float B = beta[tid] - mu * A;
        sA[tid] = A; sB[tid] = B;
        d_bnA[tid] = A; d_bnB[tid] = B;
    }
    __syncthreads();
    if (tid < 64) {
        float acc = b2[tid];
        #pragma unroll 8
        for (int k = 0; k < 64; ++k) acc += sB[k] * sW2[k * 64 + tid];
        sv[tid] = acc;
    }
    for (int idx = tid; idx < 64 * 64; idx += 1024) {
        int k = idx >> 6, j = idx & 63;
        float acc = 0.0f;
        #pragma unroll 8
        for (int q = 0; q < 64; ++q) acc += sW2[k * 64 + q] * spW1[q * 64 + j];
        float v = sA[k] * acc;
        __nv_bfloat16 h = __float2bfloat16(v);
        d_wchi[j * 64 + k] = h;
        d_wclo[j * 64 + k] = __float2bfloat16(v - __bfloat162float(h));
    }
    __syncthreads();
    if (tid < 64) {
        float acc = pb1[tid];
        #pragma unroll 8
        for (int q = 0; q < 64; ++q) acc += sv[q] * spW1[q * 64 + tid];
        d_bc[tid] = acc;
    }
}

// ---------------- pass2: wmma bf16 hi/lo, 128 edges/tile ----------------
// bytes: Ahi 0 (18432) Alo 18432 Bhi 36864 (9216) Blo 46080 -> 55296
//        Acc reuses Ahi+Alo (128*68*4 = 34816 <= 36864)
//        sbc 55296 spW2 55552 spb2 56320 sdv 56336 sdst 57872 -> 58384
#define P2_SMEM 58384
__global__ void __launch_bounds__(256, 2)
pass2_wmma(const int* __restrict__ edst,
           const float* __restrict__ pW2, const float* __restrict__ pb2) {
    extern __shared__ char smem[];
    __nv_bfloat16* sAhi = (__nv_bfloat16*)(smem);
    __nv_bfloat16* sAlo = (__nv_bfloat16*)(smem + 18432);
    __nv_bfloat16* sBhi = (__nv_bfloat16*)(smem + 36864);
    __nv_bfloat16* sBlo = (__nv_bfloat16*)(smem + 46080);
    float* sAcc = (float*)(smem);                  // reuse A after MMA
    float* sbc  = (float*)(smem + 55296);
    float* spW2 = (float*)(smem + 55552);
    float* spb2 = (float*)(smem + 56320);
    float* sdv  = (float*)(smem + 56336);
    int*   sdst = (int*)(smem + 57872);
    int tid = threadIdx.x;
    for (int i = tid; i < 64 * 8; i += 256) {
        int j = i >> 3, c = i & 7;
        *(uint4*)(sBhi + j * 72 + c * 8) = ((const uint4*)(d_wchi + j * 64))[c];
        *(uint4*)(sBlo + j * 72 + c * 8) = ((const uint4*)(d_wclo + j * 64))[c];
    }
    if (tid < 64) sbc[tid] = d_bc[tid];
    for (int i = tid; i < 192; i += 256) spW2[i] = pW2[i];
    if (tid < 3) spb2[tid] = pb2[tid];
    int w = tid >> 5, rg = w >> 1, nh = w & 1;

    for (int t = blockIdx.x; t < NT_T128; t += gridDim.x) {
        int base = t * 128;
        __syncthreads();
        if (tid < 128) sdst[tid] = edst[base + tid];
        for (int i = tid; i < 384; i += 256) sdv[i] = d_dvec[base * 3 + i];
        for (int idx = tid; idx < 128 * 16; idx += 256) {
            int e = idx >> 4, q = idx & 15, c = q & 7;
            const uint4* src = (q & 8) ? (const uint4*)(d_m1lo + (size_t)(base + e) * 64)
                                       : (const uint4*)(d_m1hi + (size_t)(base + e) * 64);
            __nv_bfloat16* dp = ((q & 8) ? sAlo : sAhi) + e * 72 + c * 8;
            *(uint4*)dp = src[c];
        }
        __syncthreads();
        wm::fragment<wm::accumulator, 16, 16, 16, float> c00, c01, c10, c11;
        wm::fill_fragment(c00, 0.0f); wm::fill_fragment(c01, 0.0f);
        wm::fill_fragment(c10, 0.0f); wm::fill_fragment(c11, 0.0f);
        {
            const __nv_bfloat16* Ah = sAhi + rg * 32 * 72;
            const __nv_bfloat16* Al = sAlo + rg * 32 * 72;
            const __nv_bfloat16* B0h = sBhi + (nh * 32) * 72;
            const __nv_bfloat16* B1h = sBhi + (nh * 32 + 16) * 72;
            const __nv_bfloat16* B0l = sBlo + (nh * 32) * 72;
            const __nv_bfloat16* B1l = sBlo + (nh * 32 + 16) * 72;
            #pragma unroll
            for (int kt = 0; kt < 4; ++kt) {
                wm::fragment<wm::matrix_a, 16, 16, 16, __nv_bfloat16, wm::row_major> ah0, ah1, al0, al1;
                wm::load_matrix_sync(ah0, Ah + kt * 16, 72);
                wm::load_matrix_sync(ah1, Ah + 16 * 72 + kt * 16, 72);
                wm::load_matrix_sync(al0, Al + kt * 16, 72);
                wm::load_matrix_sync(al1, Al + 16 * 72 + kt * 16, 72);
                wm::fragment<wm::matrix_b, 16, 16, 16, __nv_bfloat16, wm::col_major> b;
                wm::load_matrix_sync(b, B0h + kt * 16, 72);
                wm::mma_sync(c00, ah0, b, c00);
                wm::mma_sync(c10, ah1, b, c10);
                wm::mma_sync(c00, al0, b, c00);
                wm::mma_sync(c10, al1, b, c10);
                wm::load_matrix_sync(b, B1h + kt * 16, 72);
                wm::mma_sync(c01, ah0, b, c01);
                wm::mma_sync(c11, ah1, b, c11);
                wm::mma_sync(c01, al0, b, c01);
                wm::mma_sync(c11, al1, b, c11);
                wm::load_matrix_sync(b, B0l + kt * 16, 72);
                wm::mma_sync(c00, ah0, b, c00);
                wm::mma_sync(c10, ah1, b, c10);
                wm::load_matrix_sync(b, B1l + kt * 16, 72);
                wm::mma_sync(c01, ah0, b, c01);
                wm::mma_sync(c11, ah1, b, c11);
            }
        }
        __syncthreads();
        wm::store_matrix_sync(sAcc + (rg * 32) * 68 + nh * 32, c00, 68, wm::mem_row_major);
        wm::store_matrix_sync(sAcc + (rg * 32) * 68 + nh * 32 + 16, c01, 68, wm::mem_row_major);
        wm::store_matrix_sync(sAcc + (rg * 32 + 16) * 68 + nh * 32, c10, 68, wm::mem_row_major);
        wm::store_matrix_sync(sAcc + (rg * 32 + 16) * 68 + nh * 32 + 16, c11, 68, wm::mem_row_major);
        __syncthreads();
        if (tid < 128) {
            float s0 = spb2[0], s1 = spb2[1], s2 = spb2[2];
            #pragma unroll
            for (int q = 0; q < 16; ++q) {
                F4U tt; tt.v = *(const float4*)(sAcc + tid * 68 + q * 4);
                #pragma unroll
                for (int c = 0; c < 4; ++c) {
                    int j = q * 4 + c;
                    float v = silu_f(tt.f[c] + sbc[j]);
                    s0 += v * spW2[j * 3 + 0];
                    s1 += v * spW2[j * 3 + 1];
                    s2 += v * spW2[j * 3 + 2];
                }
            }
            int dn = sdst[tid];
            atomicAdd(&d_aggpm[dn * 3 + 0], sdv[tid * 3 + 0] * s0);
            atomicAdd(&d_aggpm[dn * 3 + 1], sdv[tid * 3 + 1] * s1);
            atomicAdd(&d_aggpm[dn * 3 + 2], sdv[tid * 3 + 2] * s2);
        }
    }
}

// ---------------- node (FFMA2, persistent) + h hi/lo emission ----------------
#define ND_SMEM ((64*132 + 64*68*5 + 192 + 256) * (int)sizeof(float))
__global__ void __launch_bounds__(256, 2)
node_kernel(const float* __restrict__ mW2, const float* __restrict__ mb2,
            const float* __restrict__ uW1, const float* __restrict__ ub1,
            const float* __restrict__ uW2, const float* __restrict__ ub2,
            const float* __restrict__ uW3, const float* __restrict__ ub3, int ntiles) {
    extern __shared__ float sm[];
    float* sfA  = sm;                    // 64*132
    float* sfB  = sfA + 64 * 132;        // 64*68
    float* sWm  = sfB + 64 * 68;
    float* sW1a = sWm + 64 * 68;
    float* sW2t = sW1a + 64 * 68;
    float* sW3t = sW2t + 64 * 68;
    float* sb1  = sW3t + 64 * 68;
    float* sb2  = sb1 + 64;
    float* sb3  = sb2 + 64;
    float* sAm  = sb3 + 64;
    float* sBm  = sAm + 64;
    float* sb2m = sBm + 64;
    float* sfnz = sb2m + 64;
    int tid = threadIdx.x;
    for (int idx = tid; idx < 64 * 64; idx += 256) {
        int k = idx >> 6, j = idx & 63;
        sWm[j * 68 + k]  = mW2[idx];
        sW1a[j * 68 + k] = uW1[idx];
        sW2t[j * 68 + k] = uW2[idx];
        sW3t[j * 68 + k] = uW3[idx];
    }
    if (tid < 64) {
        sb1[tid] = ub1[tid]; sb2[tid] = ub2[tid]; sb3[tid] = ub3[tid];
        sAm[tid] = d_bnA[tid]; sBm[tid] = d_bnB[tid]; sb2m[tid] = mb2[tid];
    }
    int et = tid & 15, jt = tid >> 4;

    for (int t = blockIdx.x; t < ntiles; t += gridDim.x) {
        int base = t * 64;
        __syncthreads();
        for (int idx = tid; idx < 64 * 16; idx += 256) {
            int e = idx >> 4, q = idx & 15;
            int n = base + e;
            float4 hv = make_float4(0.f, 0.f, 0.f, 0.f);
            F4U tt; tt.v = make_float4(0.f, 0.f, 0.f, 0.f);
            if (n < NN) {
                hv = *(const float4*)(d_h + n * 64 + q * 4);
                tt.v = *(const float4*)(d_summ1 + n * 64 + q * 4);
                *(float4*)(d_summ1 + n * 64 + q * 4) = make_float4(0.f, 0.f, 0.f, 0.f);
                float inv = d_invc[n];
                float f = (d_counts[n] > 0) ? 1.0f : 0.0f;
                #pragma unroll
                for (int c = 0; c < 4; ++c)
                    tt.f[c] = sAm[q * 4 + c] * (tt.f[c] * inv) + f * sBm[q * 4 + c];
            }
            *(float4*)(sfA + e * 132 + q * 4) = hv;
            *(float4*)(sfB + e * 68 + q * 4) = tt.v;
        }
        if (tid < 64) {
            int n = base + tid;
            float f = 0.0f;
            if (n < NN) {
                f = (d_counts[n] > 0) ? 1.0f : 0.0f;
                float inv = d_invc[n];
                #pragma unroll
                for (int c = 0; c < 3; ++c) {
                    d_pos[n * 3 + c] += d_aggpm[n * 3 + c] * inv;
                    d_aggpm[n * 3 + c] = 0.0f;
                }
            }
            sfnz[tid] = f;
        }
        __syncthreads();
        {   // agg = mnorm @ mW2 + f*mb2 -> sfA[:,64:128]
            ull a0[4][4] = {};
            gemm_acc4<68, 68>(sfB, sWm, 64, et, jt, a0);
            #pragma unroll
            for (int e = 0; e < 4; ++e) {
                int er = et + 16 * e;
                float f = sfnz[er];
                F4U o;
                #pragma unroll
                for (int j = 0; j < 4; ++j)
                    o.f[j] = lane_sum(a0[e][j]) + f * sb2m[jt * 4 + j];
                *(float4*)(sfA + er * 132 + 64 + jt * 4) = o.v;
            }
        }
        __syncthreads();
        ull a1[4][4] = {};
        gemm_acc4<132, 68>(sfA, sW1a, 64, et, jt, a1);
        {   // uW1 rows 64..127 direct from gmem (L2-hot broadcast)
            const float* fb = sfA + et * 132 + 64;
            #pragma unroll 2
            for (int k0 = 0; k0 < 64; k0 += 4) {
                ull w[4][2];
                #pragma unroll
                for (int j = 0; j < 4; ++j) {
                    F4U tw;
                    tw.f[0] = uW1[(64 + k0 + 0) * 64 + jt * 4 + j];
                    tw.f[1] = uW1[(64 + k0 + 1) * 64 + jt * 4 + j];
                    tw.f[2] = uW1[(64 + k0 + 2) * 64 + jt * 4 + j];
                    tw.f[3] = uW1[(64 + k0 + 3) * 64 + jt * 4 + j];
                    w[j][0] = tw.u[0]; w[j][1] = tw.u[1];
                }
                #pragma unroll
                for (int e = 0; e < 4; ++e) {
                    F4U tf; tf.v = *(const float4*)(fb + e * 16 * 132 + k0);
                    #pragma unroll
                    for (int j = 0; j < 4; ++j) {
                        a1[e][j] = ffma2(tf.u[0], w[j][0], a1[e][j]);
                        a1[e][j] = ffma2(tf.u[1], w[j][1], a1[e][j]);
                    }
                }
            }
        }
        __syncthreads();
        #pragma unroll
        for (int e = 0; e < 4; ++e) {
            F4U o;
            #pragma unroll
            for (int j = 0; j < 4; ++j)
                o.f[j] = silu_f(lane_sum(a1[e][j]) + sb1[jt * 4 + j]);
            *(float4*)(sfB + (et + 16 * e) * 68 + jt * 4) = o.v;
        }
        __syncthreads();
        {
            ull a2[4][4] = {};
            gemm_acc4<68, 68>(sfB, sW2t, 64, et, jt, a2);
            #pragma unroll
            for (int e = 0; e < 4; ++e) {
                F4U o;
                #pragma unroll
                for (int j = 0; j < 4; ++j)
                    o.f[j] = silu_f(lane_sum(a2[e][j]) + sb2[jt * 4 + j]);
                *(float4*)(sfA + (et + 16 * e) * 132 + jt * 4) = o.v;
            }
        }
        __syncthreads();
        {
            ull a3[4][4] = {};
            gemm_acc4<132, 68>(sfA, sW3t, 64, et, jt, a3);
            #pragma unroll
            for (int e = 0; e < 4; ++e) {
                int n = base + et + 16 * e;
                if (n < NN) {
                    F4U h; h.v = *(const float4*)(d_h + n * 64 + jt * 4);
                    F4U o;
                    #pragma unroll
                    for (int j = 0; j < 4; ++j)
                        o.f[j] = h.f[j] + lane_sum(a3[e][j]) + sb3[jt * 4 + j];
                    *(float4*)(d_h + n * 64 + jt * 4) = o.v;
                    __nv_bfloat16 hb[4]; float lo[4];
                    #pragma unroll
                    for (int j = 0; j < 4; ++j) {
                        hb[j] = __float2bfloat16(o.f[j]);
                        lo[j] = o.f[j] - __bfloat162float(hb[j]);
                    }
                    uint2 H, L;
                    H.x = pack_bf(hb[0], hb[1]); H.y = pack_bf(hb[2], hb[3]);
                    L.x = pack_bf(__float2bfloat16(lo[0]), __float2bfloat16(lo[1]));
                    L.y = pack_bf(__float2bfloat16(lo[2]), __float2bfloat16(lo[3]));
                    *(uint2*)(d_hhi + n * 64 + jt * 4) = H;
                    *(uint2*)(d_hlo + n * 64 + jt * 4) = L;
                }
            }
        }
    }
}

// ---------------- energy MLP ----------------
#define EN_SMEM ((64*68*2 + 64*68*2 + 64 + 64 + 64 + 4) * (int)sizeof(float))
__global__ void energy_kernel(const float* __restrict__ W1, const float* __restrict__ b1,
                              const float* __restrict__ W2, const float* __restrict__ b2,
                              const float* __restrict__ W3, const float* __restrict__ b3,
                              float* __restrict__ out) {
    extern __shared__ float sm[];
    float* sfA  = sm;
    float* sfB  = sfA + 64 * 68;
    float* sW1t = sfB + 64 * 68;
    float* sW2t = sW1t + 64 * 68;
    float* sW3  = sW2t + 64 * 68;
    float* sb1  = sW3 + 64;
    float* sb2  = sb1 + 64;
    float* sb3  = sb2 + 64;
    int tid = threadIdx.x;
    int base = blockIdx.x * 64;
    for (int idx = tid; idx < 64 * 64; idx += 256) {
        int k = idx >> 6, j = idx & 63;
        sW1t[j * 68 + k] = W1[idx];
        sW2t[j * 68 + k] = W2[idx];
    }
    if (tid < 64) { sW3[tid] = W3[tid]; sb1[tid] = b1[tid]; sb2[tid] = b2[tid]; }
    if (tid == 0) sb3[0] = b3[0];
    for (int idx = tid; idx < 64 * 16; idx += 256) {
        int e = idx >> 4, q = idx & 15;
        int n = base + e;
        float4 v = (n < NN) ? *(const float4*)(d_h + n * 64 + q * 4)
                            : make_float4(0.f, 0.f, 0.f, 0.f);
        *(float4*)(sfA + e * 68 + q * 4) = v;
    }
    __syncthreads();
    int et = tid & 15, jt = tid >> 4;
    {
        ull acc[4][4] = {};
        gemm_acc4<68, 68>(sfA, sW1t, 64, et, jt, acc);
        #pragma unroll
        for (int e = 0; e < 4; ++e) {
            F4U o;
            #pragma unroll
            for (int j = 0; j < 4; ++j)
                o.f[j] = silu_f(lane_sum(acc[e][j]) + sb1[jt * 4 + j]);
            *(float4*)(sfB + (et + 16 * e) * 68 + jt * 4) = o.v;
        }
    }
    __syncthreads();
    {
        ull acc[4][4] = {};
        gemm_acc4<68, 68>(sfB, sW2t, 64, et, jt, acc);
        #pragma unroll
        for (int e = 0; e < 4; ++e) {
            F4U o;
            #pragma unroll
            for (int j = 0; j < 4; ++j)
                o.f[j] = silu_f(lane_sum(acc[e][j]) + sb2[jt * 4 + j]);
            *(float4*)(sfA + (et + 16 * e) * 68 + jt * 4) = o.v;
        }
    }
    __syncthreads();
    if (tid < 64) {
        int n = base + tid;
        if (n < NN) {
            float s = sb3[0];
            #pragma unroll
            for (int q = 0; q < 16; ++q) {
                F4U t; t.v = *(const float4*)(sfA + tid * 68 + q * 4);
                #pragma unroll
                for (int c = 0; c < 4; ++c) s += t.f[c] * sW3[q * 4 + c];
            }
            out[n] = s;
        }
    }
}

// ---------------- launch ----------------
extern "C" void kernel_launch(void* const* d_in, const int* in_sizes, int n_in,
                              void* d_out, int out_size) {
    const float* h_in   = (const float*)d_in[0];
    const float* pos    = (const float*)d_in[1];
    const float* cell   = (const float*)d_in[2];
    const int*   esrc   = (const int*)d_in[3];
    const int*   edst   = (const int*)d_in[4];
    const float* emb_W1 = (const float*)d_in[5];
    const float* emb_b1 = (const float*)d_in[6];
    const float* emb_W2 = (const float*)d_in[7];
    const float* emb_b2 = (const float*)d_in[8];
    const float* msg_W1 = (const float*)d_in[9];
    const float* msg_b1 = (const float*)d_in[10];
    const float* bn_g   = (const float*)d_in[11];
    const float* bn_b   = (const float*)d_in[12];
    const float* msg_W2 = (const float*)d_in[13];
    const float* msg_b2 = (const float*)d_in[14];
    const float* upd_W1 = (const float*)d_in[15];
    const float* upd_b1 = (const float*)d_in[16];
    const float* upd_W2 = (const float*)d_in[17];
    const float* upd_b2 = (const float*)d_in[18];
    const float* upd_W3 = (const float*)d_in[19];
    const float* upd_b3 = (const float*)d_in[20];
    const float* pos_W1 = (const float*)d_in[21];
    const float* pos_b1 = (const float*)d_in[22];
    const float* pos_W2 = (const float*)d_in[23];
    const float* pos_b2 = (const float*)d_in[24];
    const float* en_W1  = (const float*)d_in[25];
    const float* en_b1  = (const float*)d_in[26];
    const float* en_W2  = (const float*)d_in[27];
    const float* en_b2  = (const float*)d_in[28];
    const float* en_W3  = (const float*)d_in[29];
    const float* en_b3  = (const float*)d_in[30];
    float* out = (float*)d_out;

    static int attr_done = 0;
    if (!attr_done) {
        cudaFuncSetAttribute(embed_kernel,  cudaFuncAttributeMaxDynamicSharedMemorySize, EM_SMEM);
        cudaFuncSetAttribute(pass1_wmma,    cudaFuncAttributeMaxDynamicSharedMemorySize, P1_SMEM);
        cudaFuncSetAttribute(pass2_wmma,    cudaFuncAttributeMaxDynamicSharedMemorySize, P2_SMEM);
        cudaFuncSetAttribute(node_kernel,   cudaFuncAttributeMaxDynamicSharedMemorySize, ND_SMEM);
        cudaFuncSetAttribute(energy_kernel, cudaFuncAttributeMaxDynamicSharedMemorySize, EN_SMEM);
        attr_done = 1;
    }

    const int P1_GRID = 148 * 2;
    const int P2_GRID = 148 * 2;
    const int ND_TILES = (NN + 63) / 64;
    const int ND_GRID = 148 * 2;

    init_kernel<<<(NN * F + 255) / 256, 256>>>(pos);
    count_kernel<<<(EE + 255) / 256, 256>>>(edst);
    inv_kernel<<<(NN + 255) / 256, 256>>>();
    wconv_kernel<<<(NL * F * 128 + 255) / 256, 256>>>(msg_W1);
    embed_kernel<<<313, 256, EM_SMEM>>>(h_in, emb_W1, emb_b1, emb_W2, emb_b2);

    for (int l = 0; l < NL; ++l) {
        pass1_wmma<<<P1_GRID, 256, P1_SMEM>>>(esrc, edst, cell,
                                              msg_W1 + l * (2 * F + 1) * F, msg_b1 + l * F, l);
        bnstats_kernel<<<256, 256>>>(l);
        prep_kernel<<<1, 1024>>>(bn_g + l * F, bn_b + l * F,
                                 msg_W2 + l * F * F, msg_b2 + l * F,
                                 pos_W1 + l * F * F, pos_b1 + l * F, l);
        pass2_wmma<<<P2_GRID, 256, P2_SMEM>>>(edst,
                                              pos_W2 + l * F * DIM, pos_b2 + l * DIM);
        node_kernel<<<ND_GRID, 256, ND_SMEM>>>(msg_W2 + l * F * F, msg_b2 + l * F,
                                               upd_W1 + l * 2 * F * F, upd_b1 + l * F,
                                               upd_W2 + l * F * F, upd_b2 + l * F,
                                               upd_W3 + l * F * F, upd_b3 + l * F, ND_TILES);
    }
    energy_kernel<<<313, 256, EN_SMEM>>>(en_W1, en_b1, en_W2, en_b2, en_W3, en_b3, out);
}

// round 12
// speedup vs baseline: 3.5800x; 1.0446x over previous
#include <cuda_runtime.h>
#include <cuda_bf16.h>
#include <mma.h>
#include <cstdint>

namespace wm = nvcuda::wmma;

#define NN 20000
#define EE 160000
#define FIN 9
#define F 64
#define NL 7
#define DIM 3
#define BN_EPS 1e-5f
#define NT_T128 1250

typedef unsigned long long ull;
union F4U { float4 v; ull u[2]; float f[4]; };

// ---------------- device scratch ----------------
__device__ float d_h[NN * F];
__device__ __nv_bfloat16 d_hhi[NN * F];
__device__ __nv_bfloat16 d_hlo[NN * F];
__device__ float d_pos[NN * DIM];
__device__ __nv_bfloat16 d_m1hi[EE * F];
__device__ __nv_bfloat16 d_m1lo[EE * F];
__device__ float d_dvec[EE * DIM];
__device__ float d_summ1[NN * F];
__device__ float d_aggpm[NN * DIM];
__device__ int   d_counts[NN];
__device__ float d_invc[NN];
__device__ float d_bnsum[NL * F];
__device__ float d_bnsumsq[NL * F];
__device__ __nv_bfloat16 d_w1hi[NL * F * 128];   // [l][j][k] (col-major KxN for wmma B)
__device__ __nv_bfloat16 d_w1lo[NL * F * 128];

__device__ __forceinline__ float silu_f(float x) { return x / (1.0f + expf(-x)); }

__device__ __forceinline__ ull ffma2(ull a, ull b, ull c) {
    ull d;
    asm("fma.rn.f32x2 %0, %1, %2, %3;" : "=l"(d) : "l"(a), "l"(b), "l"(c));
    return d;
}
__device__ __forceinline__ float lane_sum(ull a) {
    float lo = __uint_as_float((unsigned)(a & 0xffffffffull));
    float hi = __uint_as_float((unsigned)(a >> 32));
    return lo + hi;
}
__device__ __forceinline__ void red_add_v4(float* p, float a, float b, float c, float d) {
    asm volatile("red.global.add.v4.f32 [%0], {%1,%2,%3,%4};"
                 :: "l"(p), "f"(a), "f"(b), "f"(c), "f"(d) : "memory");
}
__device__ __forceinline__ unsigned pack_bf(__nv_bfloat16 a, __nv_bfloat16 b) {
    __nv_bfloat162 t(a, b); return *(unsigned*)&t;
}

// ---------------- FFMA2 GEMM core ----------------
template<int PF, int PW>
__device__ __forceinline__ void gemm_acc4(const float* __restrict__ sf,
                                          const float* __restrict__ sWt,
                                          int kmax, int et, int jt, ull acc[4][4]) {
    const float* fb = sf + et * PF;
    const float* wb = sWt + (jt * 4) * PW;
    #pragma unroll 2
    for (int k0 = 0; k0 < kmax; k0 += 4) {
        ull w[4][2];
        #pragma unroll
        for (int j = 0; j < 4; ++j) {
            F4U t; t.v = *(const float4*)(wb + j * PW + k0);
            w[j][0] = t.u[0]; w[j][1] = t.u[1];
        }
        #pragma unroll
        for (int e = 0; e < 4; ++e) {
            F4U t; t.v = *(const float4*)(fb + e * 16 * PF + k0);
            #pragma unroll
            for (int j = 0; j < 4; ++j) {
                acc[e][j] = ffma2(t.u[0], w[j][0], acc[e][j]);
                acc[e][j] = ffma2(t.u[1], w[j][1], acc[e][j]);
            }
        }
    }
}

// ---------------- init ----------------
__global__ void init_kernel(const float* __restrict__ pos_in) {
    int i = blockIdx.x * blockDim.x + threadIdx.x;
    if (i < NN * F) d_summ1[i] = 0.0f;
    if (i < NN * DIM) { d_aggpm[i] = 0.0f; d_pos[i] = pos_in[i]; }
    if (i < NN) d_counts[i] = 0;
    if (i < NL * F) { d_bnsum[i] = 0.0f; d_bnsumsq[i] = 0.0f; }
}
__global__ void count_kernel(const int* __restrict__ edge_dst) {
    int i = blockIdx.x * blockDim.x + threadIdx.x;
    if (i < EE) atomicAdd(&d_counts[edge_dst[i]], 1);
}
__global__ void inv_kernel() {
    int i = blockIdx.x * blockDim.x + threadIdx.x;
    if (i < NN) d_invc[i] = 1.0f / fmaxf((float)d_counts[i], 1.0f);
}
__global__ void wconv_kernel(const float* __restrict__ msg_W1) {
    int idx = blockIdx.x * blockDim.x + threadIdx.x;
    if (idx >= NL * F * 128) return;
    int l = idx >> 13, r = idx & 8191;
    int j = r >> 7, k = r & 127;
    float v = msg_W1[l * 8256 + k * 64 + j];
    __nv_bfloat16 h = __float2bfloat16(v);
    d_w1hi[idx] = h;
    d_w1lo[idx] = __float2bfloat16(v - __bfloat162float(h));
}

// ---------------- embedding (FFMA2) + h hi/lo emission ----------------
#define EM_SMEM ((64*12 + 64*12 + 64*68 + 64*68 + 128) * (int)sizeof(float))
__global__ void embed_kernel(const float* __restrict__ h_in,
                             const float* __restrict__ W1, const float* __restrict__ b1,
                             const float* __restrict__ W2, const float* __restrict__ b2) {
    extern __shared__ float sm[];
    float* sf   = sm;
    float* sW1t = sf + 64 * 12;
    float* sfB  = sW1t + 64 * 12;
    float* sW2t = sfB + 64 * 68;
    float* sb1  = sW2t + 64 * 68;
    float* sb2  = sb1 + 64;
    int tid = threadIdx.x;
    int base = blockIdx.x * 64;
    for (int idx = tid; idx < 64 * 12; idx += 256) {
        int j = idx / 12, k = idx - j * 12;
        sW1t[idx] = (k < FIN) ? W1[k * 64 + j] : 0.0f;
    }
    for (int idx = tid; idx < 64 * 64; idx += 256) {
        int k = idx >> 6, j = idx & 63;
        sW2t[j * 68 + k] = W2[idx];
    }
    if (tid < 64) { sb1[tid] = b1[tid]; sb2[tid] = b2[tid]; }
    for (int idx = tid; idx < 64 * 12; idx += 256) {
        int e = idx / 12, k = idx - e * 12;
        int n = base + e;
        sf[idx] = (k < FIN && n < NN) ? h_in[n * FIN + k] : 0.0f;
    }
    __syncthreads();
    int et = tid & 15, jt = tid >> 4;
    {
        ull acc[4][4] = {};
        gemm_acc4<12, 12>(sf, sW1t, 12, et, jt, acc);
        #pragma unroll
        for (int e = 0; e < 4; ++e) {
            F4U o;
            #pragma unroll
            for (int j = 0; j < 4; ++j)
                o.f[j] = silu_f(lane_sum(acc[e][j]) + sb1[jt * 4 + j]);
            *(float4*)(sfB + (et + 16 * e) * 68 + jt * 4) = o.v;
        }
    }
    __syncthreads();
    {
        ull acc[4][4] = {};
        gemm_acc4<68, 68>(sfB, sW2t, 64, et, jt, acc);
        #pragma unroll
        for (int e = 0; e < 4; ++e) {
            int n = base + et + 16 * e;
            if (n < NN) {
                F4U o;
                #pragma unroll
                for (int j = 0; j < 4; ++j)
                    o.f[j] = lane_sum(acc[e][j]) + sb2[jt * 4 + j];
                *(float4*)(d_h + n * 64 + jt * 4) = o.v;
                __nv_bfloat16 hb[4]; float lo[4];
                #pragma unroll
                for (int j = 0; j < 4; ++j) {
                    hb[j] = __float2bfloat16(o.f[j]);
                    lo[j] = o.f[j] - __bfloat162float(hb[j]);
                }
                uint2 H, L;
                H.x = pack_bf(hb[0], hb[1]); H.y = pack_bf(hb[2], hb[3]);
                L.x = pack_bf(__float2bfloat16(lo[0]), __float2bfloat16(lo[1]));
                L.y = pack_bf(__float2bfloat16(lo[2]), __float2bfloat16(lo[3]));
                *(uint2*)(d_hhi + n * 64 + jt * 4) = H;
                *(uint2*)(d_hlo + n * 64 + jt * 4) = L;
            }
        }
    }
}

// ---------------- pass1: wmma + fused BN stats ----------------
// bytes: Ahi 0 (34816) Alo 34816 Bhi 69632 (17408) Blo 87040 -> 104448
//        Acc reuses Ahi region; w129 104448 sb1 104704 sdist 104960 sdst 105472 ssrc 105984 -> 106496
#define P1_SMEM 106496
__global__ void __launch_bounds__(256, 2)
pass1_wmma(const int* __restrict__ esrc, const int* __restrict__ edst,
           const float* __restrict__ cell,
           const float* __restrict__ W1, const float* __restrict__ b1, int l) {
    extern __shared__ char smem[];
    __nv_bfloat16* sAhi = (__nv_bfloat16*)(smem);
    __nv_bfloat16* sAlo = (__nv_bfloat16*)(smem + 34816);
    __nv_bfloat16* sBhi = (__nv_bfloat16*)(smem + 69632);
    __nv_bfloat16* sBlo = (__nv_bfloat16*)(smem + 87040);
    float* sAcc  = (float*)(smem);
    float* w129  = (float*)(smem + 104448);
    float* sb1   = (float*)(smem + 104704);
    float* sdist = (float*)(smem + 104960);
    int*   sdst  = (int*)(smem + 105472);
    int*   ssrc  = (int*)(smem + 105984);
    int tid = threadIdx.x;
    for (int i = tid; i < 64 * 16; i += 256) {
        int j = i >> 4, c = i & 15;
        *(uint4*)(sBhi + j * 136 + c * 8) = ((const uint4*)(d_w1hi + l * 8192 + j * 128))[c];
        *(uint4*)(sBlo + j * 136 + c * 8) = ((const uint4*)(d_w1lo + l * 8192 + j * 128))[c];
    }
    if (tid < 64) { w129[tid] = W1[128 * 64 + tid]; sb1[tid] = b1[tid]; }
    int w = tid >> 5, rg = w >> 1, nh = w & 1;
    int cb = tid >> 5, el = tid & 31, j0 = cb * 8;   // epilogue mapping
    float lsum[8] = {0,0,0,0,0,0,0,0}, lsq[8] = {0,0,0,0,0,0,0,0};

    for (int t = blockIdx.x; t < NT_T128; t += gridDim.x) {
        int base = t * 128;
        __syncthreads();
        if (tid < 128) {
            int ge = base + tid;
            int dn = edst[ge], sn = esrc[ge];
            sdst[tid] = dn; ssrc[tid] = sn;
            float dv0 = d_pos[dn * 3 + 0] - d_pos[sn * 3 + 0] + cell[ge * 3 + 0];
            float dv1 = d_pos[dn * 3 + 1] - d_pos[sn * 3 + 1] + cell[ge * 3 + 1];
            float dv2 = d_pos[dn * 3 + 2] - d_pos[sn * 3 + 2] + cell[ge * 3 + 2];
            d_dvec[ge * 3 + 0] = dv0; d_dvec[ge * 3 + 1] = dv1; d_dvec[ge * 3 + 2] = dv2;
            sdist[tid] = dv0 + dv1 + dv2;
        }
        __syncthreads();
        for (int idx = tid; idx < 128 * 32; idx += 256) {
            int e = idx >> 5, q = idx & 31, c = q & 7;
            int n = (q & 8) ? ssrc[e] : sdst[e];
            const uint4* src = (q & 16) ? (const uint4*)(d_hlo + n * 64)
                                        : (const uint4*)(d_hhi + n * 64);
            __nv_bfloat16* dp = ((q & 16) ? sAlo : sAhi) + e * 136 + ((q & 8) ? 64 : 0) + c * 8;
            *(uint4*)dp = src[c];
        }
        __syncthreads();
        wm::fragment<wm::accumulator, 16, 16, 16, float> c00, c01, c10, c11;
        wm::fill_fragment(c00, 0.0f); wm::fill_fragment(c01, 0.0f);
        wm::fill_fragment(c10, 0.0f); wm::fill_fragment(c11, 0.0f);
        {
            const __nv_bfloat16* Ah = sAhi + rg * 32 * 136;
            const __nv_bfloat16* Al = sAlo + rg * 32 * 136;
            const __nv_bfloat16* B0h = sBhi + (nh * 32) * 136;
            const __nv_bfloat16* B1h = sBhi + (nh * 32 + 16) * 136;
            const __nv_bfloat16* B0l = sBlo + (nh * 32) * 136;
            const __nv_bfloat16* B1l = sBlo + (nh * 32 + 16) * 136;
            #pragma unroll
            for (int kt = 0; kt < 8; ++kt) {
                wm::fragment<wm::matrix_a, 16, 16, 16, __nv_bfloat16, wm::row_major> ah0, ah1, al0, al1;
                wm::load_matrix_sync(ah0, Ah + kt * 16, 136);
                wm::load_matrix_sync(ah1, Ah + 16 * 136 + kt * 16, 136);
                wm::load_matrix_sync(al0, Al + kt * 16, 136);
                wm::load_matrix_sync(al1, Al + 16 * 136 + kt * 16, 136);
                wm::fragment<wm::matrix_b, 16, 16, 16, __nv_bfloat16, wm::col_major> b;
                wm::load_matrix_sync(b, B0h + kt * 16, 136);
                wm::mma_sync(c00, ah0, b, c00);
                wm::mma_sync(c10, ah1, b, c10);
                wm::mma_sync(c00, al0, b, c00);
                wm::mma_sync(c10, al1, b, c10);
                wm::load_matrix_sync(b, B1h + kt * 16, 136);
                wm::mma_sync(c01, ah0, b, c01);
                wm::mma_sync(c11, ah1, b, c11);
                wm::mma_sync(c01, al0, b, c01);
                wm::mma_sync(c11, al1, b, c11);
                wm::load_matrix_sync(b, B0l + kt * 16, 136);
                wm::mma_sync(c00, ah0, b, c00);
                wm::mma_sync(c10, ah1, b, c10);
                wm::load_matrix_sync(b, B1l + kt * 16, 136);
                wm::mma_sync(c01, ah0, b, c01);
                wm::mma_sync(c11, ah1, b, c11);
            }
        }
        __syncthreads();
        wm::store_matrix_sync(sAcc + (rg * 32) * 68 + nh * 32, c00, 68, wm::mem_row_major);
        wm::store_matrix_sync(sAcc + (rg * 32) * 68 + nh * 32 + 16, c01, 68, wm::mem_row_major);
        wm::store_matrix_sync(sAcc + (rg * 32 + 16) * 68 + nh * 32, c10, 68, wm::mem_row_major);
        wm::store_matrix_sync(sAcc + (rg * 32 + 16) * 68 + nh * 32 + 16, c11, 68, wm::mem_row_major);
        __syncthreads();
        // epilogue: thread owns fixed 8-col block j0, 4 edges
        #pragma unroll
        for (int i = 0; i < 4; ++i) {
            int e = el + 32 * i;
            int ge = base + e;
            int dn = sdst[e];
            float dist = sdist[e];
            float mv[8];
            __nv_bfloat16 hb[8], lb[8];
            #pragma unroll
            for (int jj = 0; jj < 8; ++jj) {
                int j = j0 + jj;
                float v = sAcc[e * 68 + j] + dist * w129[j] + sb1[j];
                v = silu_f(v);
                mv[jj] = v;
                lsum[jj] += v; lsq[jj] += v * v;
                hb[jj] = __float2bfloat16(v);
                lb[jj] = __float2bfloat16(v - __bfloat162float(hb[jj]));
            }
            uint4 H, L;
            H.x = pack_bf(hb[0], hb[1]); H.y = pack_bf(hb[2], hb[3]);
            H.z = pack_bf(hb[4], hb[5]); H.w = pack_bf(hb[6], hb[7]);
            L.x = pack_bf(lb[0], lb[1]); L.y = pack_bf(lb[2], lb[3]);
            L.z = pack_bf(lb[4], lb[5]); L.w = pack_bf(lb[6], lb[7]);
            ((uint4*)(d_m1hi + (size_t)ge * 64))[cb] = H;
            ((uint4*)(d_m1lo + (size_t)ge * 64))[cb] = L;
            red_add_v4(d_summ1 + dn * 64 + j0,     mv[0], mv[1], mv[2], mv[3]);
            red_add_v4(d_summ1 + dn * 64 + j0 + 4, mv[4], mv[5], mv[6], mv[7]);
        }
    }
    // warp reduce (all lanes in warp share cb) then atomics
    #pragma unroll
    for (int jj = 0; jj < 8; ++jj) {
        #pragma unroll
        for (int o = 1; o < 32; o <<= 1) {
            lsum[jj] += __shfl_xor_sync(0xffffffffu, lsum[jj], o);
            lsq[jj]  += __shfl_xor_sync(0xffffffffu, lsq[jj], o);
        }
    }
    if (el == 0) {
        #pragma unroll
        for (int jj = 0; jj < 8; ++jj) {
            atomicAdd(&d_bnsum[l * 64 + j0 + jj], lsum[jj]);
            atomicAdd(&d_bnsumsq[l * 64 + j0 + jj], lsq[jj]);
        }
    }
}

// ---------------- pass2: wmma, BN prep fused in prologue ----------------
// bytes: Ahi 0 (18432) Alo 18432 Bhi 36864 (9216) Blo 46080 -> 55296
//        Acc reuses Ahi+Alo; sbc 55296 spW2 55552 spb2 56320 sdv 56336 sdst 57872
//        sA 58384 sB 58640 sv 58896 -> 59152
#define P2_SMEM 59152
__global__ void __launch_bounds__(256, 2)
pass2_wmma(const int* __restrict__ edst,
           const float* __restrict__ gamma, const float* __restrict__ beta,
           const float* __restrict__ W2, const float* __restrict__ b2,
           const float* __restrict__ pW1, const float* __restrict__ pb1,
           const float* __restrict__ pW2, const float* __restrict__ pb2, int l) {
    extern __shared__ char smem[];
    __nv_bfloat16* sAhi = (__nv_bfloat16*)(smem);
    __nv_bfloat16* sAlo = (__nv_bfloat16*)(smem + 18432);
    __nv_bfloat16* sBhi = (__nv_bfloat16*)(smem + 36864);
    __nv_bfloat16* sBlo = (__nv_bfloat16*)(smem + 46080);
    float* sAcc = (float*)(smem);
    float* sW2f = (float*)(smem);            // prologue scratch (16 KB)
    float* spW1f = (float*)(smem + 18432);   // prologue scratch (16 KB)
    float* sbc  = (float*)(smem + 55296);
    float* spW2 = (float*)(smem + 55552);
    float* spb2 = (float*)(smem + 56320);
    float* sdv  = (float*)(smem + 56336);
    int*   sdst = (int*)(smem + 57872);
    float* sA   = (float*)(smem + 58384);
    float* sB   = (float*)(smem + 58640);
    float* sv   = (float*)(smem + 58896);
    int tid = threadIdx.x;
    // ---- fused prep: A,B, bc, Wc(bf16 hi/lo) ----
    for (int idx = tid; idx < 4096; idx += 256) {
        sW2f[idx] = W2[idx];
        spW1f[idx] = pW1[idx];
    }
    for (int i = tid; i < 192; i += 256) spW2[i] = pW2[i];
    if (tid < 3) spb2[tid] = pb2[tid];
    if (tid < 64) {
        float mu  = d_bnsum[l * 64 + tid]   * (1.0f / (float)EE);
        float var = d_bnsumsq[l * 64 + tid] * (1.0f / (float)EE) - mu * mu;
        float inv = rsqrtf(var + BN_EPS);
        float A = gamma[tid] * inv;
        sA[tid] = A;
        sB[tid] = beta[tid] - mu * A;
    }
    __syncthreads();
    if (tid < 64) {
        float acc = b2[tid];
        #pragma unroll 8
        for (int k = 0; k < 64; ++k) acc += sB[k] * sW2f[k * 64 + tid];
        sv[tid] = acc;
    }
    __syncthreads();
    if (tid < 64) {
        float acc = pb1[tid];
        #pragma unroll 8
        for (int q = 0; q < 64; ++q) acc += sv[q] * spW1f[q * 64 + tid];
        sbc[tid] = acc;
    }
    for (int idx = tid; idx < 4096; idx += 256) {
        int k = idx >> 6, j = idx & 63;
        float acc = 0.0f;
        #pragma unroll 8
        for (int q = 0; q < 64; ++q) acc += sW2f[k * 64 + q] * spW1f[q * 64 + j];
        float v = sA[k] * acc;
        __nv_bfloat16 h = __float2bfloat16(v);
        sBhi[j * 72 + k] = h;
        sBlo[j * 72 + k] = __float2bfloat16(v - __bfloat162float(h));
    }
    int w = tid >> 5, rg = w >> 1, nh = w & 1;

    for (int t = blockIdx.x; t < NT_T128; t += gridDim.x) {
        int base = t * 128;
        __syncthreads();
        if (tid < 128) sdst[tid] = edst[base + tid];
        for (int i = tid; i < 384; i += 256) sdv[i] = d_dvec[base * 3 + i];
        for (int idx = tid; idx < 128 * 16; idx += 256) {
            int e = idx >> 4, q = idx & 15, c = q & 7;
            const uint4* src = (q & 8) ? (const uint4*)(d_m1lo + (size_t)(base + e) * 64)
                                       : (const uint4*)(d_m1hi + (size_t)(base + e) * 64);
            __nv_bfloat16* dp = ((q & 8) ? sAlo : sAhi) + e * 72 + c * 8;
            *(uint4*)dp = src[c];
        }
        __syncthreads();
        wm::fragment<wm::accumulator, 16, 16, 16, float> c00, c01, c10, c11;
        wm::fill_fragment(c00, 0.0f); wm::fill_fragment(c01, 0.0f);
        wm::fill_fragment(c10, 0.0f); wm::fill_fragment(c11, 0.0f);
        {
            const __nv_bfloat16* Ah = sAhi + rg * 32 * 72;
            const __nv_bfloat16* Al = sAlo + rg * 32 * 72;
            const __nv_bfloat16* B0h = sBhi + (nh * 32) * 72;
            const __nv_bfloat16* B1h = sBhi + (nh * 32 + 16) * 72;
            const __nv_bfloat16* B0l = sBlo + (nh * 32) * 72;
            const __nv_bfloat16* B1l = sBlo + (nh * 32 + 16) * 72;
            #pragma unroll
            for (int kt = 0; kt < 4; ++kt) {
                wm::fragment<wm::matrix_a, 16, 16, 16, __nv_bfloat16, wm::row_major> ah0, ah1, al0, al1;
                wm::load_matrix_sync(ah0, Ah + kt * 16, 72);
                wm::load_matrix_sync(ah1, Ah + 16 * 72 + kt * 16, 72);
                wm::load_matrix_sync(al0, Al + kt * 16, 72);
                wm::load_matrix_sync(al1, Al + 16 * 72 + kt * 16, 72);
                wm::fragment<wm::matrix_b, 16, 16, 16, __nv_bfloat16, wm::col_major> b;
                wm::load_matrix_sync(b, B0h + kt * 16, 72);
                wm::mma_sync(c00, ah0, b, c00);
                wm::mma_sync(c10, ah1, b, c10);
                wm::mma_sync(c00, al0, b, c00);
                wm::mma_sync(c10, al1, b, c10);
                wm::load_matrix_sync(b, B1h + kt * 16, 72);
                wm::mma_sync(c01, ah0, b, c01);
                wm::mma_sync(c11, ah1, b, c11);
                wm::mma_sync(c01, al0, b, c01);
                wm::mma_sync(c11, al1, b, c11);
                wm::load_matrix_sync(b, B0l + kt * 16, 72);
                wm::mma_sync(c00, ah0, b, c00);
                wm::mma_sync(c10, ah1, b, c10);
                wm::load_matrix_sync(b, B1l + kt * 16, 72);
                wm::mma_sync(c01, ah0, b, c01);
                wm::mma_sync(c11, ah1, b, c11);
            }
        }
        __syncthreads();
        wm::store_matrix_sync(sAcc + (rg * 32) * 68 + nh * 32, c00, 68, wm::mem_row_major);
        wm::store_matrix_sync(sAcc + (rg * 32) * 68 + nh * 32 + 16, c01, 68, wm::mem_row_major);
        wm::store_matrix_sync(sAcc + (rg * 32 + 16) * 68 + nh * 32, c10, 68, wm::mem_row_major);
        wm::store_matrix_sync(sAcc + (rg * 32 + 16) * 68 + nh * 32 + 16, c11, 68, wm::mem_row_major);
        __syncthreads();
        if (tid < 128) {
            float s0 = spb2[0], s1 = spb2[1], s2 = spb2[2];
            #pragma unroll
            for (int q = 0; q < 16; ++q) {
                F4U tt; tt.v = *(const float4*)(sAcc + tid * 68 + q * 4);
                #pragma unroll
                for (int c = 0; c < 4; ++c) {
                    int j = q * 4 + c;
                    float v = silu_f(tt.f[c] + sbc[j]);
                    s0 += v * spW2[j * 3 + 0];
                    s1 += v * spW2[j * 3 + 1];
                    s2 += v * spW2[j * 3 + 2];
                }
            }
            int dn = sdst[tid];
            atomicAdd(&d_aggpm[dn * 3 + 0], sdv[tid * 3 + 0] * s0);
            atomicAdd(&d_aggpm[dn * 3 + 1], sdv[tid * 3 + 1] * s1);
            atomicAdd(&d_aggpm[dn * 3 + 2], sdv[tid * 3 + 2] * s2);
        }
    }
}

// ---------------- node (FFMA2, persistent) + h hi/lo emission ----------------
#define ND_SMEM ((64*132 + 64*68*5 + 192 + 256) * (int)sizeof(float))
__global__ void __launch_bounds__(256, 2)
node_kernel(const float* __restrict__ mW2, const float* __restrict__ mb2,
            const float* __restrict__ gamma, const float* __restrict__ beta,
            const float* __restrict__ uW1, const float* __restrict__ ub1,
            const float* __restrict__ uW2, const float* __restrict__ ub2,
            const float* __restrict__ uW3, const float* __restrict__ ub3,
            int ntiles, int l) {
    extern __shared__ float sm[];
    float* sfA  = sm;                    // 64*132
    float* sfB  = sfA + 64 * 132;        // 64*68
    float* sWm  = sfB + 64 * 68;
    float* sW1a = sWm + 64 * 68;
    float* sW2t = sW1a + 64 * 68;
    float* sW3t = sW2t + 64 * 68;
    float* sb1  = sW3t + 64 * 68;
    float* sb2  = sb1 + 64;
    float* sb3  = sb2 + 64;
    float* sAm  = sb3 + 64;
    float* sBm  = sAm + 64;
    float* sb2m = sBm + 64;
    float* sfnz = sb2m + 64;
    int tid = threadIdx.x;
    for (int idx = tid; idx < 64 * 64; idx += 256) {
        int k = idx >> 6, j = idx & 63;
        sWm[j * 68 + k]  = mW2[idx];
        sW1a[j * 68 + k] = uW1[idx];
        sW2t[j * 68 + k] = uW2[idx];
        sW3t[j * 68 + k] = uW3[idx];
    }
    if (tid < 64) {
        sb1[tid] = ub1[tid]; sb2[tid] = ub2[tid]; sb3[tid] = ub3[tid];
        float mu  = d_bnsum[l * 64 + tid]   * (1.0f / (float)EE);
        float var = d_bnsumsq[l * 64 + tid] * (1.0f / (float)EE) - mu * mu;
        float inv = rsqrtf(var + BN_EPS);
        float A = gamma[tid] * inv;
        sAm[tid] = A;
        sBm[tid] = beta[tid] - mu * A;
        sb2m[tid] = mb2[tid];
    }
    int et = tid & 15, jt = tid >> 4;

    for (int t = blockIdx.x; t < ntiles; t += gridDim.x) {
        int base = t * 64;
        __syncthreads();
        for (int idx = tid; idx < 64 * 16; idx += 256) {
            int e = idx >> 4, q = idx & 15;
            int n = base + e;
            float4 hv = make_float4(0.f, 0.f, 0.f, 0.f);
            F4U tt; tt.v = make_float4(0.f, 0.f, 0.f, 0.f);
            if (n < NN) {
                hv = *(const float4*)(d_h + n * 64 + q * 4);
                tt.v = *(const float4*)(d_summ1 + n * 64 + q * 4);
                *(float4*)(d_summ1 + n * 64 + q * 4) = make_float4(0.f, 0.f, 0.f, 0.f);
                float inv = d_invc[n];
                float f = (d_counts[n] > 0) ? 1.0f : 0.0f;
                #pragma unroll
                for (int c = 0; c < 4; ++c)
                    tt.f[c] = sAm[q * 4 + c] * (tt.f[c] * inv) + f * sBm[q * 4 + c];
            }
            *(float4*)(sfA + e * 132 + q * 4) = hv;
            *(float4*)(sfB + e * 68 + q * 4) = tt.v;
        }
        if (tid < 64) {
            int n = base + tid;
            float f = 0.0f;
            if (n < NN) {
                f = (d_counts[n] > 0) ? 1.0f : 0.0f;
                float inv = d_invc[n];
                #pragma unroll
                for (int c = 0; c < 3; ++c) {
                    d_pos[n * 3 + c] += d_aggpm[n * 3 + c] * inv;
                    d_aggpm[n * 3 + c] = 0.0f;
                }
            }
            sfnz[tid] = f;
        }
        __syncthreads();
        {   // agg = mnorm @ mW2 + f*mb2 -> sfA[:,64:128]
            ull a0[4][4] = {};
            gemm_acc4<68, 68>(sfB, sWm, 64, et, jt, a0);
            #pragma unroll
            for (int e = 0; e < 4; ++e) {
                int er = et + 16 * e;
                float f = sfnz[er];
                F4U o;
                #pragma unroll
                for (int j = 0; j < 4; ++j)
                    o.f[j] = lane_sum(a0[e][j]) + f * sb2m[jt * 4 + j];
                *(float4*)(sfA + er * 132 + 64 + jt * 4) = o.v;
            }
        }
        __syncthreads();
        ull a1[4][4] = {};
        gemm_acc4<132, 68>(sfA, sW1a, 64, et, jt, a1);
        {   // uW1 rows 64..127 direct from gmem (L2-hot broadcast)
            const float* fb = sfA + et * 132 + 64;
            #pragma unroll 2
            for (int k0 = 0; k0 < 64; k0 += 4) {
                ull w[4][2];
                #pragma unroll
                for (int j = 0; j < 4; ++j) {
                    F4U tw;
                    tw.f[0] = uW1[(64 + k0 + 0) * 64 + jt * 4 + j];
                    tw.f[1] = uW1[(64 + k0 + 1) * 64 + jt * 4 + j];
                    tw.f[2] = uW1[(64 + k0 + 2) * 64 + jt * 4 + j];
                    tw.f[3] = uW1[(64 + k0 + 3) * 64 + jt * 4 + j];
                    w[j][0] = tw.u[0]; w[j][1] = tw.u[1];
                }
                #pragma unroll
                for (int e = 0; e < 4; ++e) {
                    F4U tf; tf.v = *(const float4*)(fb + e * 16 * 132 + k0);
                    #pragma unroll
                    for (int j = 0; j < 4; ++j) {
                        a1[e][j] = ffma2(tf.u[0], w[j][0], a1[e][j]);
                        a1[e][j] = ffma2(tf.u[1], w[j][1], a1[e][j]);
                    }
                }
            }
        }
        __syncthreads();
        #pragma unroll
        for (int e = 0; e < 4; ++e) {
            F4U o;
            #pragma unroll
            for (int j = 0; j < 4; ++j)
                o.f[j] = silu_f(lane_sum(a1[e][j]) + sb1[jt * 4 + j]);
            *(float4*)(sfB + (et + 16 * e) * 68 + jt * 4) = o.v;
        }
        __syncthreads();
        {
            ull a2[4][4] = {};
            gemm_acc4<68, 68>(sfB, sW2t, 64, et, jt, a2);
            #pragma unroll
            for (int e = 0; e < 4; ++e) {
                F4U o;
                #pragma unroll
                for (int j = 0; j < 4; ++j)
                    o.f[j] = silu_f(lane_sum(a2[e][j]) + sb2[jt * 4 + j]);
                *(float4*)(sfA + (et + 16 * e) * 132 + jt * 4) = o.v;
            }
        }
        __syncthreads();
        {
            ull a3[4][4] = {};
            gemm_acc4<132, 68>(sfA, sW3t, 64, et, jt, a3);
            #pragma unroll
            for (int e = 0; e < 4; ++e) {
                int n = base + et + 16 * e;
                if (n < NN) {
                    F4U h; h.v = *(const float4*)(d_h + n * 64 + jt * 4);
                    F4U o;
                    #pragma unroll
                    for (int j = 0; j < 4; ++j)
                        o.f[j] = h.f[j] + lane_sum(a3[e][j]) + sb3[jt * 4 + j];
                    *(float4*)(d_h + n * 64 + jt * 4) = o.v;
                    __nv_bfloat16 hb[4]; float lo[4];
                    #pragma unroll
                    for (int j = 0; j < 4; ++j) {
                        hb[j] = __float2bfloat16(o.f[j]);
                        lo[j] = o.f[j] - __bfloat162float(hb[j]);
                    }
                    uint2 H, L;
                    H.x = pack_bf(hb[0], hb[1]); H.y = pack_bf(hb[2], hb[3]);
                    L.x = pack_bf(__float2bfloat16(lo[0]), __float2bfloat16(lo[1]));
                    L.y = pack_bf(__float2bfloat16(lo[2]), __float2bfloat16(lo[3]));
                    *(uint2*)(d_hhi + n * 64 + jt * 4) = H;
                    *(uint2*)(d_hlo + n * 64 + jt * 4) = L;
                }
            }
        }
    }
}

// ---------------- energy MLP ----------------
#define EN_SMEM ((64*68*2 + 64*68*2 + 64 + 64 + 64 + 4) * (int)sizeof(float))
__global__ void energy_kernel(const float* __restrict__ W1, const float* __restrict__ b1,
                              const float* __restrict__ W2, const float* __restrict__ b2,
                              const float* __restrict__ W3, const float* __restrict__ b3,
                              float* __restrict__ out) {
    extern __shared__ float sm[];
    float* sfA  = sm;
    float* sfB  = sfA + 64 * 68;
    float* sW1t = sfB + 64 * 68;
    float* sW2t = sW1t + 64 * 68;
    float* sW3  = sW2t + 64 * 68;
    float* sb1  = sW3 + 64;
    float* sb2  = sb1 + 64;
    float* sb3  = sb2 + 64;
    int tid = threadIdx.x;
    int base = blockIdx.x * 64;
    for (int idx = tid; idx < 64 * 64; idx += 256) {
        int k = idx >> 6, j = idx & 63;
        sW1t[j * 68 + k] = W1[idx];
        sW2t[j * 68 + k] = W2[idx];
    }
    if (tid < 64) { sW3[tid] = W3[tid]; sb1[tid] = b1[tid]; sb2[tid] = b2[tid]; }
    if (tid == 0) sb3[0] = b3[0];
    for (int idx = tid; idx < 64 * 16; idx += 256) {
        int e = idx >> 4, q = idx & 15;
        int n = base + e;
        float4 v = (n < NN) ? *(const float4*)(d_h + n * 64 + q * 4)
                            : make_float4(0.f, 0.f, 0.f, 0.f);
        *(float4*)(sfA + e * 68 + q * 4) = v;
    }
    __syncthreads();
    int et = tid & 15, jt = tid >> 4;
    {
        ull acc[4][4] = {};
        gemm_acc4<68, 68>(sfA, sW1t, 64, et, jt, acc);
        #pragma unroll
        for (int e = 0; e < 4; ++e) {
            F4U o;
            #pragma unroll
            for (int j = 0; j < 4; ++j)
                o.f[j] = silu_f(lane_sum(acc[e][j]) + sb1[jt * 4 + j]);
            *(float4*)(sfB + (et + 16 * e) * 68 + jt * 4) = o.v;
        }
    }
    __syncthreads();
    {
        ull acc[4][4] = {};
        gemm_acc4<68, 68>(sfB, sW2t, 64, et, jt, acc);
        #pragma unroll
        for (int e = 0; e < 4; ++e) {
            F4U o;
            #pragma unroll
            for (int j = 0; j < 4; ++j)
                o.f[j] = silu_f(lane_sum(acc[e][j]) + sb2[jt * 4 + j]);
            *(float4*)(sfA + (et + 16 * e) * 68 + jt * 4) = o.v;
        }
    }
    __syncthreads();
    if (tid < 64) {
        int n = base + tid;
        if (n < NN) {
            float s = sb3[0];
            #pragma unroll
            for (int q = 0; q < 16; ++q) {
                F4U t; t.v = *(const float4*)(sfA + tid * 68 + q * 4);
                #pragma unroll
                for (int c = 0; c < 4; ++c) s += t.f[c] * sW3[q * 4 + c];
            }
            out[n] = s;
        }
    }
}

// ---------------- launch ----------------
extern "C" void kernel_launch(void* const* d_in, const int* in_sizes, int n_in,
                              void* d_out, int out_size) {
    const float* h_in   = (const float*)d_in[0];
    const float* pos    = (const float*)d_in[1];
    const float* cell   = (const float*)d_in[2];
    const int*   esrc   = (const int*)d_in[3];
    const int*   edst   = (const int*)d_in[4];
    const float* emb_W1 = (const float*)d_in[5];
    const float* emb_b1 = (const float*)d_in[6];
    const float* emb_W2 = (const float*)d_in[7];
    const float* emb_b2 = (const float*)d_in[8];
    const float* msg_W1 = (const float*)d_in[9];
    const float* msg_b1 = (const float*)d_in[10];
    const float* bn_g   = (const float*)d_in[11];
    const float* bn_b   = (const float*)d_in[12];
    const float* msg_W2 = (const float*)d_in[13];
    const float* msg_b2 = (const float*)d_in[14];
    const float* upd_W1 = (const float*)d_in[15];
    const float* upd_b1 = (const float*)d_in[16];
    const float* upd_W2 = (const float*)d_in[17];
    const float* upd_b2 = (const float*)d_in[18];
    const float* upd_W3 = (const float*)d_in[19];
    const float* upd_b3 = (const float*)d_in[20];
    const float* pos_W1 = (const float*)d_in[21];
    const float* pos_b1 = (const float*)d_in[22];
    const float* pos_W2 = (const float*)d_in[23];
    const float* pos_b2 = (const float*)d_in[24];
    const float* en_W1  = (const float*)d_in[25];
    const float* en_b1  = (const float*)d_in[26];
    const float* en_W2  = (const float*)d_in[27];
    const float* en_b2  = (const float*)d_in[28];
    const float* en_W3  = (const float*)d_in[29];
    const float* en_b3  = (const float*)d_in[30];
    float* out = (float*)d_out;

    static int attr_done = 0;
    if (!attr_done) {
        cudaFuncSetAttribute(embed_kernel,  cudaFuncAttributeMaxDynamicSharedMemorySize, EM_SMEM);
        cudaFuncSetAttribute(pass1_wmma,    cudaFuncAttributeMaxDynamicSharedMemorySize, P1_SMEM);
        cudaFuncSetAttribute(pass2_wmma,    cudaFuncAttributeMaxDynamicSharedMemorySize, P2_SMEM);
        cudaFuncSetAttribute(node_kernel,   cudaFuncAttributeMaxDynamicSharedMemorySize, ND_SMEM);
        cudaFuncSetAttribute(energy_kernel, cudaFuncAttributeMaxDynamicSharedMemorySize, EN_SMEM);
        attr_done = 1;
    }

    const int P1_GRID = 148 * 2;
    const int P2_GRID = 148 * 2;
    const int ND_TILES = (NN + 63) / 64;
    const int ND_GRID = 148 * 2;

    init_kernel<<<(NN * F + 255) / 256, 256>>>(pos);
    count_kernel<<<(EE + 255) / 256, 256>>>(edst);
    inv_kernel<<<(NN + 255) / 256, 256>>>();
    wconv_kernel<<<(NL * F * 128 + 255) / 256, 256>>>(msg_W1);
    embed_kernel<<<313, 256, EM_SMEM>>>(h_in, emb_W1, emb_b1, emb_W2, emb_b2);

    for (int l = 0; l < NL; ++l) {
        pass1_wmma<<<P1_GRID, 256, P1_SMEM>>>(esrc, edst, cell,
                                              msg_W1 + l * (2 * F + 1) * F, msg_b1 + l * F, l);
        pass2_wmma<<<P2_GRID, 256, P2_SMEM>>>(edst,
                                              bn_g + l * F, bn_b + l * F,
                                              msg_W2 + l * F * F, msg_b2 + l * F,
                                              pos_W1 + l * F * F, pos_b1 + l * F,
                                              pos_W2 + l * F * DIM, pos_b2 + l * DIM, l);
        node_kernel<<<ND_GRID, 256, ND_SMEM>>>(msg_W2 + l * F * F, msg_b2 + l * F,
                                               bn_g + l * F, bn_b + l * F,
                                               upd_W1 + l * 2 * F * F, upd_b1 + l * F,
                                               upd_W2 + l * F * F, upd_b2 + l * F,
                                               upd_W3 + l * F * F, upd_b3 + l * F,
                                               ND_TILES, l);
    }
    energy_kernel<<<313, 256, EN_SMEM>>>(en_W1, en_b1, en_W2, en_b2, en_W3, en_b3, out);
}

// round 13
// speedup vs baseline: 3.5818x; 1.0005x over previous
#include <cuda_runtime.h>
#include <cuda_bf16.h>
#include <mma.h>
#include <cstdint>

namespace wm = nvcuda::wmma;

#define NN 20000
#define EE 160000
#define FIN 9
#define F 64
#define NL 7
#define DIM 3
#define BN_EPS 1e-5f
#define NT_T128 1250

typedef unsigned long long ull;
union F4U { float4 v; ull u[2]; float f[4]; };

// ---------------- device scratch ----------------
__device__ float d_h[NN * F];
__device__ __nv_bfloat16 d_hhi[NN * F];
__device__ __nv_bfloat16 d_hlo[NN * F];
__device__ float d_pos[NN * DIM];
__device__ __nv_bfloat16 d_m1hi[EE * F];
__device__ __nv_bfloat16 d_m1lo[EE * F];
__device__ float d_dvec[EE * DIM];
__device__ float d_summ1[NN * F];
__device__ float d_aggpm[NN * DIM];
__device__ int   d_counts[NN];
__device__ float d_invc[NN];
__device__ float d_bnsum[NL * F];
__device__ float d_bnsumsq[NL * F];
__device__ __nv_bfloat16 d_w1hi[NL * F * 128];   // [l][j][k] (col-major KxN for wmma B)
__device__ __nv_bfloat16 d_w1lo[NL * F * 128];

__device__ __forceinline__ float silu_f(float x) { return x / (1.0f + expf(-x)); }

__device__ __forceinline__ ull ffma2(ull a, ull b, ull c) {
    ull d;
    asm("fma.rn.f32x2 %0, %1, %2, %3;" : "=l"(d) : "l"(a), "l"(b), "l"(c));
    return d;
}
__device__ __forceinline__ float lane_sum(ull a) {
    float lo = __uint_as_float((unsigned)(a & 0xffffffffull));
    float hi = __uint_as_float((unsigned)(a >> 32));
    return lo + hi;
}
__device__ __forceinline__ void red_add_v4(float* p, float a, float b, float c, float d) {
    asm volatile("red.global.add.v4.f32 [%0], {%1,%2,%3,%4};"
                 :: "l"(p), "f"(a), "f"(b), "f"(c), "f"(d) : "memory");
}
__device__ __forceinline__ unsigned pack_bf(__nv_bfloat16 a, __nv_bfloat16 b) {
    __nv_bfloat162 t(a, b); return *(unsigned*)&t;
}

// ---------------- FFMA2 GEMM core ----------------
template<int PF, int PW>
__device__ __forceinline__ void gemm_acc4(const float* __restrict__ sf,
                                          const float* __restrict__ sWt,
                                          int kmax, int et, int jt, ull acc[4][4]) {
    const float* fb = sf + et * PF;
    const float* wb = sWt + (jt * 4) * PW;
    #pragma unroll 2
    for (int k0 = 0; k0 < kmax; k0 += 4) {
        ull w[4][2];
        #pragma unroll
        for (int j = 0; j < 4; ++j) {
            F4U t; t.v = *(const float4*)(wb + j * PW + k0);
            w[j][0] = t.u[0]; w[j][1] = t.u[1];
        }
        #pragma unroll
        for (int e = 0; e < 4; ++e) {
            F4U t; t.v = *(const float4*)(fb + e * 16 * PF + k0);
            #pragma unroll
            for (int j = 0; j < 4; ++j) {
                acc[e][j] = ffma2(t.u[0], w[j][0], acc[e][j]);
                acc[e][j] = ffma2(t.u[1], w[j][1], acc[e][j]);
            }
        }
    }
}

// ---------------- init ----------------
__global__ void init_kernel(const float* __restrict__ pos_in) {
    int i = blockIdx.x * blockDim.x + threadIdx.x;
    if (i < NN * F) d_summ1[i] = 0.0f;
    if (i < NN * DIM) { d_aggpm[i] = 0.0f; d_pos[i] = pos_in[i]; }
    if (i < NN) d_counts[i] = 0;
    if (i < NL * F) { d_bnsum[i] = 0.0f; d_bnsumsq[i] = 0.0f; }
}
__global__ void count_kernel(const int* __restrict__ edge_dst) {
    int i = blockIdx.x * blockDim.x + threadIdx.x;
    if (i < EE) atomicAdd(&d_counts[edge_dst[i]], 1);
}
__global__ void inv_kernel() {
    int i = blockIdx.x * blockDim.x + threadIdx.x;
    if (i < NN) d_invc[i] = 1.0f / fmaxf((float)d_counts[i], 1.0f);
}
__global__ void wconv_kernel(const float* __restrict__ msg_W1) {
    int idx = blockIdx.x * blockDim.x + threadIdx.x;
    if (idx >= NL * F * 128) return;
    int l = idx >> 13, r = idx & 8191;
    int j = r >> 7, k = r & 127;
    float v = msg_W1[l * 8256 + k * 64 + j];
    __nv_bfloat16 h = __float2bfloat16(v);
    d_w1hi[idx] = h;
    d_w1lo[idx] = __float2bfloat16(v - __bfloat162float(h));
}

// ---------------- embedding (FFMA2) + h hi/lo emission ----------------
#define EM_SMEM ((64*12 + 64*12 + 64*68 + 64*68 + 128) * (int)sizeof(float))
__global__ void embed_kernel(const float* __restrict__ h_in,
                             const float* __restrict__ W1, const float* __restrict__ b1,
                             const float* __restrict__ W2, const float* __restrict__ b2) {
    extern __shared__ float sm[];
    float* sf   = sm;
    float* sW1t = sf + 64 * 12;
    float* sfB  = sW1t + 64 * 12;
    float* sW2t = sfB + 64 * 68;
    float* sb1  = sW2t + 64 * 68;
    float* sb2  = sb1 + 64;
    int tid = threadIdx.x;
    int base = blockIdx.x * 64;
    for (int idx = tid; idx < 64 * 12; idx += 256) {
        int j = idx / 12, k = idx - j * 12;
        sW1t[idx] = (k < FIN) ? W1[k * 64 + j] : 0.0f;
    }
    for (int idx = tid; idx < 64 * 64; idx += 256) {
        int k = idx >> 6, j = idx & 63;
        sW2t[j * 68 + k] = W2[idx];
    }
    if (tid < 64) { sb1[tid] = b1[tid]; sb2[tid] = b2[tid]; }
    for (int idx = tid; idx < 64 * 12; idx += 256) {
        int e = idx / 12, k = idx - e * 12;
        int n = base + e;
        sf[idx] = (k < FIN && n < NN) ? h_in[n * FIN + k] : 0.0f;
    }
    __syncthreads();
    int et = tid & 15, jt = tid >> 4;
    {
        ull acc[4][4] = {};
        gemm_acc4<12, 12>(sf, sW1t, 12, et, jt, acc);
        #pragma unroll
        for (int e = 0; e < 4; ++e) {
            F4U o;
            #pragma unroll
            for (int j = 0; j < 4; ++j)
                o.f[j] = silu_f(lane_sum(acc[e][j]) + sb1[jt * 4 + j]);
            *(float4*)(sfB + (et + 16 * e) * 68 + jt * 4) = o.v;
        }
    }
    __syncthreads();
    {
        ull acc[4][4] = {};
        gemm_acc4<68, 68>(sfB, sW2t, 64, et, jt, acc);
        #pragma unroll
        for (int e = 0; e < 4; ++e) {
            int n = base + et + 16 * e;
            if (n < NN) {
                F4U o;
                #pragma unroll
                for (int j = 0; j < 4; ++j)
                    o.f[j] = lane_sum(acc[e][j]) + sb2[jt * 4 + j];
                *(float4*)(d_h + n * 64 + jt * 4) = o.v;
                __nv_bfloat16 hb[4]; float lo[4];
                #pragma unroll
                for (int j = 0; j < 4; ++j) {
                    hb[j] = __float2bfloat16(o.f[j]);
                    lo[j] = o.f[j] - __bfloat162float(hb[j]);
                }
                uint2 H, L;
                H.x = pack_bf(hb[0], hb[1]); H.y = pack_bf(hb[2], hb[3]);
                L.x = pack_bf(__float2bfloat16(lo[0]), __float2bfloat16(lo[1]));
                L.y = pack_bf(__float2bfloat16(lo[2]), __float2bfloat16(lo[3]));
                *(uint2*)(d_hhi + n * 64 + jt * 4) = H;
                *(uint2*)(d_hlo + n * 64 + jt * 4) = L;
            }
        }
    }
}

// ---------------- pass1: wmma + fused BN stats ----------------
// bytes: Ahi 0 (34816) Alo 34816 Bhi 69632 (17408) Blo 87040 -> 104448
//        Acc reuses Ahi region; w129 104448 sb1 104704 sdist 104960 sdst 105472 ssrc 105984 -> 106496
#define P1_SMEM 106496
__global__ void __launch_bounds__(256, 2)
pass1_wmma(const int* __restrict__ esrc, const int* __restrict__ edst,
           const float* __restrict__ cell,
           const float* __restrict__ W1, const float* __restrict__ b1, int l) {
    extern __shared__ char smem[];
    __nv_bfloat16* sAhi = (__nv_bfloat16*)(smem);
    __nv_bfloat16* sAlo = (__nv_bfloat16*)(smem + 34816);
    __nv_bfloat16* sBhi = (__nv_bfloat16*)(smem + 69632);
    __nv_bfloat16* sBlo = (__nv_bfloat16*)(smem + 87040);
    float* sAcc  = (float*)(smem);
    float* w129  = (float*)(smem + 104448);
    float* sb1   = (float*)(smem + 104704);
    float* sdist = (float*)(smem + 104960);
    int*   sdst  = (int*)(smem + 105472);
    int*   ssrc  = (int*)(smem + 105984);
    int tid = threadIdx.x;
    for (int i = tid; i < 64 * 16; i += 256) {
        int j = i >> 4, c = i & 15;
        *(uint4*)(sBhi + j * 136 + c * 8) = ((const uint4*)(d_w1hi + l * 8192 + j * 128))[c];
        *(uint4*)(sBlo + j * 136 + c * 8) = ((const uint4*)(d_w1lo + l * 8192 + j * 128))[c];
    }
    if (tid < 64) { w129[tid] = W1[128 * 64 + tid]; sb1[tid] = b1[tid]; }
    int w = tid >> 5, rg = w >> 1, nh = w & 1;
    int cb = tid >> 5, el = tid & 31, j0 = cb * 8;   // epilogue mapping
    float lsum[8] = {0,0,0,0,0,0,0,0}, lsq[8] = {0,0,0,0,0,0,0,0};

    for (int t = blockIdx.x; t < NT_T128; t += gridDim.x) {
        int base = t * 128;
        __syncthreads();
        if (tid < 128) {
            int ge = base + tid;
            int dn = edst[ge], sn = esrc[ge];
            sdst[tid] = dn; ssrc[tid] = sn;
            float dv0 = d_pos[dn * 3 + 0] - d_pos[sn * 3 + 0] + cell[ge * 3 + 0];
            float dv1 = d_pos[dn * 3 + 1] - d_pos[sn * 3 + 1] + cell[ge * 3 + 1];
            float dv2 = d_pos[dn * 3 + 2] - d_pos[sn * 3 + 2] + cell[ge * 3 + 2];
            d_dvec[ge * 3 + 0] = dv0; d_dvec[ge * 3 + 1] = dv1; d_dvec[ge * 3 + 2] = dv2;
            sdist[tid] = dv0 + dv1 + dv2;
        }
        __syncthreads();
        for (int idx = tid; idx < 128 * 32; idx += 256) {
            int e = idx >> 5, q = idx & 31, c = q & 7;
            int n = (q & 8) ? ssrc[e] : sdst[e];
            const uint4* src = (q & 16) ? (const uint4*)(d_hlo + n * 64)
                                        : (const uint4*)(d_hhi + n * 64);
            __nv_bfloat16* dp = ((q & 16) ? sAlo : sAhi) + e * 136 + ((q & 8) ? 64 : 0) + c * 8;
            *(uint4*)dp = src[c];
        }
        __syncthreads();
        wm::fragment<wm::accumulator, 16, 16, 16, float> c00, c01, c10, c11;
        wm::fill_fragment(c00, 0.0f); wm::fill_fragment(c01, 0.0f);
        wm::fill_fragment(c10, 0.0f); wm::fill_fragment(c11, 0.0f);
        {
            const __nv_bfloat16* Ah = sAhi + rg * 32 * 136;
            const __nv_bfloat16* Al = sAlo + rg * 32 * 136;
            const __nv_bfloat16* B0h = sBhi + (nh * 32) * 136;
            const __nv_bfloat16* B1h = sBhi + (nh * 32 + 16) * 136;
            const __nv_bfloat16* B0l = sBlo + (nh * 32) * 136;
            const __nv_bfloat16* B1l = sBlo + (nh * 32 + 16) * 136;
            #pragma unroll
            for (int kt = 0; kt < 8; ++kt) {
                wm::fragment<wm::matrix_a, 16, 16, 16, __nv_bfloat16, wm::row_major> ah0, ah1, al0, al1;
                wm::load_matrix_sync(ah0, Ah + kt * 16, 136);
                wm::load_matrix_sync(ah1, Ah + 16 * 136 + kt * 16, 136);
                wm::load_matrix_sync(al0, Al + kt * 16, 136);
                wm::load_matrix_sync(al1, Al + 16 * 136 + kt * 16, 136);
                wm::fragment<wm::matrix_b, 16, 16, 16, __nv_bfloat16, wm::col_major> b;
                wm::load_matrix_sync(b, B0h + kt * 16, 136);
                wm::mma_sync(c00, ah0, b, c00);
                wm::mma_sync(c10, ah1, b, c10);
                wm::mma_sync(c00, al0, b, c00);
                wm::mma_sync(c10, al1, b, c10);
                wm::load_matrix_sync(b, B1h + kt * 16, 136);
                wm::mma_sync(c01, ah0, b, c01);
                wm::mma_sync(c11, ah1, b, c11);
                wm::mma_sync(c01, al0, b, c01);
                wm::mma_sync(c11, al1, b, c11);
                wm::load_matrix_sync(b, B0l + kt * 16, 136);
                wm::mma_sync(c00, ah0, b, c00);
                wm::mma_sync(c10, ah1, b, c10);
                wm::load_matrix_sync(b, B1l + kt * 16, 136);
                wm::mma_sync(c01, ah0, b, c01);
                wm::mma_sync(c11, ah1, b, c11);
            }
        }
        __syncthreads();
        wm::store_matrix_sync(sAcc + (rg * 32) * 68 + nh * 32, c00, 68, wm::mem_row_major);
        wm::store_matrix_sync(sAcc + (rg * 32) * 68 + nh * 32 + 16, c01, 68, wm::mem_row_major);
        wm::store_matrix_sync(sAcc + (rg * 32 + 16) * 68 + nh * 32, c10, 68, wm::mem_row_major);
        wm::store_matrix_sync(sAcc + (rg * 32 + 16) * 68 + nh * 32 + 16, c11, 68, wm::mem_row_major);
        __syncthreads();
        // epilogue: thread owns fixed 8-col block j0, 4 edges
        #pragma unroll
        for (int i = 0; i < 4; ++i) {
            int e = el + 32 * i;
            int ge = base + e;
            int dn = sdst[e];
            float dist = sdist[e];
            float mv[8];
            __nv_bfloat16 hb[8], lb[8];
            #pragma unroll
            for (int jj = 0; jj < 8; ++jj) {
                int j = j0 + jj;
                float v = sAcc[e * 68 + j] + dist * w129[j] + sb1[j];
                v = silu_f(v);
                mv[jj] = v;
                lsum[jj] += v; lsq[jj] += v * v;
                hb[jj] = __float2bfloat16(v);
                lb[jj] = __float2bfloat16(v - __bfloat162float(hb[jj]));
            }
            uint4 H, L;
            H.x = pack_bf(hb[0], hb[1]); H.y = pack_bf(hb[2], hb[3]);
            H.z = pack_bf(hb[4], hb[5]); H.w = pack_bf(hb[6], hb[7]);
            L.x = pack_bf(lb[0], lb[1]); L.y = pack_bf(lb[2], lb[3]);
            L.z = pack_bf(lb[4], lb[5]); L.w = pack_bf(lb[6], lb[7]);
            ((uint4*)(d_m1hi + (size_t)ge * 64))[cb] = H;
            ((uint4*)(d_m1lo + (size_t)ge * 64))[cb] = L;
            red_add_v4(d_summ1 + dn * 64 + j0,     mv[0], mv[1], mv[2], mv[3]);
            red_add_v4(d_summ1 + dn * 64 + j0 + 4, mv[4], mv[5], mv[6], mv[7]);
        }
    }
    // warp reduce (all lanes in warp share cb) then atomics
    #pragma unroll
    for (int jj = 0; jj < 8; ++jj) {
        #pragma unroll
        for (int o = 1; o < 32; o <<= 1) {
            lsum[jj] += __shfl_xor_sync(0xffffffffu, lsum[jj], o);
            lsq[jj]  += __shfl_xor_sync(0xffffffffu, lsq[jj], o);
        }
    }
    if (el == 0) {
        #pragma unroll
        for (int jj = 0; jj < 8; ++jj) {
            atomicAdd(&d_bnsum[l * 64 + j0 + jj], lsum[jj]);
            atomicAdd(&d_bnsumsq[l * 64 + j0 + jj], lsq[jj]);
        }
    }
}

// ---------------- pass2: wmma, BN prep fused in prologue ----------------
// bytes: Ahi 0 (18432) Alo 18432 Bhi 36864 (9216) Blo 46080 -> 55296
//        Acc reuses Ahi+Alo; sbc 55296 spW2 55552 spb2 56320 sdv 56336 sdst 57872
//        sA 58384 sB 58640 sv 58896 -> 59152
#define P2_SMEM 59152
__global__ void __launch_bounds__(256, 2)
pass2_wmma(const int* __restrict__ edst,
           const float* __restrict__ gamma, const float* __restrict__ beta,
           const float* __restrict__ W2, const float* __restrict__ b2,
           const float* __restrict__ pW1, const float* __restrict__ pb1,
           const float* __restrict__ pW2, const float* __restrict__ pb2, int l) {
    extern __shared__ char smem[];
    __nv_bfloat16* sAhi = (__nv_bfloat16*)(smem);
    __nv_bfloat16* sAlo = (__nv_bfloat16*)(smem + 18432);
    __nv_bfloat16* sBhi = (__nv_bfloat16*)(smem + 36864);
    __nv_bfloat16* sBlo = (__nv_bfloat16*)(smem + 46080);
    float* sAcc = (float*)(smem);
    float* sW2f = (float*)(smem);            // prologue scratch (16 KB)
    float* spW1f = (float*)(smem + 18432);   // prologue scratch (16 KB)
    float* sbc  = (float*)(smem + 55296);
    float* spW2 = (float*)(smem + 55552);
    float* spb2 = (float*)(smem + 56320);
    float* sdv  = (float*)(smem + 56336);
    int*   sdst = (int*)(smem + 57872);
    float* sA   = (float*)(smem + 58384);
    float* sB   = (float*)(smem + 58640);
    float* sv   = (float*)(smem + 58896);
    int tid = threadIdx.x;
    // ---- fused prep: A,B, bc, Wc(bf16 hi/lo) ----
    for (int idx = tid; idx < 4096; idx += 256) {
        sW2f[idx] = W2[idx];
        spW1f[idx] = pW1[idx];
    }
    for (int i = tid; i < 192; i += 256) spW2[i] = pW2[i];
    if (tid < 3) spb2[tid] = pb2[tid];
    if (tid < 64) {
        float mu  = d_bnsum[l * 64 + tid]   * (1.0f / (float)EE);
        float var = d_bnsumsq[l * 64 + tid] * (1.0f / (float)EE) - mu * mu;
        float inv = rsqrtf(var + BN_EPS);
        float A = gamma[tid] * inv;
        sA[tid] = A;
        sB[tid] = beta[tid] - mu * A;
    }
    __syncthreads();
    if (tid < 64) {
        float acc = b2[tid];
        #pragma unroll 8
        for (int k = 0; k < 64; ++k) acc += sB[k] * sW2f[k * 64 + tid];
        sv[tid] = acc;
    }
    __syncthreads();
    if (tid < 64) {
        float acc = pb1[tid];
        #pragma unroll 8
        for (int q = 0; q < 64; ++q) acc += sv[q] * spW1f[q * 64 + tid];
        sbc[tid] = acc;
    }
    for (int idx = tid; idx < 4096; idx += 256) {
        int k = idx >> 6, j = idx & 63;
        float acc = 0.0f;
        #pragma unroll 8
        for (int q = 0; q < 64; ++q) acc += sW2f[k * 64 + q] * spW1f[q * 64 + j];
        float v = sA[k] * acc;
        __nv_bfloat16 h = __float2bfloat16(v);
        sBhi[j * 72 + k] = h;
        sBlo[j * 72 + k] = __float2bfloat16(v - __bfloat162float(h));
    }
    int w = tid >> 5, rg = w >> 1, nh = w & 1;

    for (int t = blockIdx.x; t < NT_T128; t += gridDim.x) {
        int base = t * 128;
        __syncthreads();
        if (tid < 128) sdst[tid] = edst[base + tid];
        for (int i = tid; i < 384; i += 256) sdv[i] = d_dvec[base * 3 + i];
        for (int idx = tid; idx < 128 * 16; idx += 256) {
            int e = idx >> 4, q = idx & 15, c = q & 7;
            const uint4* src = (q & 8) ? (const uint4*)(d_m1lo + (size_t)(base + e) * 64)
                                       : (const uint4*)(d_m1hi + (size_t)(base + e) * 64);
            __nv_bfloat16* dp = ((q & 8) ? sAlo : sAhi) + e * 72 + c * 8;
            *(uint4*)dp = src[c];
        }
        __syncthreads();
        wm::fragment<wm::accumulator, 16, 16, 16, float> c00, c01, c10, c11;
        wm::fill_fragment(c00, 0.0f); wm::fill_fragment(c01, 0.0f);
        wm::fill_fragment(c10, 0.0f); wm::fill_fragment(c11, 0.0f);
        {
            const __nv_bfloat16* Ah = sAhi + rg * 32 * 72;
            const __nv_bfloat16* Al = sAlo + rg * 32 * 72;
            const __nv_bfloat16* B0h = sBhi + (nh * 32) * 72;
            const __nv_bfloat16* B1h = sBhi + (nh * 32 + 16) * 72;
            const __nv_bfloat16* B0l = sBlo + (nh * 32) * 72;
            const __nv_bfloat16* B1l = sBlo + (nh * 32 + 16) * 72;
            #pragma unroll
            for (int kt = 0; kt < 4; ++kt) {
                wm::fragment<wm::matrix_a, 16, 16, 16, __nv_bfloat16, wm::row_major> ah0, ah1, al0, al1;
                wm::load_matrix_sync(ah0, Ah + kt * 16, 72);
                wm::load_matrix_sync(ah1, Ah + 16 * 72 + kt * 16, 72);
                wm::load_matrix_sync(al0, Al + kt * 16, 72);
                wm::load_matrix_sync(al1, Al + 16 * 72 + kt * 16, 72);
                wm::fragment<wm::matrix_b, 16, 16, 16, __nv_bfloat16, wm::col_major> b;
                wm::load_matrix_sync(b, B0h + kt * 16, 72);
                wm::mma_sync(c00, ah0, b, c00);
                wm::mma_sync(c10, ah1, b, c10);
                wm::mma_sync(c00, al0, b, c00);
                wm::mma_sync(c10, al1, b, c10);
                wm::load_matrix_sync(b, B1h + kt * 16, 72);
                wm::mma_sync(c01, ah0, b, c01);
                wm::mma_sync(c11, ah1, b, c11);
                wm::mma_sync(c01, al0, b, c01);
                wm::mma_sync(c11, al1, b, c11);
                wm::load_matrix_sync(b, B0l + kt * 16, 72);
                wm::mma_sync(c00, ah0, b, c00);
                wm::mma_sync(c10, ah1, b, c10);
                wm::load_matrix_sync(b, B1l + kt * 16, 72);
                wm::mma_sync(c01, ah0, b, c01);
                wm::mma_sync(c11, ah1, b, c11);
            }
        }
        __syncthreads();
        wm::store_matrix_sync(sAcc + (rg * 32) * 68 + nh * 32, c00, 68, wm::mem_row_major);
        wm::store_matrix_sync(sAcc + (rg * 32) * 68 + nh * 32 + 16, c01, 68, wm::mem_row_major);
        wm::store_matrix_sync(sAcc + (rg * 32 + 16) * 68 + nh * 32, c10, 68, wm::mem_row_major);
        wm::store_matrix_sync(sAcc + (rg * 32 + 16) * 68 + nh * 32 + 16, c11, 68, wm::mem_row_major);
        __syncthreads();
        if (tid < 128) {
            float s0 = spb2[0], s1 = spb2[1], s2 = spb2[2];
            #pragma unroll
            for (int q = 0; q < 16; ++q) {
                F4U tt; tt.v = *(const float4*)(sAcc + tid * 68 + q * 4);
                #pragma unroll
                for (int c = 0; c < 4; ++c) {
                    int j = q * 4 + c;
                    float v = silu_f(tt.f[c] + sbc[j]);
                    s0 += v * spW2[j * 3 + 0];
                    s1 += v * spW2[j * 3 + 1];
                    s2 += v * spW2[j * 3 + 2];
                }
            }
            int dn = sdst[tid];
            atomicAdd(&d_aggpm[dn * 3 + 0], sdv[tid * 3 + 0] * s0);
            atomicAdd(&d_aggpm[dn * 3 + 1], sdv[tid * 3 + 1] * s1);
            atomicAdd(&d_aggpm[dn * 3 + 2], sdv[tid * 3 + 2] * s2);
        }
    }
}

// ---------------- node (FFMA2, persistent) + h hi/lo emission ----------------
#define ND_SMEM ((64*132 + 64*68*5 + 192 + 256) * (int)sizeof(float))
__global__ void __launch_bounds__(256, 2)
node_kernel(const float* __restrict__ mW2, const float* __restrict__ mb2,
            const float* __restrict__ gamma, const float* __restrict__ beta,
            const float* __restrict__ uW1, const float* __restrict__ ub1,
            const float* __restrict__ uW2, const float* __restrict__ ub2,
            const float* __restrict__ uW3, const float* __restrict__ ub3,
            int ntiles, int l) {
    extern __shared__ float sm[];
    float* sfA  = sm;                    // 64*132
    float* sfB  = sfA + 64 * 132;        // 64*68
    float* sWm  = sfB + 64 * 68;
    float* sW1a = sWm + 64 * 68;
    float* sW2t = sW1a + 64 * 68;
    float* sW3t = sW2t + 64 * 68;
    float* sb1  = sW3t + 64 * 68;
    float* sb2  = sb1 + 64;
    float* sb3  = sb2 + 64;
    float* sAm  = sb3 + 64;
    float* sBm  = sAm + 64;
    float* sb2m = sBm + 64;
    float* sfnz = sb2m + 64;
    int tid = threadIdx.x;
    for (int idx = tid; idx < 64 * 64; idx += 256) {
        int k = idx >> 6, j = idx & 63;
        sWm[j * 68 + k]  = mW2[idx];
        sW1a[j * 68 + k] = uW1[idx];
        sW2t[j * 68 + k] = uW2[idx];
        sW3t[j * 68 + k] = uW3[idx];
    }
    if (tid < 64) {
        sb1[tid] = ub1[tid]; sb2[tid] = ub2[tid]; sb3[tid] = ub3[tid];
        float mu  = d_bnsum[l * 64 + tid]   * (1.0f / (float)EE);
        float var = d_bnsumsq[l * 64 + tid] * (1.0f / (float)EE) - mu * mu;
        float inv = rsqrtf(var + BN_EPS);
        float A = gamma[tid] * inv;
        sAm[tid] = A;
        sBm[tid] = beta[tid] - mu * A;
        sb2m[tid] = mb2[tid];
    }
    int et = tid & 15, jt = tid >> 4;

    for (int t = blockIdx.x; t < ntiles; t += gridDim.x) {
        int base = t * 64;
        __syncthreads();
        for (int idx = tid; idx < 64 * 16; idx += 256) {
            int e = idx >> 4, q = idx & 15;
            int n = base + e;
            float4 hv = make_float4(0.f, 0.f, 0.f, 0.f);
            F4U tt; tt.v = make_float4(0.f, 0.f, 0.f, 0.f);
            if (n < NN) {
                hv = *(const float4*)(d_h + n * 64 + q * 4);
                tt.v = *(const float4*)(d_summ1 + n * 64 + q * 4);
                *(float4*)(d_summ1 + n * 64 + q * 4) = make_float4(0.f, 0.f, 0.f, 0.f);
                float inv = d_invc[n];
                float f = (d_counts[n] > 0) ? 1.0f : 0.0f;
                #pragma unroll
                for (int c = 0; c < 4; ++c)
                    tt.f[c] = sAm[q * 4 + c] * (tt.f[c] * inv) + f * sBm[q * 4 + c];
            }
            *(float4*)(sfA + e * 132 + q * 4) = hv;
            *(float4*)(sfB + e * 68 + q * 4) = tt.v;
        }
        if (tid < 64) {
            int n = base + tid;
            float f = 0.0f;
            if (n < NN) {
                f = (d_counts[n] > 0) ? 1.0f : 0.0f;
                float inv = d_invc[n];
                #pragma unroll
                for (int c = 0; c < 3; ++c) {
                    d_pos[n * 3 + c] += d_aggpm[n * 3 + c] * inv;
                    d_aggpm[n * 3 + c] = 0.0f;
                }
            }
            sfnz[tid] = f;
        }
        __syncthreads();
        {   // agg = mnorm @ mW2 + f*mb2 -> sfA[:,64:128]
            ull a0[4][4] = {};
            gemm_acc4<68, 68>(sfB, sWm, 64, et, jt, a0);
            #pragma unroll
            for (int e = 0; e < 4; ++e) {
                int er = et + 16 * e;
                float f = sfnz[er];
                F4U o;
                #pragma unroll
                for (int j = 0; j < 4; ++j)
                    o.f[j] = lane_sum(a0[e][j]) + f * sb2m[jt * 4 + j];
                *(float4*)(sfA + er * 132 + 64 + jt * 4) = o.v;
            }
        }
        __syncthreads();
        ull a1[4][4] = {};
        gemm_acc4<132, 68>(sfA, sW1a, 64, et, jt, a1);
        {   // uW1 rows 64..127 direct from gmem (L2-hot broadcast)
            const float* fb = sfA + et * 132 + 64;
            #pragma unroll 2
            for (int k0 = 0; k0 < 64; k0 += 4) {
                ull w[4][2];
                #pragma unroll
                for (int j = 0; j < 4; ++j) {
                    F4U tw;
                    tw.f[0] = uW1[(64 + k0 + 0) * 64 + jt * 4 + j];
                    tw.f[1] = uW1[(64 + k0 + 1) * 64 + jt * 4 + j];
                    tw.f[2] = uW1[(64 + k0 + 2) * 64 + jt * 4 + j];
                    tw.f[3] = uW1[(64 + k0 + 3) * 64 + jt * 4 + j];
                    w[j][0] = tw.u[0]; w[j][1] = tw.u[1];
                }
                #pragma unroll
                for (int e = 0; e < 4; ++e) {
                    F4U tf; tf.v = *(const float4*)(fb + e * 16 * 132 + k0);
                    #pragma unroll
                    for (int j = 0; j < 4; ++j) {
                        a1[e][j] = ffma2(tf.u[0], w[j][0], a1[e][j]);
                        a1[e][j] = ffma2(tf.u[1], w[j][1], a1[e][j]);
                    }
                }
            }
        }
        __syncthreads();
        #pragma unroll
        for (int e = 0; e < 4; ++e) {
            F4U o;
            #pragma unroll
            for (int j = 0; j < 4; ++j)
                o.f[j] = silu_f(lane_sum(a1[e][j]) + sb1[jt * 4 + j]);
            *(float4*)(sfB + (et + 16 * e) * 68 + jt * 4) = o.v;
        }
        __syncthreads();
        {
            ull a2[4][4] = {};
            gemm_acc4<68, 68>(sfB, sW2t, 64, et, jt, a2);
            #pragma unroll
            for (int e = 0; e < 4; ++e) {
                F4U o;
                #pragma unroll
                for (int j = 0; j < 4; ++j)
                    o.f[j] = silu_f(lane_sum(a2[e][j]) + sb2[jt * 4 + j]);
                *(float4*)(sfA + (et + 16 * e) * 132 + jt * 4) = o.v;
            }
        }
        __syncthreads();
        {
            ull a3[4][4] = {};
            gemm_acc4<132, 68>(sfA, sW3t, 64, et, jt, a3);
            #pragma unroll
            for (int e = 0; e < 4; ++e) {
                int n = base + et + 16 * e;
                if (n < NN) {
                    F4U h; h.v = *(const float4*)(d_h + n * 64 + jt * 4);
                    F4U o;
                    #pragma unroll
                    for (int j = 0; j < 4; ++j)
                        o.f[j] = h.f[j] + lane_sum(a3[e][j]) + sb3[jt * 4 + j];
                    *(float4*)(d_h + n * 64 + jt * 4) = o.v;
                    __nv_bfloat16 hb[4]; float lo[4];
                    #pragma unroll
                    for (int j = 0; j < 4; ++j) {
                        hb[j] = __float2bfloat16(o.f[j]);
                        lo[j] = o.f[j] - __bfloat162float(hb[j]);
                    }
                    uint2 H, L;
                    H.x = pack_bf(hb[0], hb[1]); H.y = pack_bf(hb[2], hb[3]);
                    L.x = pack_bf(__float2bfloat16(lo[0]), __float2bfloat16(lo[1]));
                    L.y = pack_bf(__float2bfloat16(lo[2]), __float2bfloat16(lo[3]));
                    *(uint2*)(d_hhi + n * 64 + jt * 4) = H;
                    *(uint2*)(d_hlo + n * 64 + jt * 4) = L;
                }
            }
        }
    }
}

// ---------------- energy MLP ----------------
#define EN_SMEM ((64*68*2 + 64*68*2 + 64 + 64 + 64 + 4) * (int)sizeof(float))
__global__ void energy_kernel(const float* __restrict__ W1, const float* __restrict__ b1,
                              const float* __restrict__ W2, const float* __restrict__ b2,
                              const float* __restrict__ W3, const float* __restrict__ b3,
                              float* __restrict__ out) {
    extern __shared__ float sm[];
    float* sfA  = sm;
    float* sfB  = sfA + 64 * 68;
    float* sW1t = sfB + 64 * 68;
    float* sW2t = sW1t + 64 * 68;
    float* sW3  = sW2t + 64 * 68;
    float* sb1  = sW3 + 64;
    float* sb2  = sb1 + 64;
    float* sb3  = sb2 + 64;
    int tid = threadIdx.x;
    int base = blockIdx.x * 64;
    for (int idx = tid; idx < 64 * 64; idx += 256) {
        int k = idx >> 6, j = idx & 63;
        sW1t[j * 68 + k] = W1[idx];
        sW2t[j * 68 + k] = W2[idx];
    }
    if (tid < 64) { sW3[tid] = W3[tid]; sb1[tid] = b1[tid]; sb2[tid] = b2[tid]; }
    if (tid == 0) sb3[0] = b3[0];
    for (int idx = tid; idx < 64 * 16; idx += 256) {
        int e = idx >> 4, q = idx & 15;
        int n = base + e;
        float4 v = (n < NN) ? *(const float4*)(d_h + n * 64 + q * 4)
                            : make_float4(0.f, 0.f, 0.f, 0.f);
        *(float4*)(sfA + e * 68 + q * 4) = v;
    }
    __syncthreads();
    int et = tid & 15, jt = tid >> 4;
    {
        ull acc[4][4] = {};
        gemm_acc4<68, 68>(sfA, sW1t, 64, et, jt, acc);
        #pragma unroll
        for (int e = 0; e < 4; ++e) {
            F4U o;
            #pragma unroll
            for (int j = 0; j < 4; ++j)
                o.f[j] = silu_f(lane_sum(acc[e][j]) + sb1[jt * 4 + j]);
            *(float4*)(sfB + (et + 16 * e) * 68 + jt * 4) = o.v;
        }
    }
    __syncthreads();
    {
        ull acc[4][4] = {};
        gemm_acc4<68, 68>(sfB, sW2t, 64, et, jt, acc);
        #pragma unroll
        for (int e = 0; e < 4; ++e) {
            F4U o;
            #pragma unroll
            for (int j = 0; j < 4; ++j)
                o.f[j] = silu_f(lane_sum(acc[e][j]) + sb2[jt * 4 + j]);
            *(float4*)(sfA + (et + 16 * e) * 68 + jt * 4) = o.v;
        }
    }
    __syncthreads();
    if (tid < 64) {
        int n = base + tid;
        if (n < NN) {
            float s = sb3[0];
            #pragma unroll
            for (int q = 0; q < 16; ++q) {
                F4U t; t.v = *(const float4*)(sfA + tid * 68 + q * 4);
                #pragma unroll
                for (int c = 0; c < 4; ++c) s += t.f[c] * sW3[q * 4 + c];
            }
            out[n] = s;
        }
    }
}

// ---------------- launch ----------------
extern "C" void kernel_launch(void* const* d_in, const int* in_sizes, int n_in,
                              void* d_out, int out_size) {
    const float* h_in   = (const float*)d_in[0];
    const float* pos    = (const float*)d_in[1];
    const float* cell   = (const float*)d_in[2];
    const int*   esrc   = (const int*)d_in[3];
    const int*   edst   = (const int*)d_in[4];
    const float* emb_W1 = (const float*)d_in[5];
    const float* emb_b1 = (const float*)d_in[6];
    const float* emb_W2 = (const float*)d_in[7];
    const float* emb_b2 = (const float*)d_in[8];
    const float* msg_W1 = (const float*)d_in[9];
    const float* msg_b1 = (const float*)d_in[10];
    const float* bn_g   = (const float*)d_in[11];
    const float* bn_b   = (const float*)d_in[12];
    const float* msg_W2 = (const float*)d_in[13];
    const float* msg_b2 = (const float*)d_in[14];
    const float* upd_W1 = (const float*)d_in[15];
    const float* upd_b1 = (const float*)d_in[16];
    const float* upd_W2 = (const float*)d_in[17];
    const float* upd_b2 = (const float*)d_in[18];
    const float* upd_W3 = (const float*)d_in[19];
    const float* upd_b3 = (const float*)d_in[20];
    const float* pos_W1 = (const float*)d_in[21];
    const float* pos_b1 = (const float*)d_in[22];
    const float* pos_W2 = (const float*)d_in[23];
    const float* pos_b2 = (const float*)d_in[24];
    const float* en_W1  = (const float*)d_in[25];
    const float* en_b1  = (const float*)d_in[26];
    const float* en_W2  = (const float*)d_in[27];
    const float* en_b2  = (const float*)d_in[28];
    const float* en_W3  = (const float*)d_in[29];
    const float* en_b3  = (const float*)d_in[30];
    float* out = (float*)d_out;

    static int attr_done = 0;
    if (!attr_done) {
        cudaFuncSetAttribute(embed_kernel,  cudaFuncAttributeMaxDynamicSharedMemorySize, EM_SMEM);
        cudaFuncSetAttribute(pass1_wmma,    cudaFuncAttributeMaxDynamicSharedMemorySize, P1_SMEM);
        cudaFuncSetAttribute(pass2_wmma,    cudaFuncAttributeMaxDynamicSharedMemorySize, P2_SMEM);
        cudaFuncSetAttribute(node_kernel,   cudaFuncAttributeMaxDynamicSharedMemorySize, ND_SMEM);
        cudaFuncSetAttribute(energy_kernel, cudaFuncAttributeMaxDynamicSharedMemorySize, EN_SMEM);
        attr_done = 1;
    }

    const int P1_GRID = 148 * 2;
    const int P2_GRID = 148 * 2;
    const int ND_TILES = (NN + 63) / 64;
    const int ND_GRID = 148 * 2;

    init_kernel<<<(NN * F + 255) / 256, 256>>>(pos);
    count_kernel<<<(EE + 255) / 256, 256>>>(edst);
    inv_kernel<<<(NN + 255) / 256, 256>>>();
    wconv_kernel<<<(NL * F * 128 + 255) / 256, 256>>>(msg_W1);
    embed_kernel<<<313, 256, EM_SMEM>>>(h_in, emb_W1, emb_b1, emb_W2, emb_b2);

    for (int l = 0; l < NL; ++l) {
        pass1_wmma<<<P1_GRID, 256, P1_SMEM>>>(esrc, edst, cell,
                                              msg_W1 + l * (2 * F + 1) * F, msg_b1 + l * F, l);
        pass2_wmma<<<P2_GRID, 256, P2_SMEM>>>(edst,
                                              bn_g + l * F, bn_b + l * F,
                                              msg_W2 + l * F * F, msg_b2 + l * F,
                                              pos_W1 + l * F * F, pos_b1 + l * F,
                                              pos_W2 + l * F * DIM, pos_b2 + l * DIM, l);
        node_kernel<<<ND_GRID, 256, ND_SMEM>>>(msg_W2 + l * F * F, msg_b2 + l * F,
                                               bn_g + l * F, bn_b + l * F,
                                               upd_W1 + l * 2 * F * F, upd_b1 + l * F,
                                               upd_W2 + l * F * F, upd_b2 + l * F,
                                               upd_W3 + l * F * F, upd_b3 + l * F,
                                               ND_TILES, l);
    }
    energy_kernel<<<313, 256, EN_SMEM>>>(en_W1, en_b1, en_W2, en_b2, en_W3, en_b3, out);
}